// round 13
// baseline (speedup 1.0000x reference)
#include <cuda_runtime.h>
#include <cuda_bf16.h>
#include <math.h>
#include <stdint.h>

#define BATCH   2
#define SEQLEN  2048
#define NTOK    (BATCH*SEQLEN)        // 4096
#define DMODEL  768
#define DINNER  1536
#define DSTATE  128
#define HEADDIM 64
#define NHEADS  24
#define CONVDIM 1792                  // DINNER + 2*DSTATE
#define DINPROJ 3352                  // 2*DINNER + 2*DSTATE + NHEADS
#define CT      64                    // chunk tokens
#define NCH     (SEQLEN/CT)           // 32 chunks per sequence

// ---------------------------------------------------------------------------
// Scratch buffers (device globals — no allocations allowed)
// ---------------------------------------------------------------------------
__device__ __align__(128) float g_zx[NTOK * DINPROJ];     // in_proj output
__device__ __align__(128) float g_conv[NTOK * CONVDIM];   // conv+silu (x | B | C)
__device__ __align__(128) float g_dt[NTOK * NHEADS];      // softplus(dt + bias)
__device__ __align__(128) float g_a[NTOK * NHEADS];       // A * dt  (log decay)
__device__ __align__(128) float g_ecum[NTOK * NHEADS];    // exp(within-chunk cumsum)
__device__ __align__(128) float g_ptot[BATCH*NHEADS*NCH]; // per-chunk total decay
__device__ __align__(128) float g_y[NTOK * DINNER];       // scan output
__device__ __align__(128) float g_cstate[BATCH*NHEADS*NCH*HEADDIM*DSTATE]; // chunk-local states
__device__ __align__(128) float g_istate[BATCH*NHEADS*NCH*HEADDIM*DSTATE]; // chunk-entry states

// bf16 hi/lo split operands for tensor-core GEMMs
__device__ __align__(128) __nv_bfloat16 g_u_hi[NTOK * DMODEL];
__device__ __align__(128) __nv_bfloat16 g_u_lo[NTOK * DMODEL];
__device__ __align__(128) __nv_bfloat16 g_w1_hi[DINPROJ * DMODEL];
__device__ __align__(128) __nv_bfloat16 g_w1_lo[DINPROJ * DMODEL];
__device__ __align__(128) __nv_bfloat16 g_w2_hi[DMODEL * DINNER];
__device__ __align__(128) __nv_bfloat16 g_w2_lo[DMODEL * DINNER];
__device__ __align__(128) __nv_bfloat16 g_yn_hi[NTOK * DINNER];
__device__ __align__(128) __nv_bfloat16 g_yn_lo[NTOK * DINNER];

// ---------------------------------------------------------------------------
// MMA helpers (baseline PTX — works under compute_103 virtual arch)
// ---------------------------------------------------------------------------
static __device__ __forceinline__ uint32_t smem_u32(const void* p) {
    return (uint32_t)__cvta_generic_to_shared(p);
}

static __device__ __forceinline__ void mma_bf16(
    float* d, const uint32_t* a, const uint32_t* b)
{
    asm volatile(
        "mma.sync.aligned.m16n8k16.row.col.f32.bf16.bf16.f32 "
        "{%0,%1,%2,%3}, {%4,%5,%6,%7}, {%8,%9}, {%0,%1,%2,%3};"
        : "+f"(d[0]), "+f"(d[1]), "+f"(d[2]), "+f"(d[3])
        : "r"(a[0]), "r"(a[1]), "r"(a[2]), "r"(a[3]), "r"(b[0]), "r"(b[1]));
}

static __device__ __forceinline__ void ldmatrix_x4(uint32_t* r, uint32_t addr)
{
    asm volatile("ldmatrix.sync.aligned.m8n8.x4.shared.b16 {%0,%1,%2,%3}, [%4];"
                 : "=r"(r[0]), "=r"(r[1]), "=r"(r[2]), "=r"(r[3]) : "r"(addr));
}

static __device__ __forceinline__ void ldmatrix_x2(uint32_t* r, uint32_t addr)
{
    asm volatile("ldmatrix.sync.aligned.m8n8.x2.shared.b16 {%0,%1}, [%2];"
                 : "=r"(r[0]), "=r"(r[1]) : "r"(addr));
}

static __device__ __forceinline__ void ldmatrix_x2_trans(uint32_t* r, uint32_t addr)
{
    asm volatile("ldmatrix.sync.aligned.m8n8.x2.trans.shared.b16 {%0,%1}, [%2];"
                 : "=r"(r[0]), "=r"(r[1]) : "r"(addr));
}

static __device__ __forceinline__ void cp16(uint32_t dst, const void* src, int sz)
{
    asm volatile("cp.async.cg.shared.global [%0], [%1], 16, %2;"
                 :: "r"(dst), "l"(src), "r"(sz));
}

// split fp32x4 into packed bf16 hi/lo (uint2 each)
static __device__ __forceinline__ void split4(float4 v, uint2& hi, uint2& lo)
{
    __nv_bfloat16 h0=__float2bfloat16(v.x), h1=__float2bfloat16(v.y),
                  h2=__float2bfloat16(v.z), h3=__float2bfloat16(v.w);
    __nv_bfloat16 l0=__float2bfloat16(v.x-__bfloat162float(h0)),
                  l1=__float2bfloat16(v.y-__bfloat162float(h1)),
                  l2=__float2bfloat16(v.z-__bfloat162float(h2)),
                  l3=__float2bfloat16(v.w-__bfloat162float(h3));
    hi.x = ((uint32_t)__bfloat16_as_ushort(h1)<<16) | __bfloat16_as_ushort(h0);
    hi.y = ((uint32_t)__bfloat16_as_ushort(h3)<<16) | __bfloat16_as_ushort(h2);
    lo.x = ((uint32_t)__bfloat16_as_ushort(l1)<<16) | __bfloat16_as_ushort(l0);
    lo.y = ((uint32_t)__bfloat16_as_ushort(l3)<<16) | __bfloat16_as_ushort(l2);
}

// ---------------------------------------------------------------------------
// bf16x3 GEMM via mma.sync:  C[M,N] = A[M,K] @ B[N,K]^T  (~fp32 accuracy)
// CTA tile 128x128, BK=32, FOUR warps (2x2), warp tile 64x64, 128 threads.
// The 64x64 warp tile cuts smem LDSM bytes per MMA from 128B to 85B —
// the kernel is LDSM-bandwidth bound (53% tensor == HMMA/LDSM cycle ratio).
// Double-buffered cp.async, single barrier per chunk, 2 CTAs/SM.
// ---------------------------------------------------------------------------
#define ROWB   80
#define MATB   (128 * ROWB)
#define STAGEB (4 * MATB)                 // 40960
#define GEMM_SMEM (2 * STAGEB)            // 81920

__global__ void __launch_bounds__(128) gemm_mma(
    const __nv_bfloat16* __restrict__ Ah, const __nv_bfloat16* __restrict__ Al,
    const __nv_bfloat16* __restrict__ Bh, const __nv_bfloat16* __restrict__ Bl,
    float* __restrict__ C, int M, int N, int K)
{
    extern __shared__ __align__(128) char smem[];
    const uint32_t sb = smem_u32(smem);
    const int tid = threadIdx.x;
    const int wid = tid >> 5, lid = tid & 31;
    const int bm = blockIdx.y * 128;
    const int bn = blockIdx.x * 128;
    const int wr = wid & 1;               // warp m-half (x64)
    const int wc = wid >> 1;              // warp n-half (x64)

    float acc[4][8][4];
#pragma unroll
    for (int i = 0; i < 4; i++)
#pragma unroll
        for (int j = 0; j < 8; j++)
#pragma unroll
            for (int k = 0; k < 4; k++) acc[i][j][k] = 0.f;

    // staging: thread -> row tid (0..127), all four 16B chunks per matrix
    const int lrow = tid;
    const int bok  = (bn + lrow) < N ? 16 : 0;
    const size_t arowoff = (size_t)(bm + lrow) * K;
    const size_t browoff = (size_t)(bok ? (bn + lrow) : 0) * K;
    const uint32_t dst0 = sb + lrow * ROWB;

    const int NC = K >> 5;

    auto stage_issue = [&](int c) {
        const uint32_t d = dst0 + (uint32_t)(c & 1) * STAGEB;
        const size_t ao = arowoff + (size_t)c * 32;
        const size_t bo = browoff + (size_t)c * 32;
#pragma unroll
        for (int j = 0; j < 4; ++j) {
            cp16(d + j * 16,            Ah + ao + j * 8, 16);
            cp16(d + MATB + j * 16,     Al + ao + j * 8, 16);
            cp16(d + 2 * MATB + j * 16, Bh + bo + j * 8, bok);
            cp16(d + 3 * MATB + j * 16, Bl + bo + j * 8, bok);
        }
        asm volatile("cp.async.commit_group;");
    };

    stage_issue(0);

    for (int c = 0; c < NC; ++c) {
        asm volatile("cp.async.wait_group 0;");
        __syncthreads();
        if (c + 1 < NC) stage_issue(c + 1);

        const uint32_t st = sb + (uint32_t)(c & 1) * STAGEB;
#pragma unroll
        for (int ks = 0; ks < 2; ++ks) {
            uint32_t ah[4][4], al[4][4], bh[8][2], bl[8][2];
            const int arow = wr * 64 + (lid & 15);
            const int akc  = ks * 2 + (lid >> 4);
#pragma unroll
            for (int mt = 0; mt < 4; ++mt) {
                const uint32_t a = st + (arow + mt * 16) * ROWB + akc * 16;
                ldmatrix_x4(ah[mt], a);
                ldmatrix_x4(al[mt], a + MATB);
            }
            const int brow = wc * 64 + (lid & 7);
            const int bkc  = ks * 2 + ((lid >> 3) & 1);
#pragma unroll
            for (int nt = 0; nt < 8; ++nt) {
                const uint32_t b = st + 2*MATB + (brow + nt * 8) * ROWB + bkc * 16;
                ldmatrix_x2(bh[nt], b);
                ldmatrix_x2(bl[nt], b + MATB);
            }
#pragma unroll
            for (int mt = 0; mt < 4; ++mt)
#pragma unroll
                for (int nt = 0; nt < 8; ++nt)
                    mma_bf16(acc[mt][nt], ah[mt], bh[nt]);
#pragma unroll
            for (int mt = 0; mt < 4; ++mt)
#pragma unroll
                for (int nt = 0; nt < 8; ++nt)
                    mma_bf16(acc[mt][nt], ah[mt], bl[nt]);
#pragma unroll
            for (int mt = 0; mt < 4; ++mt)
#pragma unroll
                for (int nt = 0; nt < 8; ++nt)
                    mma_bf16(acc[mt][nt], al[mt], bh[nt]);
        }
    }

    const int mbase = bm + wr * 64 + (lid >> 2);
    const int nbase = bn + wc * 64 + (lid & 3) * 2;
#pragma unroll
    for (int mt = 0; mt < 4; ++mt) {
#pragma unroll
        for (int nt = 0; nt < 8; ++nt) {
            const int n0 = nbase + nt * 8;
            if (n0 < N) {
                const int m0 = mbase + mt * 16;
                float2 v0 = make_float2(acc[mt][nt][0], acc[mt][nt][1]);
                float2 v1 = make_float2(acc[mt][nt][2], acc[mt][nt][3]);
                *(float2*)(C + (size_t)m0 * N + n0)       = v0;
                *(float2*)(C + (size_t)(m0 + 8) * N + n0) = v1;
            }
        }
    }
}

// ---------------------------------------------------------------------------
// fp32 -> bf16 hi/lo split
// ---------------------------------------------------------------------------
__global__ void split_kernel(const float* __restrict__ src,
                             __nv_bfloat16* __restrict__ hi,
                             __nv_bfloat16* __restrict__ lo, int n)
{
    const int i = blockIdx.x * 256 + threadIdx.x;
    if (i >= n) return;
    const float x = src[i];
    const __nv_bfloat16 h = __float2bfloat16(x);
    hi[i] = h;
    lo[i] = __float2bfloat16(x - __bfloat162float(h));
}

// ---------------------------------------------------------------------------
// Depthwise causal conv (width 4) + bias + SiLU over the xBC slice of g_zx.
// ---------------------------------------------------------------------------
__global__ void conv_silu_kernel(const float* __restrict__ cw,
                                 const float* __restrict__ cb)
{
    const int idx = blockIdx.x * 256 + threadIdx.x;
    if (idx >= NTOK * CONVDIM) return;
    const int c  = idx % CONVDIM;
    const int bt = idx / CONVDIM;
    const int t  = bt % SEQLEN;
    float acc = cb[c];
#pragma unroll
    for (int k = 0; k < 4; k++) {
        const int tt = t - 3 + k;
        if (tt >= 0)
            acc = fmaf(cw[c * 4 + k],
                       g_zx[((size_t)bt + k - 3) * DINPROJ + DINNER + c], acc);
    }
    g_conv[idx] = acc / (1.f + __expf(-acc));   // silu
}

// ---------------------------------------------------------------------------
// dt_dis = softplus(dt + dt_bias); a = dt_dis * A  (log decay, negative)
// ---------------------------------------------------------------------------
__global__ void dt_kernel(const float* __restrict__ dt_bias,
                          const float* __restrict__ A_log)
{
    const int idx = blockIdx.x * 256 + threadIdx.x;
    if (idx >= NTOK * NHEADS) return;
    const int h  = idx % NHEADS;
    const int bt = idx / NHEADS;
    const float x  = g_zx[(size_t)bt * DINPROJ + DINNER + CONVDIM + h] + dt_bias[h];
    const float sp = (x > 20.f) ? x : log1pf(expf(x));
    const float Ah = -expf(A_log[h]);
    g_dt[idx] = sp;
    g_a[idx]  = sp * Ah;
}

// ---------------------------------------------------------------------------
// SSD chunk kernel: per (chunk, head, batch) block, 256 threads (8 warps 2x4).
// ---------------------------------------------------------------------------
#define PB 272
#define PX 144
#define SM_BH 0
#define SM_BL 17408
#define SM_CH 34816
#define SM_CL 52224
#define SM_XH 69632
#define SM_XL 78848
#define SM_PH 88064
#define SM_PL 97280
#define SM_CUM 106496
#define SM_DTA 106752
#define SM_WW  107008
#define CHUNK_SMEM 107264

__global__ void __launch_bounds__(256) chunk_kernel()
{
    extern __shared__ __align__(128) char smem[];
    const uint32_t sb = smem_u32(smem);
    const int ch = blockIdx.x, h = blockIdx.y, b = blockIdx.z;
    const int tid = threadIdx.x;
    const int wid = tid >> 5, lid = tid & 31;
    const int wr = wid & 1, wc = wid >> 1;
    const size_t tb = (size_t)b * SEQLEN + (size_t)ch * CT;

    float* s_cum = (float*)(smem + SM_CUM);
    float* s_dt  = (float*)(smem + SM_DTA);
    float* s_w   = (float*)(smem + SM_WW);

    // ---- stage B, C (hi/lo bf16, pitch PB): 256 threads ----
    {
        const int row = tid >> 2, c0 = (tid & 3) * 32;
        const float* src = g_conv + (tb + row) * CONVDIM + DINNER;
#pragma unroll
        for (int c = 0; c < 32; c += 4) {
            float4 v = *(const float4*)(src + c0 + c);
            uint2 hi, lo; split4(v, hi, lo);
            *(uint2*)(smem + SM_BH + row * PB + (c0 + c) * 2) = hi;
            *(uint2*)(smem + SM_BL + row * PB + (c0 + c) * 2) = lo;
            float4 u = *(const float4*)(src + DSTATE + c0 + c);
            split4(u, hi, lo);
            *(uint2*)(smem + SM_CH + row * PB + (c0 + c) * 2) = hi;
            *(uint2*)(smem + SM_CL + row * PB + (c0 + c) * 2) = lo;
        }
    }
    // ---- stage X transposed: Xs[p][t] (hi/lo, pitch PX) ----
    {
        const int t = tid >> 2, p0 = (tid & 3) * 16;
        const float* src = g_conv + (tb + t) * CONVDIM + h * HEADDIM;
#pragma unroll
        for (int p = 0; p < 16; p += 4) {
            float4 v = *(const float4*)(src + p0 + p);
            const float vv[4] = {v.x, v.y, v.z, v.w};
#pragma unroll
            for (int i = 0; i < 4; i++) {
                const __nv_bfloat16 hb = __float2bfloat16(vv[i]);
                const __nv_bfloat16 lb = __float2bfloat16(vv[i] - __bfloat162float(hb));
                *(unsigned short*)(smem + SM_XH + (p0 + p + i) * PX + t * 2) =
                    __bfloat16_as_ushort(hb);
                *(unsigned short*)(smem + SM_XL + (p0 + p + i) * PX + t * 2) =
                    __bfloat16_as_ushort(lb);
            }
        }
    }
    // ---- warp 0: within-chunk inclusive cumsum of a (64) ----
    if (wid == 0) {
        const float a0 = g_a[(tb + 2 * lid)     * NHEADS + h];
        const float a1 = g_a[(tb + 2 * lid + 1) * NHEADS + h];
        const float ps = a0 + a1;
        float sc = ps;
#pragma unroll
        for (int off = 1; off < 32; off <<= 1) {
            const float t = __shfl_up_sync(0xffffffffu, sc, off);
            if (lid >= off) sc += t;
        }
        float excl = __shfl_up_sync(0xffffffffu, sc, 1);
        if (lid == 0) excl = 0.f;
        s_cum[2 * lid]     = excl + a0;
        s_cum[2 * lid + 1] = excl + ps;
    }
    if (tid >= 64 && tid < 128) s_dt[tid - 64] = g_dt[(tb + tid - 64) * NHEADS + h];
    __syncthreads();

    if (tid < 64) {
        const float ct = s_cum[tid], tot = s_cum[63];
        s_w[tid] = expf(tot - ct) * s_dt[tid];
        g_ecum[(tb + tid) * NHEADS + h] = expf(ct);
        if (tid == 63)
            g_ptot[((size_t)b * NHEADS + h) * NCH + ch] = expf(tot);
    }

    // ---- G = C·B^T (64x64, K=128), bf16x3, warp tile 32x16 ----
    float gacc[2][2][4];
#pragma unroll
    for (int i = 0; i < 2; i++)
#pragma unroll
        for (int j = 0; j < 2; j++)
#pragma unroll
            for (int k = 0; k < 4; k++) gacc[i][j][k] = 0.f;
#pragma unroll
    for (int ks = 0; ks < 8; ++ks) {
        uint32_t ah[2][4], al[2][4], bh2[2][2], bl2[2][2];
        const int arow = wr * 32 + (lid & 15);
        const int akc  = ks * 2 + (lid >> 4);
#pragma unroll
        for (int mt = 0; mt < 2; ++mt) {
            const uint32_t a = sb + SM_CH + (arow + mt * 16) * PB + akc * 16;
            ldmatrix_x4(ah[mt], a);
            ldmatrix_x4(al[mt], a + (SM_CL - SM_CH));
        }
        const int brow = wc * 16 + (lid & 7);
        const int bkc  = ks * 2 + ((lid >> 3) & 1);
#pragma unroll
        for (int nt = 0; nt < 2; ++nt) {
            const uint32_t bp = sb + SM_BH + (brow + nt * 8) * PB + bkc * 16;
            ldmatrix_x2(bh2[nt], bp);
            ldmatrix_x2(bl2[nt], bp + (SM_BL - SM_BH));
        }
#pragma unroll
        for (int mt = 0; mt < 2; ++mt)
#pragma unroll
            for (int nt = 0; nt < 2; ++nt)
                mma_bf16(gacc[mt][nt], ah[mt], bh2[nt]);
#pragma unroll
        for (int mt = 0; mt < 2; ++mt)
#pragma unroll
            for (int nt = 0; nt < 2; ++nt)
                mma_bf16(gacc[mt][nt], ah[mt], bl2[nt]);
#pragma unroll
        for (int mt = 0; mt < 2; ++mt)
#pragma unroll
            for (int nt = 0; nt < 2; ++nt)
                mma_bf16(gacc[mt][nt], al[mt], bh2[nt]);
    }

    // ---- P = mask * G * dt -> smem ----
#pragma unroll
    for (int mt = 0; mt < 2; ++mt)
#pragma unroll
        for (int nt = 0; nt < 2; ++nt)
#pragma unroll
            for (int r = 0; r < 4; ++r) {
                const int t1 = wr * 32 + mt * 16 + (lid >> 2) + ((r >> 1) ? 8 : 0);
                const int t2 = wc * 16 + nt * 8 + (lid & 3) * 2 + (r & 1);
                float pv = 0.f;
                if (t1 >= t2)
                    pv = __expf(s_cum[t1] - s_cum[t2]) * gacc[mt][nt][r] * s_dt[t2];
                const __nv_bfloat16 hb = __float2bfloat16(pv);
                const __nv_bfloat16 lb = __float2bfloat16(pv - __bfloat162float(hb));
                *(unsigned short*)(smem + SM_PH + t1 * PX + t2 * 2) =
                    __bfloat16_as_ushort(hb);
                *(unsigned short*)(smem + SM_PL + t1 * PX + t2 * 2) =
                    __bfloat16_as_ushort(lb);
            }
    __syncthreads();

    // ---- Y_intra = P·X ----
    {
        float yacc[2][2][4];
#pragma unroll
        for (int i = 0; i < 2; i++)
#pragma unroll
            for (int j = 0; j < 2; j++)
#pragma unroll
                for (int k = 0; k < 4; k++) yacc[i][j][k] = 0.f;
#pragma unroll
        for (int ks = 0; ks < 4; ++ks) {
            uint32_t ah[2][4], al[2][4], bh2[2][2], bl2[2][2];
            const int arow = wr * 32 + (lid & 15);
            const int akc  = ks * 2 + (lid >> 4);
#pragma unroll
            for (int mt = 0; mt < 2; ++mt) {
                const uint32_t a = sb + SM_PH + (arow + mt * 16) * PX + akc * 16;
                ldmatrix_x4(ah[mt], a);
                ldmatrix_x4(al[mt], a + (SM_PL - SM_PH));
            }
            const int brow = wc * 16 + (lid & 7);
            const int bkc  = ks * 2 + ((lid >> 3) & 1);
#pragma unroll
            for (int nt = 0; nt < 2; ++nt) {
                const uint32_t bp = sb + SM_XH + (brow + nt * 8) * PX + bkc * 16;
                ldmatrix_x2(bh2[nt], bp);
                ldmatrix_x2(bl2[nt], bp + (SM_XL - SM_XH));
            }
#pragma unroll
            for (int mt = 0; mt < 2; ++mt)
#pragma unroll
                for (int nt = 0; nt < 2; ++nt)
                    mma_bf16(yacc[mt][nt], ah[mt], bh2[nt]);
#pragma unroll
            for (int mt = 0; mt < 2; ++mt)
#pragma unroll
                for (int nt = 0; nt < 2; ++nt)
                    mma_bf16(yacc[mt][nt], ah[mt], bl2[nt]);
#pragma unroll
            for (int mt = 0; mt < 2; ++mt)
#pragma unroll
                for (int nt = 0; nt < 2; ++nt)
                    mma_bf16(yacc[mt][nt], al[mt], bh2[nt]);
        }
#pragma unroll
        for (int mt = 0; mt < 2; ++mt)
#pragma unroll
            for (int nt = 0; nt < 2; ++nt) {
                const int t0 = wr * 32 + mt * 16 + (lid >> 2);
                const int p0 = wc * 16 + nt * 8 + (lid & 3) * 2;
                *(float2*)(g_y + (tb + t0) * DINNER + h * HEADDIM + p0) =
                    make_float2(yacc[mt][nt][0], yacc[mt][nt][1]);
                *(float2*)(g_y + (tb + t0 + 8) * DINNER + h * HEADDIM + p0) =
                    make_float2(yacc[mt][nt][2], yacc[mt][nt][3]);
            }
    }
    __syncthreads();

    // ---- Xw[p][j] = x[j,p] * w_j into P region ----
    {
        const int p = tid >> 2, j0 = (tid & 3) * 16;
#pragma unroll
        for (int j = 0; j < 16; ++j) {
            const int jj = j0 + j;
            const float xv =
                __bfloat162float(__ushort_as_bfloat16(
                    *(unsigned short*)(smem + SM_XH + p * PX + jj * 2))) +
                __bfloat162float(__ushort_as_bfloat16(
                    *(unsigned short*)(smem + SM_XL + p * PX + jj * 2)));
            const float xw = xv * s_w[jj];
            const __nv_bfloat16 hb = __float2bfloat16(xw);
            const __nv_bfloat16 lb = __float2bfloat16(xw - __bfloat162float(hb));
            *(unsigned short*)(smem + SM_PH + p * PX + jj * 2) =
                __bfloat16_as_ushort(hb);
            *(unsigned short*)(smem + SM_PL + p * PX + jj * 2) =
                __bfloat16_as_ushort(lb);
        }
    }
    __syncthreads();

    // ---- L = Xw·B (64p x 128n, K=64), trans-B ----
    {
        float lacc[2][4][4];
#pragma unroll
        for (int i = 0; i < 2; i++)
#pragma unroll
            for (int j = 0; j < 4; j++)
#pragma unroll
                for (int k = 0; k < 4; k++) lacc[i][j][k] = 0.f;
#pragma unroll
        for (int ks = 0; ks < 4; ++ks) {
            uint32_t ah[2][4], al[2][4], bh2[4][2], bl2[4][2];
            const int arow = wr * 32 + (lid & 15);
            const int akc  = ks * 2 + (lid >> 4);
#pragma unroll
            for (int mt = 0; mt < 2; ++mt) {
                const uint32_t a = sb + SM_PH + (arow + mt * 16) * PX + akc * 16;
                ldmatrix_x4(ah[mt], a);
                ldmatrix_x4(al[mt], a + (SM_PL - SM_PH));
            }
            const int j0 = ks * 16 + (lid & 15);
#pragma unroll
            for (int nt = 0; nt < 4; ++nt) {
                const int n0 = wc * 32 + nt * 8;
                const uint32_t bp = sb + SM_BH + j0 * PB + n0 * 2;
                ldmatrix_x2_trans(bh2[nt], bp);
                ldmatrix_x2_trans(bl2[nt], bp + (SM_BL - SM_BH));
            }
#pragma unroll
            for (int mt = 0; mt < 2; ++mt)
#pragma unroll
                for (int nt = 0; nt < 4; ++nt)
                    mma_bf16(lacc[mt][nt], ah[mt], bh2[nt]);
#pragma unroll
            for (int mt = 0; mt < 2; ++mt)
#pragma unroll
                for (int nt = 0; nt < 4; ++nt)
                    mma_bf16(lacc[mt][nt], ah[mt], bl2[nt]);
#pragma unroll
            for (int mt = 0; mt < 2; ++mt)
#pragma unroll
                for (int nt = 0; nt < 4; ++nt)
                    mma_bf16(lacc[mt][nt], al[mt], bh2[nt]);
        }
        float* Lout = g_cstate +
            (((size_t)b * NHEADS + h) * NCH + ch) * (HEADDIM * DSTATE);
#pragma unroll
        for (int mt = 0; mt < 2; ++mt)
#pragma unroll
            for (int nt = 0; nt < 4; ++nt) {
                const int p0 = wr * 32 + mt * 16 + (lid >> 2);
                const int n0 = wc * 32 + nt * 8 + (lid & 3) * 2;
                *(float2*)(Lout + (size_t)p0 * DSTATE + n0) =
                    make_float2(lacc[mt][nt][0], lacc[mt][nt][1]);
                *(float2*)(Lout + (size_t)(p0 + 8) * DSTATE + n0) =
                    make_float2(lacc[mt][nt][2], lacc[mt][nt][3]);
            }
    }
}

// ---------------------------------------------------------------------------
// Sequential combine over chunks
// ---------------------------------------------------------------------------
__global__ __launch_bounds__(256) void combine_kernel()
{
    const int h = blockIdx.x, b = blockIdx.y;
    const int tid = threadIdx.x;
    const size_t off = (size_t)tid * 32;
    float4 acc[8];
#pragma unroll
    for (int r = 0; r < 8; r++) acc[r] = make_float4(0.f, 0.f, 0.f, 0.f);

    for (int c = 0; c < NCH; ++c) {
        const size_t base = (((size_t)b * NHEADS + h) * NCH + c) * (HEADDIM * DSTATE);
#pragma unroll
        for (int r = 0; r < 8; r++)
            *(float4*)(g_istate + base + off + r * 4) = acc[r];
        const float P = g_ptot[((size_t)b * NHEADS + h) * NCH + c];
#pragma unroll
        for (int r = 0; r < 8; r++) {
            const float4 f = *(const float4*)(g_cstate + base + off + r * 4);
            acc[r].x = fmaf(acc[r].x, P, f.x);
            acc[r].y = fmaf(acc[r].y, P, f.y);
            acc[r].z = fmaf(acc[r].z, P, f.z);
            acc[r].w = fmaf(acc[r].w, P, f.w);
        }
    }
}

// ---------------------------------------------------------------------------
// Inter-chunk: Y[t,p] += ecum_t * (C_t · S0[p,:])
// ---------------------------------------------------------------------------
#define ISM_CH 0
#define ISM_CL 17408
#define ISM_SH 34816
#define ISM_SL 52224
#define ISM_EC 69632
#define INTER_SMEM 69888

__global__ void __launch_bounds__(256) inter_kernel()
{
    extern __shared__ __align__(128) char smem[];
    const uint32_t sb = smem_u32(smem);
    const int ch = blockIdx.x + 1, h = blockIdx.y, b = blockIdx.z;
    const int tid = threadIdx.x;
    const int wid = tid >> 5, lid = tid & 31;
    const int wr = wid & 1, wc = wid >> 1;
    const size_t tb = (size_t)b * SEQLEN + (size_t)ch * CT;

    {
        const int row = tid >> 2, c0 = (tid & 3) * 32;
        const float* csrc = g_conv + (tb + row) * CONVDIM + DINNER + DSTATE;
        const float* ssrc = g_istate +
            (((size_t)b * NHEADS + h) * NCH + ch) * (HEADDIM * DSTATE) +
            (size_t)row * DSTATE;
#pragma unroll
        for (int c = 0; c < 32; c += 4) {
            float4 v = *(const float4*)(csrc + c0 + c);
            uint2 hi, lo; split4(v, hi, lo);
            *(uint2*)(smem + ISM_CH + row * PB + (c0 + c) * 2) = hi;
            *(uint2*)(smem + ISM_CL + row * PB + (c0 + c) * 2) = lo;
            float4 u = *(const float4*)(ssrc + c0 + c);
            split4(u, hi, lo);
            *(uint2*)(smem + ISM_SH + row * PB + (c0 + c) * 2) = hi;
            *(uint2*)(smem + ISM_SL + row * PB + (c0 + c) * 2) = lo;
        }
    }
    if (tid < 64)
        ((float*)(smem + ISM_EC))[tid] = g_ecum[(tb + tid) * NHEADS + h];
    __syncthreads();

    float acc[2][2][4];
#pragma unroll
    for (int i = 0; i < 2; i++)
#pragma unroll
        for (int j = 0; j < 2; j++)
#pragma unroll
            for (int k = 0; k < 4; k++) acc[i][j][k] = 0.f;

#pragma unroll
    for (int ks = 0; ks < 8; ++ks) {
        uint32_t ah[2][4], al[2][4], bh2[2][2], bl2[2][2];
        const int arow = wr * 32 + (lid & 15);
        const int akc  = ks * 2 + (lid >> 4);
#pragma unroll
        for (int mt = 0; mt < 2; ++mt) {
            const uint32_t a = sb + ISM_CH + (arow + mt * 16) * PB + akc * 16;
            ldmatrix_x4(ah[mt], a);
            ldmatrix_x4(al[mt], a + (ISM_CL - ISM_CH));
        }
        const int brow = wc * 16 + (lid & 7);
        const int bkc  = ks * 2 + ((lid >> 3) & 1);
#pragma unroll
        for (int nt = 0; nt < 2; ++nt) {
            const uint32_t bp = sb + ISM_SH + (brow + nt * 8) * PB + bkc * 16;
            ldmatrix_x2(bh2[nt], bp);
            ldmatrix_x2(bl2[nt], bp + (ISM_SL - ISM_SH));
        }
#pragma unroll
        for (int mt = 0; mt < 2; ++mt)
#pragma unroll
            for (int nt = 0; nt < 2; ++nt)
                mma_bf16(acc[mt][nt], ah[mt], bh2[nt]);
#pragma unroll
        for (int mt = 0; mt < 2; ++mt)
#pragma unroll
            for (int nt = 0; nt < 2; ++nt)
                mma_bf16(acc[mt][nt], ah[mt], bl2[nt]);
#pragma unroll
        for (int mt = 0; mt < 2; ++mt)
#pragma unroll
            for (int nt = 0; nt < 2; ++nt)
                mma_bf16(acc[mt][nt], al[mt], bh2[nt]);
    }

    const float* s_ec = (const float*)(smem + ISM_EC);
#pragma unroll
    for (int mt = 0; mt < 2; ++mt)
#pragma unroll
        for (int nt = 0; nt < 2; ++nt) {
            const int t0 = wr * 32 + mt * 16 + (lid >> 2);
            const int p0 = wc * 16 + nt * 8 + (lid & 3) * 2;
            {
                float* yp = g_y + (tb + t0) * DINNER + h * HEADDIM + p0;
                float2 o = *(float2*)yp;
                o.x += s_ec[t0] * acc[mt][nt][0];
                o.y += s_ec[t0] * acc[mt][nt][1];
                *(float2*)yp = o;
            }
            {
                float* yp = g_y + (tb + t0 + 8) * DINNER + h * HEADDIM + p0;
                float2 o = *(float2*)yp;
                o.x += s_ec[t0 + 8] * acc[mt][nt][2];
                o.y += s_ec[t0 + 8] * acc[mt][nt][3];
                *(float2*)yp = o;
            }
        }
}

// ---------------------------------------------------------------------------
// y += x*D; yz = y*silu(z); RMSNorm(yz) * norm_w -> bf16 hi/lo
// ---------------------------------------------------------------------------
__global__ __launch_bounds__(256) void gate_norm_kernel(
    const float* __restrict__ Dv, const float* __restrict__ nw)
{
    const int bt = blockIdx.x;
    const float* zrow = g_zx   + (size_t)bt * DINPROJ;
    const float* xrow = g_conv + (size_t)bt * CONVDIM;
    const float* yrow = g_y    + (size_t)bt * DINNER;

    float v[6];
    float ss = 0.f;
#pragma unroll
    for (int i = 0; i < 6; i++) {
        const int c = threadIdx.x + i * 256;
        const float yv = fmaf(xrow[c], Dv[c >> 6], yrow[c]);
        const float z  = zrow[c];
        const float gz = z / (1.f + __expf(-z));
        const float val = yv * gz;
        v[i] = val;
        ss = fmaf(val, val, ss);
    }
#pragma unroll
    for (int o = 16; o; o >>= 1) ss += __shfl_xor_sync(0xffffffffu, ss, o);
    __shared__ float sred[8];
    if ((threadIdx.x & 31) == 0) sred[threadIdx.x >> 5] = ss;
    __syncthreads();
    float tot = 0.f;
#pragma unroll
    for (int i = 0; i < 8; i++) tot += sred[i];
    const float scale = rsqrtf(tot * (1.f / DINNER) + 1e-5f);

    __nv_bfloat16* yh = g_yn_hi + (size_t)bt * DINNER;
    __nv_bfloat16* yl = g_yn_lo + (size_t)bt * DINNER;
#pragma unroll
    for (int i = 0; i < 6; i++) {
        const int c = threadIdx.x + i * 256;
        const float val = v[i] * scale * nw[c];
        const __nv_bfloat16 hb = __float2bfloat16(val);
        yh[c] = hb;
        yl[c] = __float2bfloat16(val - __bfloat162float(hb));
    }
}

// ---------------------------------------------------------------------------
// Launch
// ---------------------------------------------------------------------------
extern "C" void kernel_launch(void* const* d_in, const int* in_sizes, int n_in,
                              void* d_out, int out_size)
{
    const float* u          = (const float*)d_in[0];
    const float* in_proj_w  = (const float*)d_in[1];
    const float* conv_w     = (const float*)d_in[2];
    const float* conv_b     = (const float*)d_in[3];
    const float* dt_bias    = (const float*)d_in[4];
    const float* A_log      = (const float*)d_in[5];
    const float* Dv         = (const float*)d_in[6];
    const float* norm_w     = (const float*)d_in[7];
    const float* out_proj_w = (const float*)d_in[8];
    float* out = (float*)d_out;

    float* zx = nullptr;
    __nv_bfloat16 *uh, *ul, *w1h, *w1l, *w2h, *w2l, *ynh, *ynl;
    cudaGetSymbolAddress((void**)&zx,  g_zx);
    cudaGetSymbolAddress((void**)&uh,  g_u_hi);
    cudaGetSymbolAddress((void**)&ul,  g_u_lo);
    cudaGetSymbolAddress((void**)&w1h, g_w1_hi);
    cudaGetSymbolAddress((void**)&w1l, g_w1_lo);
    cudaGetSymbolAddress((void**)&w2h, g_w2_hi);
    cudaGetSymbolAddress((void**)&w2l, g_w2_lo);
    cudaGetSymbolAddress((void**)&ynh, g_yn_hi);
    cudaGetSymbolAddress((void**)&ynl, g_yn_lo);

    cudaFuncSetAttribute(gemm_mma,
                         cudaFuncAttributeMaxDynamicSharedMemorySize, GEMM_SMEM);
    cudaFuncSetAttribute(chunk_kernel,
                         cudaFuncAttributeMaxDynamicSharedMemorySize, CHUNK_SMEM);
    cudaFuncSetAttribute(inter_kernel,
                         cudaFuncAttributeMaxDynamicSharedMemorySize, INTER_SMEM);

    // 0) bf16 hi/lo splits for GEMM operands
    split_kernel<<<(NTOK * DMODEL + 255) / 256, 256>>>(u, uh, ul, NTOK * DMODEL);
    split_kernel<<<(DINPROJ * DMODEL + 255) / 256, 256>>>(in_proj_w, w1h, w1l,
                                                          DINPROJ * DMODEL);
    split_kernel<<<(DMODEL * DINNER + 255) / 256, 256>>>(out_proj_w, w2h, w2l,
                                                         DMODEL * DINNER);

    // 1) zxbcdt = u @ in_proj_w^T — HMMA bf16x3, 64x64 warp tiles
    dim3 g1((DINPROJ + 127) / 128, NTOK / 128);
    gemm_mma<<<g1, 128, GEMM_SMEM>>>(uh, ul, w1h, w1l, zx,
                                     NTOK, DINPROJ, DMODEL);

    // 2) depthwise causal conv + silu
    conv_silu_kernel<<<(NTOK * CONVDIM + 255) / 256, 256>>>(conv_w, conv_b);

    // 3) dt softplus / log-decay a
    dt_kernel<<<(NTOK * NHEADS + 255) / 256, 256>>>(dt_bias, A_log);

    // 4) SSD chunk pass — tensor cores
    chunk_kernel<<<dim3(NCH, NHEADS, BATCH), 256, CHUNK_SMEM>>>();

    // 5) combine chunk states sequentially
    combine_kernel<<<dim3(NHEADS, BATCH), 256>>>();

    // 6) inter-chunk contribution — tensor cores
    inter_kernel<<<dim3(NCH - 1, NHEADS, BATCH), 256, INTER_SMEM>>>();

    // 7) gate + RMSNorm -> bf16 hi/lo
    gate_norm_kernel<<<NTOK, 256>>>(Dv, norm_w);

    // 8) out = yn @ out_proj_w^T — HMMA bf16x3, 64x64 warp tiles
    dim3 g2((DMODEL + 127) / 128, NTOK / 128);
    gemm_mma<<<g2, 128, GEMM_SMEM>>>(ynh, ynl, w2h, w2l, out,
                                     NTOK, DMODEL, DINNER);
}

// round 14
// speedup vs baseline: 1.1866x; 1.1866x over previous
#include <cuda_runtime.h>
#include <cuda_bf16.h>
#include <math.h>
#include <stdint.h>

#define BATCH   2
#define SEQLEN  2048
#define NTOK    (BATCH*SEQLEN)        // 4096
#define DMODEL  768
#define DINNER  1536
#define DSTATE  128
#define HEADDIM 64
#define NHEADS  24
#define CONVDIM 1792                  // DINNER + 2*DSTATE
#define DINPROJ 3352                  // 2*DINNER + 2*DSTATE + NHEADS
#define CT      64                    // chunk tokens
#define NCH     (SEQLEN/CT)           // 32 chunks per sequence

// ---------------------------------------------------------------------------
// Scratch buffers (device globals — no allocations allowed)
// ---------------------------------------------------------------------------
__device__ __align__(128) float g_zx[NTOK * DINPROJ];     // in_proj output
__device__ __align__(128) float g_conv[NTOK * CONVDIM];   // conv+silu (x | B | C) fp32
__device__ __align__(128) __nv_bfloat16 g_cvh[NTOK * CONVDIM]; // conv out bf16 hi
__device__ __align__(128) __nv_bfloat16 g_cvl[NTOK * CONVDIM]; // conv out bf16 lo
__device__ __align__(128) float g_dt[NTOK * NHEADS];      // softplus(dt + bias)
__device__ __align__(128) float g_a[NTOK * NHEADS];       // A * dt  (log decay)
__device__ __align__(128) float g_ecum[NTOK * NHEADS];    // exp(within-chunk cumsum)
__device__ __align__(128) float g_ptot[BATCH*NHEADS*NCH]; // per-chunk total decay
__device__ __align__(128) float g_y[NTOK * DINNER];       // scan output
__device__ __align__(128) float g_cstate[BATCH*NHEADS*NCH*HEADDIM*DSTATE]; // chunk-local states
__device__ __align__(128) __nv_bfloat16 g_isth[BATCH*NHEADS*NCH*HEADDIM*DSTATE]; // entry states hi
__device__ __align__(128) __nv_bfloat16 g_istl[BATCH*NHEADS*NCH*HEADDIM*DSTATE]; // entry states lo

// bf16 hi/lo split operands for tensor-core GEMMs
__device__ __align__(128) __nv_bfloat16 g_u_hi[NTOK * DMODEL];
__device__ __align__(128) __nv_bfloat16 g_u_lo[NTOK * DMODEL];
__device__ __align__(128) __nv_bfloat16 g_w1_hi[DINPROJ * DMODEL];
__device__ __align__(128) __nv_bfloat16 g_w1_lo[DINPROJ * DMODEL];
__device__ __align__(128) __nv_bfloat16 g_w2_hi[DMODEL * DINNER];
__device__ __align__(128) __nv_bfloat16 g_w2_lo[DMODEL * DINNER];
__device__ __align__(128) __nv_bfloat16 g_yn_hi[NTOK * DINNER];
__device__ __align__(128) __nv_bfloat16 g_yn_lo[NTOK * DINNER];

// ---------------------------------------------------------------------------
// MMA helpers (baseline PTX — works under compute_103 virtual arch)
// ---------------------------------------------------------------------------
static __device__ __forceinline__ uint32_t smem_u32(const void* p) {
    return (uint32_t)__cvta_generic_to_shared(p);
}

static __device__ __forceinline__ void mma_bf16(
    float* d, const uint32_t* a, const uint32_t* b)
{
    asm volatile(
        "mma.sync.aligned.m16n8k16.row.col.f32.bf16.bf16.f32 "
        "{%0,%1,%2,%3}, {%4,%5,%6,%7}, {%8,%9}, {%0,%1,%2,%3};"
        : "+f"(d[0]), "+f"(d[1]), "+f"(d[2]), "+f"(d[3])
        : "r"(a[0]), "r"(a[1]), "r"(a[2]), "r"(a[3]), "r"(b[0]), "r"(b[1]));
}

static __device__ __forceinline__ void ldmatrix_x4(uint32_t* r, uint32_t addr)
{
    asm volatile("ldmatrix.sync.aligned.m8n8.x4.shared.b16 {%0,%1,%2,%3}, [%4];"
                 : "=r"(r[0]), "=r"(r[1]), "=r"(r[2]), "=r"(r[3]) : "r"(addr));
}

static __device__ __forceinline__ void ldmatrix_x2(uint32_t* r, uint32_t addr)
{
    asm volatile("ldmatrix.sync.aligned.m8n8.x2.shared.b16 {%0,%1}, [%2];"
                 : "=r"(r[0]), "=r"(r[1]) : "r"(addr));
}

static __device__ __forceinline__ void ldmatrix_x2_trans(uint32_t* r, uint32_t addr)
{
    asm volatile("ldmatrix.sync.aligned.m8n8.x2.trans.shared.b16 {%0,%1}, [%2];"
                 : "=r"(r[0]), "=r"(r[1]) : "r"(addr));
}

static __device__ __forceinline__ void cp16(uint32_t dst, const void* src, int sz)
{
    asm volatile("cp.async.cg.shared.global [%0], [%1], 16, %2;"
                 :: "r"(dst), "l"(src), "r"(sz));
}

// split fp32x4 into packed bf16 hi/lo (uint2 each)
static __device__ __forceinline__ void split4(float4 v, uint2& hi, uint2& lo)
{
    __nv_bfloat16 h0=__float2bfloat16(v.x), h1=__float2bfloat16(v.y),
                  h2=__float2bfloat16(v.z), h3=__float2bfloat16(v.w);
    __nv_bfloat16 l0=__float2bfloat16(v.x-__bfloat162float(h0)),
                  l1=__float2bfloat16(v.y-__bfloat162float(h1)),
                  l2=__float2bfloat16(v.z-__bfloat162float(h2)),
                  l3=__float2bfloat16(v.w-__bfloat162float(h3));
    hi.x = ((uint32_t)__bfloat16_as_ushort(h1)<<16) | __bfloat16_as_ushort(h0);
    hi.y = ((uint32_t)__bfloat16_as_ushort(h3)<<16) | __bfloat16_as_ushort(h2);
    lo.x = ((uint32_t)__bfloat16_as_ushort(l1)<<16) | __bfloat16_as_ushort(l0);
    lo.y = ((uint32_t)__bfloat16_as_ushort(l3)<<16) | __bfloat16_as_ushort(l2);
}

// ---------------------------------------------------------------------------
// bf16x3 GEMM via mma.sync (R9 proven form — 600us config, frozen)
// ---------------------------------------------------------------------------
#define ROWB   80
#define MATB   (128 * ROWB)
#define STAGEB (4 * MATB)                 // 40960
#define GEMM_SMEM (2 * STAGEB)            // 81920

__global__ void __launch_bounds__(256) gemm_mma(
    const __nv_bfloat16* __restrict__ Ah, const __nv_bfloat16* __restrict__ Al,
    const __nv_bfloat16* __restrict__ Bh, const __nv_bfloat16* __restrict__ Bl,
    float* __restrict__ C, int M, int N, int K)
{
    extern __shared__ __align__(128) char smem[];
    const uint32_t sb = smem_u32(smem);
    const int tid = threadIdx.x;
    const int wid = tid >> 5, lid = tid & 31;
    const int bm = blockIdx.y * 128;
    const int bn = blockIdx.x * 128;
    const int wr = wid & 1;
    const int wc = wid >> 1;

    float acc[4][4][4];
#pragma unroll
    for (int i = 0; i < 4; i++)
#pragma unroll
        for (int j = 0; j < 4; j++)
#pragma unroll
            for (int k = 0; k < 4; k++) acc[i][j][k] = 0.f;

    const int lrow = tid >> 1;
    const int lch  = (tid & 1) * 2;
    const int bok  = (bn + lrow) < N ? 16 : 0;
    const size_t arowoff = (size_t)(bm + lrow) * K;
    const size_t browoff = (size_t)(bok ? (bn + lrow) : 0) * K;
    const uint32_t dst0 = sb + lrow * ROWB + lch * 16;

    const int NC = K >> 5;

    {
        const size_t ao = arowoff + lch * 8;
        const size_t bo = browoff + lch * 8;
        cp16(dst0,             Ah + ao, 16); cp16(dst0 + 16,            Ah + ao + 8, 16);
        cp16(dst0 + MATB,      Al + ao, 16); cp16(dst0 + MATB + 16,     Al + ao + 8, 16);
        cp16(dst0 + 2*MATB,    Bh + bo, bok); cp16(dst0 + 2*MATB + 16,  Bh + bo + 8, bok);
        cp16(dst0 + 3*MATB,    Bl + bo, bok); cp16(dst0 + 3*MATB + 16,  Bl + bo + 8, bok);
        asm volatile("cp.async.commit_group;");
    }

    for (int c = 0; c < NC; ++c) {
        if (c + 1 < NC) {
            const uint32_t d = dst0 + ((c + 1) & 1) * STAGEB;
            const size_t ao = arowoff + (size_t)(c + 1) * 32 + lch * 8;
            const size_t bo = browoff + (size_t)(c + 1) * 32 + lch * 8;
            cp16(d,            Ah + ao, 16); cp16(d + 16,           Ah + ao + 8, 16);
            cp16(d + MATB,     Al + ao, 16); cp16(d + MATB + 16,    Al + ao + 8, 16);
            cp16(d + 2*MATB,   Bh + bo, bok); cp16(d + 2*MATB + 16, Bh + bo + 8, bok);
            cp16(d + 3*MATB,   Bl + bo, bok); cp16(d + 3*MATB + 16, Bl + bo + 8, bok);
            asm volatile("cp.async.commit_group;");
            asm volatile("cp.async.wait_group 1;");
        } else {
            asm volatile("cp.async.wait_group 0;");
        }
        __syncthreads();

        const uint32_t st = sb + (c & 1) * STAGEB;
#pragma unroll
        for (int ks = 0; ks < 2; ++ks) {
            uint32_t ah[4][4], al[4][4], bh[4][2], bl[4][2];
            const int arow = wr * 64 + (lid & 15);
            const int akc  = ks * 2 + (lid >> 4);
#pragma unroll
            for (int mt = 0; mt < 4; ++mt) {
                const uint32_t a = st + (arow + mt * 16) * ROWB + akc * 16;
                ldmatrix_x4(ah[mt], a);
                ldmatrix_x4(al[mt], a + MATB);
            }
            const int brow = wc * 32 + (lid & 7);
            const int bkc  = ks * 2 + ((lid >> 3) & 1);
#pragma unroll
            for (int nt = 0; nt < 4; ++nt) {
                const uint32_t b = st + 2*MATB + (brow + nt * 8) * ROWB + bkc * 16;
                ldmatrix_x2(bh[nt], b);
                ldmatrix_x2(bl[nt], b + MATB);
            }
#pragma unroll
            for (int mt = 0; mt < 4; ++mt)
#pragma unroll
                for (int nt = 0; nt < 4; ++nt) {
                    mma_bf16(acc[mt][nt], ah[mt], bh[nt]);
                    mma_bf16(acc[mt][nt], ah[mt], bl[nt]);
                    mma_bf16(acc[mt][nt], al[mt], bh[nt]);
                }
        }
        __syncthreads();
    }

    const int mbase = bm + wr * 64 + (lid >> 2);
    const int nbase = bn + wc * 32 + (lid & 3) * 2;
#pragma unroll
    for (int mt = 0; mt < 4; ++mt) {
#pragma unroll
        for (int nt = 0; nt < 4; ++nt) {
            const int n0 = nbase + nt * 8;
            if (n0 < N) {
                const int m0 = mbase + mt * 16;
                float2 v0 = make_float2(acc[mt][nt][0], acc[mt][nt][1]);
                float2 v1 = make_float2(acc[mt][nt][2], acc[mt][nt][3]);
                *(float2*)(C + (size_t)m0 * N + n0)       = v0;
                *(float2*)(C + (size_t)(m0 + 8) * N + n0) = v1;
            }
        }
    }
}

// ---------------------------------------------------------------------------
// fp32 -> bf16 hi/lo split
// ---------------------------------------------------------------------------
__global__ void split_kernel(const float* __restrict__ src,
                             __nv_bfloat16* __restrict__ hi,
                             __nv_bfloat16* __restrict__ lo, int n)
{
    const int i = blockIdx.x * 256 + threadIdx.x;
    if (i >= n) return;
    const float x = src[i];
    const __nv_bfloat16 h = __float2bfloat16(x);
    hi[i] = h;
    lo[i] = __float2bfloat16(x - __bfloat162float(h));
}

// ---------------------------------------------------------------------------
// Depthwise causal conv (width 4) + bias + SiLU. Emits fp32 AND bf16 hi/lo —
// the bf16 split is done ONCE here instead of 24x (per head) in chunk_kernel.
// ---------------------------------------------------------------------------
__global__ void conv_silu_kernel(const float* __restrict__ cw,
                                 const float* __restrict__ cb)
{
    const int idx = blockIdx.x * 256 + threadIdx.x;
    if (idx >= NTOK * CONVDIM) return;
    const int c  = idx % CONVDIM;
    const int bt = idx / CONVDIM;
    const int t  = bt % SEQLEN;
    float acc = cb[c];
#pragma unroll
    for (int k = 0; k < 4; k++) {
        const int tt = t - 3 + k;
        if (tt >= 0)
            acc = fmaf(cw[c * 4 + k],
                       g_zx[((size_t)bt + k - 3) * DINPROJ + DINNER + c], acc);
    }
    const float v = acc / (1.f + __expf(-acc));   // silu
    g_conv[idx] = v;
    const __nv_bfloat16 hb = __float2bfloat16(v);
    g_cvh[idx] = hb;
    g_cvl[idx] = __float2bfloat16(v - __bfloat162float(hb));
}

// ---------------------------------------------------------------------------
// dt_dis = softplus(dt + dt_bias); a = dt_dis * A  (log decay, negative)
// ---------------------------------------------------------------------------
__global__ void dt_kernel(const float* __restrict__ dt_bias,
                          const float* __restrict__ A_log)
{
    const int idx = blockIdx.x * 256 + threadIdx.x;
    if (idx >= NTOK * NHEADS) return;
    const int h  = idx % NHEADS;
    const int bt = idx / NHEADS;
    const float x  = g_zx[(size_t)bt * DINPROJ + DINNER + CONVDIM + h] + dt_bias[h];
    const float sp = (x > 20.f) ? x : log1pf(expf(x));
    const float Ah = -expf(A_log[h]);
    g_dt[idx] = sp;
    g_a[idx]  = sp * Ah;
}

// ---------------------------------------------------------------------------
// SSD chunk kernel: per (chunk, head, batch) block, 256 threads (8 warps 2x4).
// Staging is now pure uint4 copies from pre-split bf16 arrays.
// ---------------------------------------------------------------------------
#define PB 272
#define PX 144
#define SM_BH 0
#define SM_BL 17408
#define SM_CH 34816
#define SM_CL 52224
#define SM_XH 69632
#define SM_XL 78848
#define SM_PH 88064
#define SM_PL 97280
#define SM_CUM 106496
#define SM_DTA 106752
#define SM_WW  107008
#define CHUNK_SMEM 107264

__global__ void __launch_bounds__(256) chunk_kernel()
{
    extern __shared__ __align__(128) char smem[];
    const uint32_t sb = smem_u32(smem);
    const int ch = blockIdx.x, h = blockIdx.y, b = blockIdx.z;
    const int tid = threadIdx.x;
    const int wid = tid >> 5, lid = tid & 31;
    const int wr = wid & 1, wc = wid >> 1;
    const size_t tb = (size_t)b * SEQLEN + (size_t)ch * CT;

    float* s_cum = (float*)(smem + SM_CUM);
    float* s_dt  = (float*)(smem + SM_DTA);
    float* s_w   = (float*)(smem + SM_WW);

    // ---- stage B, C: uint4 copies of pre-split bf16 (no conversion math) ----
    {
        const int row = tid >> 2, c0 = (tid & 3) * 32;
        const size_t so = (tb + row) * CONVDIM + DINNER + c0;
#pragma unroll
        for (int c = 0; c < 32; c += 8) {
            *(uint4*)(smem + SM_BH + row * PB + (c0 + c) * 2) =
                *(const uint4*)(g_cvh + so + c);
            *(uint4*)(smem + SM_BL + row * PB + (c0 + c) * 2) =
                *(const uint4*)(g_cvl + so + c);
            *(uint4*)(smem + SM_CH + row * PB + (c0 + c) * 2) =
                *(const uint4*)(g_cvh + so + DSTATE + c);
            *(uint4*)(smem + SM_CL + row * PB + (c0 + c) * 2) =
                *(const uint4*)(g_cvl + so + DSTATE + c);
        }
    }
    // ---- stage X transposed: Xs[p][t] from pre-split bf16 ----
    {
        const int t = tid >> 2, p0 = (tid & 3) * 16;
        const size_t so = (tb + t) * CONVDIM + h * HEADDIM + p0;
#pragma unroll
        for (int p = 0; p < 16; ++p) {
            *(unsigned short*)(smem + SM_XH + (p0 + p) * PX + t * 2) =
                *(const unsigned short*)(g_cvh + so + p);
            *(unsigned short*)(smem + SM_XL + (p0 + p) * PX + t * 2) =
                *(const unsigned short*)(g_cvl + so + p);
        }
    }
    // ---- warp 0: within-chunk inclusive cumsum of a (64) ----
    if (wid == 0) {
        const float a0 = g_a[(tb + 2 * lid)     * NHEADS + h];
        const float a1 = g_a[(tb + 2 * lid + 1) * NHEADS + h];
        const float ps = a0 + a1;
        float sc = ps;
#pragma unroll
        for (int off = 1; off < 32; off <<= 1) {
            const float t = __shfl_up_sync(0xffffffffu, sc, off);
            if (lid >= off) sc += t;
        }
        float excl = __shfl_up_sync(0xffffffffu, sc, 1);
        if (lid == 0) excl = 0.f;
        s_cum[2 * lid]     = excl + a0;
        s_cum[2 * lid + 1] = excl + ps;
    }
    if (tid >= 64 && tid < 128) s_dt[tid - 64] = g_dt[(tb + tid - 64) * NHEADS + h];
    __syncthreads();

    if (tid < 64) {
        const float ct = s_cum[tid], tot = s_cum[63];
        s_w[tid] = expf(tot - ct) * s_dt[tid];
        g_ecum[(tb + tid) * NHEADS + h] = expf(ct);
        if (tid == 63)
            g_ptot[((size_t)b * NHEADS + h) * NCH + ch] = expf(tot);
    }

    // ---- G = C·B^T (64x64, K=128), bf16x3, warp tile 32x16 ----
    float gacc[2][2][4];
#pragma unroll
    for (int i = 0; i < 2; i++)
#pragma unroll
        for (int j = 0; j < 2; j++)
#pragma unroll
            for (int k = 0; k < 4; k++) gacc[i][j][k] = 0.f;
#pragma unroll
    for (int ks = 0; ks < 8; ++ks) {
        uint32_t ah[2][4], al[2][4], bh2[2][2], bl2[2][2];
        const int arow = wr * 32 + (lid & 15);
        const int akc  = ks * 2 + (lid >> 4);
#pragma unroll
        for (int mt = 0; mt < 2; ++mt) {
            const uint32_t a = sb + SM_CH + (arow + mt * 16) * PB + akc * 16;
            ldmatrix_x4(ah[mt], a);
            ldmatrix_x4(al[mt], a + (SM_CL - SM_CH));
        }
        const int brow = wc * 16 + (lid & 7);
        const int bkc  = ks * 2 + ((lid >> 3) & 1);
#pragma unroll
        for (int nt = 0; nt < 2; ++nt) {
            const uint32_t bp = sb + SM_BH + (brow + nt * 8) * PB + bkc * 16;
            ldmatrix_x2(bh2[nt], bp);
            ldmatrix_x2(bl2[nt], bp + (SM_BL - SM_BH));
        }
#pragma unroll
        for (int mt = 0; mt < 2; ++mt)
#pragma unroll
            for (int nt = 0; nt < 2; ++nt) {
                mma_bf16(gacc[mt][nt], ah[mt], bh2[nt]);
                mma_bf16(gacc[mt][nt], ah[mt], bl2[nt]);
                mma_bf16(gacc[mt][nt], al[mt], bh2[nt]);
            }
    }

    // ---- P = mask * G * dt -> smem ----
#pragma unroll
    for (int mt = 0; mt < 2; ++mt)
#pragma unroll
        for (int nt = 0; nt < 2; ++nt)
#pragma unroll
            for (int r = 0; r < 4; ++r) {
                const int t1 = wr * 32 + mt * 16 + (lid >> 2) + ((r >> 1) ? 8 : 0);
                const int t2 = wc * 16 + nt * 8 + (lid & 3) * 2 + (r & 1);
                float pv = 0.f;
                if (t1 >= t2)
                    pv = __expf(s_cum[t1] - s_cum[t2]) * gacc[mt][nt][r] * s_dt[t2];
                const __nv_bfloat16 hb = __float2bfloat16(pv);
                const __nv_bfloat16 lb = __float2bfloat16(pv - __bfloat162float(hb));
                *(unsigned short*)(smem + SM_PH + t1 * PX + t2 * 2) =
                    __bfloat16_as_ushort(hb);
                *(unsigned short*)(smem + SM_PL + t1 * PX + t2 * 2) =
                    __bfloat16_as_ushort(lb);
            }
    __syncthreads();

    // ---- Y_intra = P·X ----
    {
        float yacc[2][2][4];
#pragma unroll
        for (int i = 0; i < 2; i++)
#pragma unroll
            for (int j = 0; j < 2; j++)
#pragma unroll
                for (int k = 0; k < 4; k++) yacc[i][j][k] = 0.f;
#pragma unroll
        for (int ks = 0; ks < 4; ++ks) {
            uint32_t ah[2][4], al[2][4], bh2[2][2], bl2[2][2];
            const int arow = wr * 32 + (lid & 15);
            const int akc  = ks * 2 + (lid >> 4);
#pragma unroll
            for (int mt = 0; mt < 2; ++mt) {
                const uint32_t a = sb + SM_PH + (arow + mt * 16) * PX + akc * 16;
                ldmatrix_x4(ah[mt], a);
                ldmatrix_x4(al[mt], a + (SM_PL - SM_PH));
            }
            const int brow = wc * 16 + (lid & 7);
            const int bkc  = ks * 2 + ((lid >> 3) & 1);
#pragma unroll
            for (int nt = 0; nt < 2; ++nt) {
                const uint32_t bp = sb + SM_XH + (brow + nt * 8) * PX + bkc * 16;
                ldmatrix_x2(bh2[nt], bp);
                ldmatrix_x2(bl2[nt], bp + (SM_XL - SM_XH));
            }
#pragma unroll
            for (int mt = 0; mt < 2; ++mt)
#pragma unroll
                for (int nt = 0; nt < 2; ++nt) {
                    mma_bf16(yacc[mt][nt], ah[mt], bh2[nt]);
                    mma_bf16(yacc[mt][nt], ah[mt], bl2[nt]);
                    mma_bf16(yacc[mt][nt], al[mt], bh2[nt]);
                }
        }
#pragma unroll
        for (int mt = 0; mt < 2; ++mt)
#pragma unroll
            for (int nt = 0; nt < 2; ++nt) {
                const int t0 = wr * 32 + mt * 16 + (lid >> 2);
                const int p0 = wc * 16 + nt * 8 + (lid & 3) * 2;
                *(float2*)(g_y + (tb + t0) * DINNER + h * HEADDIM + p0) =
                    make_float2(yacc[mt][nt][0], yacc[mt][nt][1]);
                *(float2*)(g_y + (tb + t0 + 8) * DINNER + h * HEADDIM + p0) =
                    make_float2(yacc[mt][nt][2], yacc[mt][nt][3]);
            }
    }
    __syncthreads();

    // ---- Xw[p][j] = x[j,p] * w_j into P region ----
    {
        const int p = tid >> 2, j0 = (tid & 3) * 16;
#pragma unroll
        for (int j = 0; j < 16; ++j) {
            const int jj = j0 + j;
            const float xv =
                __bfloat162float(__ushort_as_bfloat16(
                    *(unsigned short*)(smem + SM_XH + p * PX + jj * 2))) +
                __bfloat162float(__ushort_as_bfloat16(
                    *(unsigned short*)(smem + SM_XL + p * PX + jj * 2)));
            const float xw = xv * s_w[jj];
            const __nv_bfloat16 hb = __float2bfloat16(xw);
            const __nv_bfloat16 lb = __float2bfloat16(xw - __bfloat162float(hb));
            *(unsigned short*)(smem + SM_PH + p * PX + jj * 2) =
                __bfloat16_as_ushort(hb);
            *(unsigned short*)(smem + SM_PL + p * PX + jj * 2) =
                __bfloat16_as_ushort(lb);
        }
    }
    __syncthreads();

    // ---- L = Xw·B (64p x 128n, K=64), trans-B ----
    {
        float lacc[2][4][4];
#pragma unroll
        for (int i = 0; i < 2; i++)
#pragma unroll
            for (int j = 0; j < 4; j++)
#pragma unroll
                for (int k = 0; k < 4; k++) lacc[i][j][k] = 0.f;
#pragma unroll
        for (int ks = 0; ks < 4; ++ks) {
            uint32_t ah[2][4], al[2][4];
            const int arow = wr * 32 + (lid & 15);
            const int akc  = ks * 2 + (lid >> 4);
#pragma unroll
            for (int mt = 0; mt < 2; ++mt) {
                const uint32_t a = sb + SM_PH + (arow + mt * 16) * PX + akc * 16;
                ldmatrix_x4(ah[mt], a);
                ldmatrix_x4(al[mt], a + (SM_PL - SM_PH));
            }
            const int j0 = ks * 16 + (lid & 15);
#pragma unroll
            for (int nt = 0; nt < 4; ++nt) {
                const int n0 = wc * 32 + nt * 8;
                uint32_t bh2[2], bl2[2];
                const uint32_t bp = sb + SM_BH + j0 * PB + n0 * 2;
                ldmatrix_x2_trans(bh2, bp);
                ldmatrix_x2_trans(bl2, bp + (SM_BL - SM_BH));
#pragma unroll
                for (int mt = 0; mt < 2; ++mt) {
                    mma_bf16(lacc[mt][nt], ah[mt], bh2);
                    mma_bf16(lacc[mt][nt], ah[mt], bl2);
                    mma_bf16(lacc[mt][nt], al[mt], bh2);
                }
            }
        }
        float* Lout = g_cstate +
            (((size_t)b * NHEADS + h) * NCH + ch) * (HEADDIM * DSTATE);
#pragma unroll
        for (int mt = 0; mt < 2; ++mt)
#pragma unroll
            for (int nt = 0; nt < 4; ++nt) {
                const int p0 = wr * 32 + mt * 16 + (lid >> 2);
                const int n0 = wc * 32 + nt * 8 + (lid & 3) * 2;
                *(float2*)(Lout + (size_t)p0 * DSTATE + n0) =
                    make_float2(lacc[mt][nt][0], lacc[mt][nt][1]);
                *(float2*)(Lout + (size_t)(p0 + 8) * DSTATE + n0) =
                    make_float2(lacc[mt][nt][2], lacc[mt][nt][3]);
            }
    }
}

// ---------------------------------------------------------------------------
// Sequential combine over chunks — writes entry states pre-split to bf16 hi/lo
// ---------------------------------------------------------------------------
__global__ __launch_bounds__(256) void combine_kernel()
{
    const int h = blockIdx.x, b = blockIdx.y;
    const int tid = threadIdx.x;
    const size_t off = (size_t)tid * 32;
    float4 acc[8];
#pragma unroll
    for (int r = 0; r < 8; r++) acc[r] = make_float4(0.f, 0.f, 0.f, 0.f);

    for (int c = 0; c < NCH; ++c) {
        const size_t base = (((size_t)b * NHEADS + h) * NCH + c) * (HEADDIM * DSTATE);
#pragma unroll
        for (int r = 0; r < 8; r++) {
            uint2 hi, lo;
            split4(acc[r], hi, lo);
            *(uint2*)(g_isth + base + off + r * 4) = hi;
            *(uint2*)(g_istl + base + off + r * 4) = lo;
        }
        const float P = g_ptot[((size_t)b * NHEADS + h) * NCH + c];
#pragma unroll
        for (int r = 0; r < 8; r++) {
            const float4 f = *(const float4*)(g_cstate + base + off + r * 4);
            acc[r].x = fmaf(acc[r].x, P, f.x);
            acc[r].y = fmaf(acc[r].y, P, f.y);
            acc[r].z = fmaf(acc[r].z, P, f.z);
            acc[r].w = fmaf(acc[r].w, P, f.w);
        }
    }
}

// ---------------------------------------------------------------------------
// Inter-chunk: Y[t,p] += ecum_t * (C_t · S0[p,:]) — staging via uint4 copies
// ---------------------------------------------------------------------------
#define ISM_CH 0
#define ISM_CL 17408
#define ISM_SH 34816
#define ISM_SL 52224
#define ISM_EC 69632
#define INTER_SMEM 69888

__global__ void __launch_bounds__(256) inter_kernel()
{
    extern __shared__ __align__(128) char smem[];
    const uint32_t sb = smem_u32(smem);
    const int ch = blockIdx.x + 1, h = blockIdx.y, b = blockIdx.z;
    const int tid = threadIdx.x;
    const int wid = tid >> 5, lid = tid & 31;
    const int wr = wid & 1, wc = wid >> 1;
    const size_t tb = (size_t)b * SEQLEN + (size_t)ch * CT;

    {
        const int row = tid >> 2, c0 = (tid & 3) * 32;
        const size_t co = (tb + row) * CONVDIM + DINNER + DSTATE + c0;
        const size_t so = (((size_t)b * NHEADS + h) * NCH + ch) * (HEADDIM * DSTATE)
                        + (size_t)row * DSTATE + c0;
#pragma unroll
        for (int c = 0; c < 32; c += 8) {
            *(uint4*)(smem + ISM_CH + row * PB + (c0 + c) * 2) =
                *(const uint4*)(g_cvh + co + c);
            *(uint4*)(smem + ISM_CL + row * PB + (c0 + c) * 2) =
                *(const uint4*)(g_cvl + co + c);
            *(uint4*)(smem + ISM_SH + row * PB + (c0 + c) * 2) =
                *(const uint4*)(g_isth + so + c);
            *(uint4*)(smem + ISM_SL + row * PB + (c0 + c) * 2) =
                *(const uint4*)(g_istl + so + c);
        }
    }
    if (tid < 64)
        ((float*)(smem + ISM_EC))[tid] = g_ecum[(tb + tid) * NHEADS + h];
    __syncthreads();

    float acc[2][2][4];
#pragma unroll
    for (int i = 0; i < 2; i++)
#pragma unroll
        for (int j = 0; j < 2; j++)
#pragma unroll
            for (int k = 0; k < 4; k++) acc[i][j][k] = 0.f;

#pragma unroll
    for (int ks = 0; ks < 8; ++ks) {
        uint32_t ah[2][4], al[2][4], bh2[2][2], bl2[2][2];
        const int arow = wr * 32 + (lid & 15);
        const int akc  = ks * 2 + (lid >> 4);
#pragma unroll
        for (int mt = 0; mt < 2; ++mt) {
            const uint32_t a = sb + ISM_CH + (arow + mt * 16) * PB + akc * 16;
            ldmatrix_x4(ah[mt], a);
            ldmatrix_x4(al[mt], a + (ISM_CL - ISM_CH));
        }
        const int brow = wc * 16 + (lid & 7);
        const int bkc  = ks * 2 + ((lid >> 3) & 1);
#pragma unroll
        for (int nt = 0; nt < 2; ++nt) {
            const uint32_t bp = sb + ISM_SH + (brow + nt * 8) * PB + bkc * 16;
            ldmatrix_x2(bh2[nt], bp);
            ldmatrix_x2(bl2[nt], bp + (ISM_SL - ISM_SH));
        }
#pragma unroll
        for (int mt = 0; mt < 2; ++mt)
#pragma unroll
            for (int nt = 0; nt < 2; ++nt) {
                mma_bf16(acc[mt][nt], ah[mt], bh2[nt]);
                mma_bf16(acc[mt][nt], ah[mt], bl2[nt]);
                mma_bf16(acc[mt][nt], al[mt], bh2[nt]);
            }
    }

    const float* s_ec = (const float*)(smem + ISM_EC);
#pragma unroll
    for (int mt = 0; mt < 2; ++mt)
#pragma unroll
        for (int nt = 0; nt < 2; ++nt) {
            const int t0 = wr * 32 + mt * 16 + (lid >> 2);
            const int p0 = wc * 16 + nt * 8 + (lid & 3) * 2;
            {
                float* yp = g_y + (tb + t0) * DINNER + h * HEADDIM + p0;
                float2 o = *(float2*)yp;
                o.x += s_ec[t0] * acc[mt][nt][0];
                o.y += s_ec[t0] * acc[mt][nt][1];
                *(float2*)yp = o;
            }
            {
                float* yp = g_y + (tb + t0 + 8) * DINNER + h * HEADDIM + p0;
                float2 o = *(float2*)yp;
                o.x += s_ec[t0 + 8] * acc[mt][nt][2];
                o.y += s_ec[t0 + 8] * acc[mt][nt][3];
                *(float2*)yp = o;
            }
        }
}

// ---------------------------------------------------------------------------
// y += x*D; yz = y*silu(z); RMSNorm(yz) * norm_w -> bf16 hi/lo
// ---------------------------------------------------------------------------
__global__ __launch_bounds__(256) void gate_norm_kernel(
    const float* __restrict__ Dv, const float* __restrict__ nw)
{
    const int bt = blockIdx.x;
    const float* zrow = g_zx   + (size_t)bt * DINPROJ;
    const float* xrow = g_conv + (size_t)bt * CONVDIM;
    const float* yrow = g_y    + (size_t)bt * DINNER;

    float v[6];
    float ss = 0.f;
#pragma unroll
    for (int i = 0; i < 6; i++) {
        const int c = threadIdx.x + i * 256;
        const float yv = fmaf(xrow[c], Dv[c >> 6], yrow[c]);
        const float z  = zrow[c];
        const float gz = z / (1.f + __expf(-z));
        const float val = yv * gz;
        v[i] = val;
        ss = fmaf(val, val, ss);
    }
#pragma unroll
    for (int o = 16; o; o >>= 1) ss += __shfl_xor_sync(0xffffffffu, ss, o);
    __shared__ float sred[8];
    if ((threadIdx.x & 31) == 0) sred[threadIdx.x >> 5] = ss;
    __syncthreads();
    float tot = 0.f;
#pragma unroll
    for (int i = 0; i < 8; i++) tot += sred[i];
    const float scale = rsqrtf(tot * (1.f / DINNER) + 1e-5f);

    __nv_bfloat16* yh = g_yn_hi + (size_t)bt * DINNER;
    __nv_bfloat16* yl = g_yn_lo + (size_t)bt * DINNER;
#pragma unroll
    for (int i = 0; i < 6; i++) {
        const int c = threadIdx.x + i * 256;
        const float val = v[i] * scale * nw[c];
        const __nv_bfloat16 hb = __float2bfloat16(val);
        yh[c] = hb;
        yl[c] = __float2bfloat16(val - __bfloat162float(hb));
    }
}

// ---------------------------------------------------------------------------
// Launch
// ---------------------------------------------------------------------------
extern "C" void kernel_launch(void* const* d_in, const int* in_sizes, int n_in,
                              void* d_out, int out_size)
{
    const float* u          = (const float*)d_in[0];
    const float* in_proj_w  = (const float*)d_in[1];
    const float* conv_w     = (const float*)d_in[2];
    const float* conv_b     = (const float*)d_in[3];
    const float* dt_bias    = (const float*)d_in[4];
    const float* A_log      = (const float*)d_in[5];
    const float* Dv         = (const float*)d_in[6];
    const float* norm_w     = (const float*)d_in[7];
    const float* out_proj_w = (const float*)d_in[8];
    float* out = (float*)d_out;

    float* zx = nullptr;
    __nv_bfloat16 *uh, *ul, *w1h, *w1l, *w2h, *w2l, *ynh, *ynl;
    cudaGetSymbolAddress((void**)&zx,  g_zx);
    cudaGetSymbolAddress((void**)&uh,  g_u_hi);
    cudaGetSymbolAddress((void**)&ul,  g_u_lo);
    cudaGetSymbolAddress((void**)&w1h, g_w1_hi);
    cudaGetSymbolAddress((void**)&w1l, g_w1_lo);
    cudaGetSymbolAddress((void**)&w2h, g_w2_hi);
    cudaGetSymbolAddress((void**)&w2l, g_w2_lo);
    cudaGetSymbolAddress((void**)&ynh, g_yn_hi);
    cudaGetSymbolAddress((void**)&ynl, g_yn_lo);

    cudaFuncSetAttribute(gemm_mma,
                         cudaFuncAttributeMaxDynamicSharedMemorySize, GEMM_SMEM);
    cudaFuncSetAttribute(chunk_kernel,
                         cudaFuncAttributeMaxDynamicSharedMemorySize, CHUNK_SMEM);
    cudaFuncSetAttribute(inter_kernel,
                         cudaFuncAttributeMaxDynamicSharedMemorySize, INTER_SMEM);

    // 0) bf16 hi/lo splits for GEMM operands
    split_kernel<<<(NTOK * DMODEL + 255) / 256, 256>>>(u, uh, ul, NTOK * DMODEL);
    split_kernel<<<(DINPROJ * DMODEL + 255) / 256, 256>>>(in_proj_w, w1h, w1l,
                                                          DINPROJ * DMODEL);
    split_kernel<<<(DMODEL * DINNER + 255) / 256, 256>>>(out_proj_w, w2h, w2l,
                                                         DMODEL * DINNER);

    // 1) zxbcdt = u @ in_proj_w^T — HMMA bf16x3 (frozen R9 config)
    dim3 g1((DINPROJ + 127) / 128, NTOK / 128);
    gemm_mma<<<g1, 256, GEMM_SMEM>>>(uh, ul, w1h, w1l, zx,
                                     NTOK, DINPROJ, DMODEL);

    // 2) depthwise causal conv + silu (+ one-time bf16 hi/lo emit)
    conv_silu_kernel<<<(NTOK * CONVDIM + 255) / 256, 256>>>(conv_w, conv_b);

    // 3) dt softplus / log-decay a
    dt_kernel<<<(NTOK * NHEADS + 255) / 256, 256>>>(dt_bias, A_log);

    // 4) SSD chunk pass — tensor cores, conversion-free staging
    chunk_kernel<<<dim3(NCH, NHEADS, BATCH), 256, CHUNK_SMEM>>>();

    // 5) combine chunk states sequentially (emits bf16 hi/lo entry states)
    combine_kernel<<<dim3(NHEADS, BATCH), 256>>>();

    // 6) inter-chunk contribution — tensor cores, conversion-free staging
    inter_kernel<<<dim3(NCH - 1, NHEADS, BATCH), 256, INTER_SMEM>>>();

    // 7) gate + RMSNorm -> bf16 hi/lo
    gate_norm_kernel<<<NTOK, 256>>>(Dv, norm_w);

    // 8) out = yn @ out_proj_w^T — HMMA bf16x3
    dim3 g2((DMODEL + 127) / 128, NTOK / 128);
    gemm_mma<<<g2, 256, GEMM_SMEM>>>(ynh, ynl, w2h, w2l, out,
                                     NTOK, DMODEL, DINNER);
}

// round 15
// speedup vs baseline: 1.2612x; 1.0629x over previous
#include <cuda_runtime.h>
#include <cuda_bf16.h>
#include <math.h>
#include <stdint.h>

#define BATCH   2
#define SEQLEN  2048
#define NTOK    (BATCH*SEQLEN)        // 4096
#define DMODEL  768
#define DINNER  1536
#define DSTATE  128
#define HEADDIM 64
#define NHEADS  24
#define CONVDIM 1792                  // DINNER + 2*DSTATE
#define DINPROJ 3352                  // 2*DINNER + 2*DSTATE + NHEADS
#define CT      64                    // chunk tokens
#define NCH     (SEQLEN/CT)           // 32 chunks per sequence

// ---------------------------------------------------------------------------
// Scratch buffers (device globals — no allocations allowed)
// ---------------------------------------------------------------------------
__device__ __align__(128) float g_zx[NTOK * DINPROJ];     // in_proj output
__device__ __align__(128) float g_conv[NTOK * CONVDIM];   // conv+silu fp32 (x slice only)
__device__ __align__(128) __nv_bfloat16 g_cvh[NTOK * CONVDIM]; // conv out bf16 hi
__device__ __align__(128) __nv_bfloat16 g_cvl[NTOK * CONVDIM]; // conv out bf16 lo
__device__ __align__(128) float g_dt[NTOK * NHEADS];      // softplus(dt + bias)
__device__ __align__(128) float g_a[NTOK * NHEADS];       // A * dt  (log decay)
__device__ __align__(128) float g_ecum[NTOK * NHEADS];    // exp(within-chunk cumsum)
__device__ __align__(128) float g_ptot[BATCH*NHEADS*NCH]; // per-chunk total decay
__device__ __align__(128) float g_y[NTOK * DINNER];       // scan output
__device__ __align__(128) float g_cstate[BATCH*NHEADS*NCH*HEADDIM*DSTATE]; // chunk-local states
__device__ __align__(128) __nv_bfloat16 g_isth[BATCH*NHEADS*NCH*HEADDIM*DSTATE]; // entry states hi
__device__ __align__(128) __nv_bfloat16 g_istl[BATCH*NHEADS*NCH*HEADDIM*DSTATE]; // entry states lo

// bf16 hi/lo split operands for tensor-core GEMMs
__device__ __align__(128) __nv_bfloat16 g_u_hi[NTOK * DMODEL];
__device__ __align__(128) __nv_bfloat16 g_u_lo[NTOK * DMODEL];
__device__ __align__(128) __nv_bfloat16 g_w1_hi[DINPROJ * DMODEL];
__device__ __align__(128) __nv_bfloat16 g_w1_lo[DINPROJ * DMODEL];
__device__ __align__(128) __nv_bfloat16 g_w2_hi[DMODEL * DINNER];
__device__ __align__(128) __nv_bfloat16 g_w2_lo[DMODEL * DINNER];
__device__ __align__(128) __nv_bfloat16 g_yn_hi[NTOK * DINNER];
__device__ __align__(128) __nv_bfloat16 g_yn_lo[NTOK * DINNER];

// ---------------------------------------------------------------------------
// MMA helpers
// ---------------------------------------------------------------------------
static __device__ __forceinline__ uint32_t smem_u32(const void* p) {
    return (uint32_t)__cvta_generic_to_shared(p);
}

static __device__ __forceinline__ void mma_bf16(
    float* d, const uint32_t* a, const uint32_t* b)
{
    asm volatile(
        "mma.sync.aligned.m16n8k16.row.col.f32.bf16.bf16.f32 "
        "{%0,%1,%2,%3}, {%4,%5,%6,%7}, {%8,%9}, {%0,%1,%2,%3};"
        : "+f"(d[0]), "+f"(d[1]), "+f"(d[2]), "+f"(d[3])
        : "r"(a[0]), "r"(a[1]), "r"(a[2]), "r"(a[3]), "r"(b[0]), "r"(b[1]));
}

static __device__ __forceinline__ void ldmatrix_x4(uint32_t* r, uint32_t addr)
{
    asm volatile("ldmatrix.sync.aligned.m8n8.x4.shared.b16 {%0,%1,%2,%3}, [%4];"
                 : "=r"(r[0]), "=r"(r[1]), "=r"(r[2]), "=r"(r[3]) : "r"(addr));
}

static __device__ __forceinline__ void ldmatrix_x2(uint32_t* r, uint32_t addr)
{
    asm volatile("ldmatrix.sync.aligned.m8n8.x2.shared.b16 {%0,%1}, [%2];"
                 : "=r"(r[0]), "=r"(r[1]) : "r"(addr));
}

static __device__ __forceinline__ void ldmatrix_x2_trans(uint32_t* r, uint32_t addr)
{
    asm volatile("ldmatrix.sync.aligned.m8n8.x2.trans.shared.b16 {%0,%1}, [%2];"
                 : "=r"(r[0]), "=r"(r[1]) : "r"(addr));
}

static __device__ __forceinline__ void cp16(uint32_t dst, const void* src, int sz)
{
    asm volatile("cp.async.cg.shared.global [%0], [%1], 16, %2;"
                 :: "r"(dst), "l"(src), "r"(sz));
}

// split fp32x4 into packed bf16 hi/lo (uint2 each)
static __device__ __forceinline__ void split4(float4 v, uint2& hi, uint2& lo)
{
    __nv_bfloat16 h0=__float2bfloat16(v.x), h1=__float2bfloat16(v.y),
                  h2=__float2bfloat16(v.z), h3=__float2bfloat16(v.w);
    __nv_bfloat16 l0=__float2bfloat16(v.x-__bfloat162float(h0)),
                  l1=__float2bfloat16(v.y-__bfloat162float(h1)),
                  l2=__float2bfloat16(v.z-__bfloat162float(h2)),
                  l3=__float2bfloat16(v.w-__bfloat162float(h3));
    hi.x = ((uint32_t)__bfloat16_as_ushort(h1)<<16) | __bfloat16_as_ushort(h0);
    hi.y = ((uint32_t)__bfloat16_as_ushort(h3)<<16) | __bfloat16_as_ushort(h2);
    lo.x = ((uint32_t)__bfloat16_as_ushort(l1)<<16) | __bfloat16_as_ushort(l0);
    lo.y = ((uint32_t)__bfloat16_as_ushort(l3)<<16) | __bfloat16_as_ushort(l2);
}

// ---------------------------------------------------------------------------
// bf16x3 GEMM via mma.sync, 128x128 tile (R9 proven config — for GEMM1)
// ---------------------------------------------------------------------------
#define ROWB   80
#define MATB   (128 * ROWB)
#define STAGEB (4 * MATB)                 // 40960
#define GEMM_SMEM (2 * STAGEB)            // 81920

__global__ void __launch_bounds__(256) gemm_mma(
    const __nv_bfloat16* __restrict__ Ah, const __nv_bfloat16* __restrict__ Al,
    const __nv_bfloat16* __restrict__ Bh, const __nv_bfloat16* __restrict__ Bl,
    float* __restrict__ C, int M, int N, int K)
{
    extern __shared__ __align__(128) char smem[];
    const uint32_t sb = smem_u32(smem);
    const int tid = threadIdx.x;
    const int wid = tid >> 5, lid = tid & 31;
    const int bm = blockIdx.y * 128;
    const int bn = blockIdx.x * 128;
    const int wr = wid & 1;
    const int wc = wid >> 1;

    float acc[4][4][4];
#pragma unroll
    for (int i = 0; i < 4; i++)
#pragma unroll
        for (int j = 0; j < 4; j++)
#pragma unroll
            for (int k = 0; k < 4; k++) acc[i][j][k] = 0.f;

    const int lrow = tid >> 1;
    const int lch  = (tid & 1) * 2;
    const int bok  = (bn + lrow) < N ? 16 : 0;
    const size_t arowoff = (size_t)(bm + lrow) * K;
    const size_t browoff = (size_t)(bok ? (bn + lrow) : 0) * K;
    const uint32_t dst0 = sb + lrow * ROWB + lch * 16;

    const int NC = K >> 5;

    {
        const size_t ao = arowoff + lch * 8;
        const size_t bo = browoff + lch * 8;
        cp16(dst0,             Ah + ao, 16); cp16(dst0 + 16,            Ah + ao + 8, 16);
        cp16(dst0 + MATB,      Al + ao, 16); cp16(dst0 + MATB + 16,     Al + ao + 8, 16);
        cp16(dst0 + 2*MATB,    Bh + bo, bok); cp16(dst0 + 2*MATB + 16,  Bh + bo + 8, bok);
        cp16(dst0 + 3*MATB,    Bl + bo, bok); cp16(dst0 + 3*MATB + 16,  Bl + bo + 8, bok);
        asm volatile("cp.async.commit_group;");
    }

    for (int c = 0; c < NC; ++c) {
        if (c + 1 < NC) {
            const uint32_t d = dst0 + ((c + 1) & 1) * STAGEB;
            const size_t ao = arowoff + (size_t)(c + 1) * 32 + lch * 8;
            const size_t bo = browoff + (size_t)(c + 1) * 32 + lch * 8;
            cp16(d,            Ah + ao, 16); cp16(d + 16,           Ah + ao + 8, 16);
            cp16(d + MATB,     Al + ao, 16); cp16(d + MATB + 16,    Al + ao + 8, 16);
            cp16(d + 2*MATB,   Bh + bo, bok); cp16(d + 2*MATB + 16, Bh + bo + 8, bok);
            cp16(d + 3*MATB,   Bl + bo, bok); cp16(d + 3*MATB + 16, Bl + bo + 8, bok);
            asm volatile("cp.async.commit_group;");
            asm volatile("cp.async.wait_group 1;");
        } else {
            asm volatile("cp.async.wait_group 0;");
        }
        __syncthreads();

        const uint32_t st = sb + (c & 1) * STAGEB;
#pragma unroll
        for (int ks = 0; ks < 2; ++ks) {
            uint32_t ah[4][4], al[4][4], bh[4][2], bl[4][2];
            const int arow = wr * 64 + (lid & 15);
            const int akc  = ks * 2 + (lid >> 4);
#pragma unroll
            for (int mt = 0; mt < 4; ++mt) {
                const uint32_t a = st + (arow + mt * 16) * ROWB + akc * 16;
                ldmatrix_x4(ah[mt], a);
                ldmatrix_x4(al[mt], a + MATB);
            }
            const int brow = wc * 32 + (lid & 7);
            const int bkc  = ks * 2 + ((lid >> 3) & 1);
#pragma unroll
            for (int nt = 0; nt < 4; ++nt) {
                const uint32_t b = st + 2*MATB + (brow + nt * 8) * ROWB + bkc * 16;
                ldmatrix_x2(bh[nt], b);
                ldmatrix_x2(bl[nt], b + MATB);
            }
#pragma unroll
            for (int mt = 0; mt < 4; ++mt)
#pragma unroll
                for (int nt = 0; nt < 4; ++nt) {
                    mma_bf16(acc[mt][nt], ah[mt], bh[nt]);
                    mma_bf16(acc[mt][nt], ah[mt], bl[nt]);
                    mma_bf16(acc[mt][nt], al[mt], bh[nt]);
                }
        }
        __syncthreads();
    }

    const int mbase = bm + wr * 64 + (lid >> 2);
    const int nbase = bn + wc * 32 + (lid & 3) * 2;
#pragma unroll
    for (int mt = 0; mt < 4; ++mt) {
#pragma unroll
        for (int nt = 0; nt < 4; ++nt) {
            const int n0 = nbase + nt * 8;
            if (n0 < N) {
                const int m0 = mbase + mt * 16;
                float2 v0 = make_float2(acc[mt][nt][0], acc[mt][nt][1]);
                float2 v1 = make_float2(acc[mt][nt][2], acc[mt][nt][3]);
                *(float2*)(C + (size_t)m0 * N + n0)       = v0;
                *(float2*)(C + (size_t)(m0 + 8) * N + n0) = v1;
            }
        }
    }
}

// ---------------------------------------------------------------------------
// bf16x3 GEMM, 64x128 CTA tile (for GEMM2: M=4096 gives 384 blocks -> no
// wave quantization; 8 warps at 32x32 warp tiles; 61440B smem -> 2 CTA/SM)
// ---------------------------------------------------------------------------
#define AMATB64 (64 * ROWB)                 // 5120
#define STAGE64 (2 * AMATB64 + 2 * MATB)    // 30720
#define GEMM64_SMEM (2 * STAGE64)           // 61440

__global__ void __launch_bounds__(256) gemm_mma64(
    const __nv_bfloat16* __restrict__ Ah, const __nv_bfloat16* __restrict__ Al,
    const __nv_bfloat16* __restrict__ Bh, const __nv_bfloat16* __restrict__ Bl,
    float* __restrict__ C, int M, int N, int K)
{
    extern __shared__ __align__(128) char smem[];
    const uint32_t sb = smem_u32(smem);
    const int tid = threadIdx.x;
    const int wid = tid >> 5, lid = tid & 31;
    const int bm = blockIdx.y * 64;
    const int bn = blockIdx.x * 128;
    const int wr = wid & 1;               // m-half (x32)
    const int wc = wid >> 1;              // n-quarter (x32)

    float acc[2][4][4];
#pragma unroll
    for (int i = 0; i < 2; i++)
#pragma unroll
        for (int j = 0; j < 4; j++)
#pragma unroll
            for (int k = 0; k < 4; k++) acc[i][j][k] = 0.f;

    // A staging: row = tid>>2 (0..63), chunk tid&3 (1 cp16 per matrix)
    const int alrow = tid >> 2;
    const int alch  = tid & 3;
    const size_t arowoff = (size_t)(bm + alrow) * K + alch * 8;
    const uint32_t adst0 = sb + alrow * ROWB + alch * 16;
    // B staging: row = tid>>1 (0..127), chunks (tid&1)*2 (2 cp16 per matrix)
    const int blrow = tid >> 1;
    const int blch  = (tid & 1) * 2;
    const int bok   = (bn + blrow) < N ? 16 : 0;
    const size_t browoff = (size_t)(bok ? (bn + blrow) : 0) * K + blch * 8;
    const uint32_t bdst0 = sb + 2 * AMATB64 + blrow * ROWB + blch * 16;

    const int NC = K >> 5;

    auto stage_issue = [&](int c) {
        const uint32_t so = (uint32_t)(c & 1) * STAGE64;
        const size_t ao = arowoff + (size_t)c * 32;
        const size_t bo = browoff + (size_t)c * 32;
        const uint32_t ad = adst0 + so;
        const uint32_t bd = bdst0 + so;
        cp16(ad,           Ah + ao, 16);
        cp16(ad + AMATB64, Al + ao, 16);
        cp16(bd,           Bh + bo, bok); cp16(bd + 16,        Bh + bo + 8, bok);
        cp16(bd + MATB,    Bl + bo, bok); cp16(bd + MATB + 16, Bl + bo + 8, bok);
        asm volatile("cp.async.commit_group;");
    };

    stage_issue(0);

    for (int c = 0; c < NC; ++c) {
        if (c + 1 < NC) {
            stage_issue(c + 1);
            asm volatile("cp.async.wait_group 1;");
        } else {
            asm volatile("cp.async.wait_group 0;");
        }
        __syncthreads();

        const uint32_t st = sb + (uint32_t)(c & 1) * STAGE64;
#pragma unroll
        for (int ks = 0; ks < 2; ++ks) {
            uint32_t ah[2][4], al[2][4], bh[4][2], bl[4][2];
            const int arow = wr * 32 + (lid & 15);
            const int akc  = ks * 2 + (lid >> 4);
#pragma unroll
            for (int mt = 0; mt < 2; ++mt) {
                const uint32_t a = st + (arow + mt * 16) * ROWB + akc * 16;
                ldmatrix_x4(ah[mt], a);
                ldmatrix_x4(al[mt], a + AMATB64);
            }
            const int brow = wc * 32 + (lid & 7);
            const int bkc  = ks * 2 + ((lid >> 3) & 1);
#pragma unroll
            for (int nt = 0; nt < 4; ++nt) {
                const uint32_t b = st + 2 * AMATB64 + (brow + nt * 8) * ROWB + bkc * 16;
                ldmatrix_x2(bh[nt], b);
                ldmatrix_x2(bl[nt], b + MATB);
            }
#pragma unroll
            for (int mt = 0; mt < 2; ++mt)
#pragma unroll
                for (int nt = 0; nt < 4; ++nt) {
                    mma_bf16(acc[mt][nt], ah[mt], bh[nt]);
                    mma_bf16(acc[mt][nt], ah[mt], bl[nt]);
                    mma_bf16(acc[mt][nt], al[mt], bh[nt]);
                }
        }
        __syncthreads();
    }

    const int mbase = bm + wr * 32 + (lid >> 2);
    const int nbase = bn + wc * 32 + (lid & 3) * 2;
#pragma unroll
    for (int mt = 0; mt < 2; ++mt) {
#pragma unroll
        for (int nt = 0; nt < 4; ++nt) {
            const int n0 = nbase + nt * 8;
            if (n0 < N) {
                const int m0 = mbase + mt * 16;
                float2 v0 = make_float2(acc[mt][nt][0], acc[mt][nt][1]);
                float2 v1 = make_float2(acc[mt][nt][2], acc[mt][nt][3]);
                *(float2*)(C + (size_t)m0 * N + n0)       = v0;
                *(float2*)(C + (size_t)(m0 + 8) * N + n0) = v1;
            }
        }
    }
}

// ---------------------------------------------------------------------------
// fp32 -> bf16 hi/lo split
// ---------------------------------------------------------------------------
__global__ void split_kernel(const float* __restrict__ src,
                             __nv_bfloat16* __restrict__ hi,
                             __nv_bfloat16* __restrict__ lo, int n)
{
    const int i = blockIdx.x * 256 + threadIdx.x;
    if (i >= n) return;
    const float x = src[i];
    const __nv_bfloat16 h = __float2bfloat16(x);
    hi[i] = h;
    lo[i] = __float2bfloat16(x - __bfloat162float(h));
}

// ---------------------------------------------------------------------------
// Depthwise causal conv (width 4) + bias + SiLU.
// bf16 hi/lo emitted for all channels; fp32 only for the x slice (gate_norm).
// ---------------------------------------------------------------------------
__global__ void conv_silu_kernel(const float* __restrict__ cw,
                                 const float* __restrict__ cb)
{
    const int idx = blockIdx.x * 256 + threadIdx.x;
    if (idx >= NTOK * CONVDIM) return;
    const int c  = idx % CONVDIM;
    const int bt = idx / CONVDIM;
    const int t  = bt % SEQLEN;
    float acc = cb[c];
#pragma unroll
    for (int k = 0; k < 4; k++) {
        const int tt = t - 3 + k;
        if (tt >= 0)
            acc = fmaf(cw[c * 4 + k],
                       g_zx[((size_t)bt + k - 3) * DINPROJ + DINNER + c], acc);
    }
    const float v = acc / (1.f + __expf(-acc));   // silu
    if (c < DINNER) g_conv[idx] = v;              // fp32 only where still read
    const __nv_bfloat16 hb = __float2bfloat16(v);
    g_cvh[idx] = hb;
    g_cvl[idx] = __float2bfloat16(v - __bfloat162float(hb));
}

// ---------------------------------------------------------------------------
// dt_dis = softplus(dt + dt_bias); a = dt_dis * A  (log decay, negative)
// ---------------------------------------------------------------------------
__global__ void dt_kernel(const float* __restrict__ dt_bias,
                          const float* __restrict__ A_log)
{
    const int idx = blockIdx.x * 256 + threadIdx.x;
    if (idx >= NTOK * NHEADS) return;
    const int h  = idx % NHEADS;
    const int bt = idx / NHEADS;
    const float x  = g_zx[(size_t)bt * DINPROJ + DINNER + CONVDIM + h] + dt_bias[h];
    const float sp = (x > 20.f) ? x : log1pf(expf(x));
    const float Ah = -expf(A_log[h]);
    g_dt[idx] = sp;
    g_a[idx]  = sp * Ah;
}

// ---------------------------------------------------------------------------
// SSD chunk kernel: per (chunk, head, batch) block, 256 threads (8 warps 2x4).
// ---------------------------------------------------------------------------
#define PB 272
#define PX 144
#define SM_BH 0
#define SM_BL 17408
#define SM_CH 34816
#define SM_CL 52224
#define SM_XH 69632
#define SM_XL 78848
#define SM_PH 88064
#define SM_PL 97280
#define SM_CUM 106496
#define SM_DTA 106752
#define SM_WW  107008
#define CHUNK_SMEM 107264

__global__ void __launch_bounds__(256) chunk_kernel()
{
    extern __shared__ __align__(128) char smem[];
    const uint32_t sb = smem_u32(smem);
    const int ch = blockIdx.x, h = blockIdx.y, b = blockIdx.z;
    const int tid = threadIdx.x;
    const int wid = tid >> 5, lid = tid & 31;
    const int wr = wid & 1, wc = wid >> 1;
    const size_t tb = (size_t)b * SEQLEN + (size_t)ch * CT;

    float* s_cum = (float*)(smem + SM_CUM);
    float* s_dt  = (float*)(smem + SM_DTA);
    float* s_w   = (float*)(smem + SM_WW);

    // ---- stage B, C: uint4 copies of pre-split bf16 ----
    {
        const int row = tid >> 2, c0 = (tid & 3) * 32;
        const size_t so = (tb + row) * CONVDIM + DINNER + c0;
#pragma unroll
        for (int c = 0; c < 32; c += 8) {
            *(uint4*)(smem + SM_BH + row * PB + (c0 + c) * 2) =
                *(const uint4*)(g_cvh + so + c);
            *(uint4*)(smem + SM_BL + row * PB + (c0 + c) * 2) =
                *(const uint4*)(g_cvl + so + c);
            *(uint4*)(smem + SM_CH + row * PB + (c0 + c) * 2) =
                *(const uint4*)(g_cvh + so + DSTATE + c);
            *(uint4*)(smem + SM_CL + row * PB + (c0 + c) * 2) =
                *(const uint4*)(g_cvl + so + DSTATE + c);
        }
    }
    // ---- stage X transposed: Xs[p][t] ----
    {
        const int t = tid >> 2, p0 = (tid & 3) * 16;
        const size_t so = (tb + t) * CONVDIM + h * HEADDIM + p0;
#pragma unroll
        for (int p = 0; p < 16; ++p) {
            *(unsigned short*)(smem + SM_XH + (p0 + p) * PX + t * 2) =
                *(const unsigned short*)(g_cvh + so + p);
            *(unsigned short*)(smem + SM_XL + (p0 + p) * PX + t * 2) =
                *(const unsigned short*)(g_cvl + so + p);
        }
    }
    // ---- warp 0: within-chunk inclusive cumsum of a (64) ----
    if (wid == 0) {
        const float a0 = g_a[(tb + 2 * lid)     * NHEADS + h];
        const float a1 = g_a[(tb + 2 * lid + 1) * NHEADS + h];
        const float ps = a0 + a1;
        float sc = ps;
#pragma unroll
        for (int off = 1; off < 32; off <<= 1) {
            const float t = __shfl_up_sync(0xffffffffu, sc, off);
            if (lid >= off) sc += t;
        }
        float excl = __shfl_up_sync(0xffffffffu, sc, 1);
        if (lid == 0) excl = 0.f;
        s_cum[2 * lid]     = excl + a0;
        s_cum[2 * lid + 1] = excl + ps;
    }
    if (tid >= 64 && tid < 128) s_dt[tid - 64] = g_dt[(tb + tid - 64) * NHEADS + h];
    __syncthreads();

    if (tid < 64) {
        const float ct = s_cum[tid], tot = s_cum[63];
        s_w[tid] = expf(tot - ct) * s_dt[tid];
        g_ecum[(tb + tid) * NHEADS + h] = expf(ct);
        if (tid == 63)
            g_ptot[((size_t)b * NHEADS + h) * NCH + ch] = expf(tot);
    }

    // ---- G = C·B^T ----
    float gacc[2][2][4];
#pragma unroll
    for (int i = 0; i < 2; i++)
#pragma unroll
        for (int j = 0; j < 2; j++)
#pragma unroll
            for (int k = 0; k < 4; k++) gacc[i][j][k] = 0.f;
#pragma unroll
    for (int ks = 0; ks < 8; ++ks) {
        uint32_t ah[2][4], al[2][4], bh2[2][2], bl2[2][2];
        const int arow = wr * 32 + (lid & 15);
        const int akc  = ks * 2 + (lid >> 4);
#pragma unroll
        for (int mt = 0; mt < 2; ++mt) {
            const uint32_t a = sb + SM_CH + (arow + mt * 16) * PB + akc * 16;
            ldmatrix_x4(ah[mt], a);
            ldmatrix_x4(al[mt], a + (SM_CL - SM_CH));
        }
        const int brow = wc * 16 + (lid & 7);
        const int bkc  = ks * 2 + ((lid >> 3) & 1);
#pragma unroll
        for (int nt = 0; nt < 2; ++nt) {
            const uint32_t bp = sb + SM_BH + (brow + nt * 8) * PB + bkc * 16;
            ldmatrix_x2(bh2[nt], bp);
            ldmatrix_x2(bl2[nt], bp + (SM_BL - SM_BH));
        }
#pragma unroll
        for (int mt = 0; mt < 2; ++mt)
#pragma unroll
            for (int nt = 0; nt < 2; ++nt) {
                mma_bf16(gacc[mt][nt], ah[mt], bh2[nt]);
                mma_bf16(gacc[mt][nt], ah[mt], bl2[nt]);
                mma_bf16(gacc[mt][nt], al[mt], bh2[nt]);
            }
    }

    // ---- P = mask * G * dt -> smem ----
#pragma unroll
    for (int mt = 0; mt < 2; ++mt)
#pragma unroll
        for (int nt = 0; nt < 2; ++nt)
#pragma unroll
            for (int r = 0; r < 4; ++r) {
                const int t1 = wr * 32 + mt * 16 + (lid >> 2) + ((r >> 1) ? 8 : 0);
                const int t2 = wc * 16 + nt * 8 + (lid & 3) * 2 + (r & 1);
                float pv = 0.f;
                if (t1 >= t2)
                    pv = __expf(s_cum[t1] - s_cum[t2]) * gacc[mt][nt][r] * s_dt[t2];
                const __nv_bfloat16 hb = __float2bfloat16(pv);
                const __nv_bfloat16 lb = __float2bfloat16(pv - __bfloat162float(hb));
                *(unsigned short*)(smem + SM_PH + t1 * PX + t2 * 2) =
                    __bfloat16_as_ushort(hb);
                *(unsigned short*)(smem + SM_PL + t1 * PX + t2 * 2) =
                    __bfloat16_as_ushort(lb);
            }
    __syncthreads();

    // ---- Y_intra = P·X ----
    {
        float yacc[2][2][4];
#pragma unroll
        for (int i = 0; i < 2; i++)
#pragma unroll
            for (int j = 0; j < 2; j++)
#pragma unroll
                for (int k = 0; k < 4; k++) yacc[i][j][k] = 0.f;
#pragma unroll
        for (int ks = 0; ks < 4; ++ks) {
            uint32_t ah[2][4], al[2][4], bh2[2][2], bl2[2][2];
            const int arow = wr * 32 + (lid & 15);
            const int akc  = ks * 2 + (lid >> 4);
#pragma unroll
            for (int mt = 0; mt < 2; ++mt) {
                const uint32_t a = sb + SM_PH + (arow + mt * 16) * PX + akc * 16;
                ldmatrix_x4(ah[mt], a);
                ldmatrix_x4(al[mt], a + (SM_PL - SM_PH));
            }
            const int brow = wc * 16 + (lid & 7);
            const int bkc  = ks * 2 + ((lid >> 3) & 1);
#pragma unroll
            for (int nt = 0; nt < 2; ++nt) {
                const uint32_t bp = sb + SM_XH + (brow + nt * 8) * PX + bkc * 16;
                ldmatrix_x2(bh2[nt], bp);
                ldmatrix_x2(bl2[nt], bp + (SM_XL - SM_XH));
            }
#pragma unroll
            for (int mt = 0; mt < 2; ++mt)
#pragma unroll
                for (int nt = 0; nt < 2; ++nt) {
                    mma_bf16(yacc[mt][nt], ah[mt], bh2[nt]);
                    mma_bf16(yacc[mt][nt], ah[mt], bl2[nt]);
                    mma_bf16(yacc[mt][nt], al[mt], bh2[nt]);
                }
        }
#pragma unroll
        for (int mt = 0; mt < 2; ++mt)
#pragma unroll
            for (int nt = 0; nt < 2; ++nt) {
                const int t0 = wr * 32 + mt * 16 + (lid >> 2);
                const int p0 = wc * 16 + nt * 8 + (lid & 3) * 2;
                *(float2*)(g_y + (tb + t0) * DINNER + h * HEADDIM + p0) =
                    make_float2(yacc[mt][nt][0], yacc[mt][nt][1]);
                *(float2*)(g_y + (tb + t0 + 8) * DINNER + h * HEADDIM + p0) =
                    make_float2(yacc[mt][nt][2], yacc[mt][nt][3]);
            }
    }
    __syncthreads();

    // ---- Xw[p][j] = x[j,p] * w_j into P region ----
    {
        const int p = tid >> 2, j0 = (tid & 3) * 16;
#pragma unroll
        for (int j = 0; j < 16; ++j) {
            const int jj = j0 + j;
            const float xv =
                __bfloat162float(__ushort_as_bfloat16(
                    *(unsigned short*)(smem + SM_XH + p * PX + jj * 2))) +
                __bfloat162float(__ushort_as_bfloat16(
                    *(unsigned short*)(smem + SM_XL + p * PX + jj * 2)));
            const float xw = xv * s_w[jj];
            const __nv_bfloat16 hb = __float2bfloat16(xw);
            const __nv_bfloat16 lb = __float2bfloat16(xw - __bfloat162float(hb));
            *(unsigned short*)(smem + SM_PH + p * PX + jj * 2) =
                __bfloat16_as_ushort(hb);
            *(unsigned short*)(smem + SM_PL + p * PX + jj * 2) =
                __bfloat16_as_ushort(lb);
        }
    }
    __syncthreads();

    // ---- L = Xw·B (64p x 128n, K=64), trans-B ----
    {
        float lacc[2][4][4];
#pragma unroll
        for (int i = 0; i < 2; i++)
#pragma unroll
            for (int j = 0; j < 4; j++)
#pragma unroll
                for (int k = 0; k < 4; k++) lacc[i][j][k] = 0.f;
#pragma unroll
        for (int ks = 0; ks < 4; ++ks) {
            uint32_t ah[2][4], al[2][4];
            const int arow = wr * 32 + (lid & 15);
            const int akc  = ks * 2 + (lid >> 4);
#pragma unroll
            for (int mt = 0; mt < 2; ++mt) {
                const uint32_t a = sb + SM_PH + (arow + mt * 16) * PX + akc * 16;
                ldmatrix_x4(ah[mt], a);
                ldmatrix_x4(al[mt], a + (SM_PL - SM_PH));
            }
            const int j0 = ks * 16 + (lid & 15);
#pragma unroll
            for (int nt = 0; nt < 4; ++nt) {
                const int n0 = wc * 32 + nt * 8;
                uint32_t bh2[2], bl2[2];
                const uint32_t bp = sb + SM_BH + j0 * PB + n0 * 2;
                ldmatrix_x2_trans(bh2, bp);
                ldmatrix_x2_trans(bl2, bp + (SM_BL - SM_BH));
#pragma unroll
                for (int mt = 0; mt < 2; ++mt) {
                    mma_bf16(lacc[mt][nt], ah[mt], bh2);
                    mma_bf16(lacc[mt][nt], ah[mt], bl2);
                    mma_bf16(lacc[mt][nt], al[mt], bh2);
                }
            }
        }
        float* Lout = g_cstate +
            (((size_t)b * NHEADS + h) * NCH + ch) * (HEADDIM * DSTATE);
#pragma unroll
        for (int mt = 0; mt < 2; ++mt)
#pragma unroll
            for (int nt = 0; nt < 4; ++nt) {
                const int p0 = wr * 32 + mt * 16 + (lid >> 2);
                const int n0 = wc * 32 + nt * 8 + (lid & 3) * 2;
                *(float2*)(Lout + (size_t)p0 * DSTATE + n0) =
                    make_float2(lacc[mt][nt][0], lacc[mt][nt][1]);
                *(float2*)(Lout + (size_t)(p0 + 8) * DSTATE + n0) =
                    make_float2(lacc[mt][nt][2], lacc[mt][nt][3]);
            }
    }
}

// ---------------------------------------------------------------------------
// Sequential combine over chunks — 4x parallel slices per (h,b) for latency
// ---------------------------------------------------------------------------
__global__ __launch_bounds__(256) void combine_kernel()
{
    const int h = blockIdx.x, b = blockIdx.y, q = blockIdx.z;
    const int tid = threadIdx.x;
    const size_t off = (size_t)q * 2048 + (size_t)tid * 8;
    float4 acc[2];
#pragma unroll
    for (int r = 0; r < 2; r++) acc[r] = make_float4(0.f, 0.f, 0.f, 0.f);

    for (int c = 0; c < NCH; ++c) {
        const size_t base = (((size_t)b * NHEADS + h) * NCH + c) * (HEADDIM * DSTATE);
#pragma unroll
        for (int r = 0; r < 2; r++) {
            uint2 hi, lo;
            split4(acc[r], hi, lo);
            *(uint2*)(g_isth + base + off + r * 4) = hi;
            *(uint2*)(g_istl + base + off + r * 4) = lo;
        }
        const float P = g_ptot[((size_t)b * NHEADS + h) * NCH + c];
#pragma unroll
        for (int r = 0; r < 2; r++) {
            const float4 f = *(const float4*)(g_cstate + base + off + r * 4);
            acc[r].x = fmaf(acc[r].x, P, f.x);
            acc[r].y = fmaf(acc[r].y, P, f.y);
            acc[r].z = fmaf(acc[r].z, P, f.z);
            acc[r].w = fmaf(acc[r].w, P, f.w);
        }
    }
}

// ---------------------------------------------------------------------------
// Inter-chunk: Y[t,p] += ecum_t * (C_t · S0[p,:])
// ---------------------------------------------------------------------------
#define ISM_CH 0
#define ISM_CL 17408
#define ISM_SH 34816
#define ISM_SL 52224
#define ISM_EC 69632
#define INTER_SMEM 69888

__global__ void __launch_bounds__(256) inter_kernel()
{
    extern __shared__ __align__(128) char smem[];
    const uint32_t sb = smem_u32(smem);
    const int ch = blockIdx.x + 1, h = blockIdx.y, b = blockIdx.z;
    const int tid = threadIdx.x;
    const int wid = tid >> 5, lid = tid & 31;
    const int wr = wid & 1, wc = wid >> 1;
    const size_t tb = (size_t)b * SEQLEN + (size_t)ch * CT;

    {
        const int row = tid >> 2, c0 = (tid & 3) * 32;
        const size_t co = (tb + row) * CONVDIM + DINNER + DSTATE + c0;
        const size_t so = (((size_t)b * NHEADS + h) * NCH + ch) * (HEADDIM * DSTATE)
                        + (size_t)row * DSTATE + c0;
#pragma unroll
        for (int c = 0; c < 32; c += 8) {
            *(uint4*)(smem + ISM_CH + row * PB + (c0 + c) * 2) =
                *(const uint4*)(g_cvh + co + c);
            *(uint4*)(smem + ISM_CL + row * PB + (c0 + c) * 2) =
                *(const uint4*)(g_cvl + co + c);
            *(uint4*)(smem + ISM_SH + row * PB + (c0 + c) * 2) =
                *(const uint4*)(g_isth + so + c);
            *(uint4*)(smem + ISM_SL + row * PB + (c0 + c) * 2) =
                *(const uint4*)(g_istl + so + c);
        }
    }
    if (tid < 64)
        ((float*)(smem + ISM_EC))[tid] = g_ecum[(tb + tid) * NHEADS + h];
    __syncthreads();

    float acc[2][2][4];
#pragma unroll
    for (int i = 0; i < 2; i++)
#pragma unroll
        for (int j = 0; j < 2; j++)
#pragma unroll
            for (int k = 0; k < 4; k++) acc[i][j][k] = 0.f;

#pragma unroll
    for (int ks = 0; ks < 8; ++ks) {
        uint32_t ah[2][4], al[2][4], bh2[2][2], bl2[2][2];
        const int arow = wr * 32 + (lid & 15);
        const int akc  = ks * 2 + (lid >> 4);
#pragma unroll
        for (int mt = 0; mt < 2; ++mt) {
            const uint32_t a = sb + ISM_CH + (arow + mt * 16) * PB + akc * 16;
            ldmatrix_x4(ah[mt], a);
            ldmatrix_x4(al[mt], a + (ISM_CL - ISM_CH));
        }
        const int brow = wc * 16 + (lid & 7);
        const int bkc  = ks * 2 + ((lid >> 3) & 1);
#pragma unroll
        for (int nt = 0; nt < 2; ++nt) {
            const uint32_t bp = sb + ISM_SH + (brow + nt * 8) * PB + bkc * 16;
            ldmatrix_x2(bh2[nt], bp);
            ldmatrix_x2(bl2[nt], bp + (ISM_SL - ISM_SH));
        }
#pragma unroll
        for (int mt = 0; mt < 2; ++mt)
#pragma unroll
            for (int nt = 0; nt < 2; ++nt) {
                mma_bf16(acc[mt][nt], ah[mt], bh2[nt]);
                mma_bf16(acc[mt][nt], ah[mt], bl2[nt]);
                mma_bf16(acc[mt][nt], al[mt], bh2[nt]);
            }
    }

    const float* s_ec = (const float*)(smem + ISM_EC);
#pragma unroll
    for (int mt = 0; mt < 2; ++mt)
#pragma unroll
        for (int nt = 0; nt < 2; ++nt) {
            const int t0 = wr * 32 + mt * 16 + (lid >> 2);
            const int p0 = wc * 16 + nt * 8 + (lid & 3) * 2;
            {
                float* yp = g_y + (tb + t0) * DINNER + h * HEADDIM + p0;
                float2 o = *(float2*)yp;
                o.x += s_ec[t0] * acc[mt][nt][0];
                o.y += s_ec[t0] * acc[mt][nt][1];
                *(float2*)yp = o;
            }
            {
                float* yp = g_y + (tb + t0 + 8) * DINNER + h * HEADDIM + p0;
                float2 o = *(float2*)yp;
                o.x += s_ec[t0 + 8] * acc[mt][nt][2];
                o.y += s_ec[t0 + 8] * acc[mt][nt][3];
                *(float2*)yp = o;
            }
        }
}

// ---------------------------------------------------------------------------
// y += x*D; yz = y*silu(z); RMSNorm(yz) * norm_w -> bf16 hi/lo
// ---------------------------------------------------------------------------
__global__ __launch_bounds__(256) void gate_norm_kernel(
    const float* __restrict__ Dv, const float* __restrict__ nw)
{
    const int bt = blockIdx.x;
    const float* zrow = g_zx   + (size_t)bt * DINPROJ;
    const float* xrow = g_conv + (size_t)bt * CONVDIM;
    const float* yrow = g_y    + (size_t)bt * DINNER;

    float v[6];
    float ss = 0.f;
#pragma unroll
    for (int i = 0; i < 6; i++) {
        const int c = threadIdx.x + i * 256;
        const float yv = fmaf(xrow[c], Dv[c >> 6], yrow[c]);
        const float z  = zrow[c];
        const float gz = z / (1.f + __expf(-z));
        const float val = yv * gz;
        v[i] = val;
        ss = fmaf(val, val, ss);
    }
#pragma unroll
    for (int o = 16; o; o >>= 1) ss += __shfl_xor_sync(0xffffffffu, ss, o);
    __shared__ float sred[8];
    if ((threadIdx.x & 31) == 0) sred[threadIdx.x >> 5] = ss;
    __syncthreads();
    float tot = 0.f;
#pragma unroll
    for (int i = 0; i < 8; i++) tot += sred[i];
    const float scale = rsqrtf(tot * (1.f / DINNER) + 1e-5f);

    __nv_bfloat16* yh = g_yn_hi + (size_t)bt * DINNER;
    __nv_bfloat16* yl = g_yn_lo + (size_t)bt * DINNER;
#pragma unroll
    for (int i = 0; i < 6; i++) {
        const int c = threadIdx.x + i * 256;
        const float val = v[i] * scale * nw[c];
        const __nv_bfloat16 hb = __float2bfloat16(val);
        yh[c] = hb;
        yl[c] = __float2bfloat16(val - __bfloat162float(hb));
    }
}

// ---------------------------------------------------------------------------
// Launch
// ---------------------------------------------------------------------------
extern "C" void kernel_launch(void* const* d_in, const int* in_sizes, int n_in,
                              void* d_out, int out_size)
{
    const float* u          = (const float*)d_in[0];
    const float* in_proj_w  = (const float*)d_in[1];
    const float* conv_w     = (const float*)d_in[2];
    const float* conv_b     = (const float*)d_in[3];
    const float* dt_bias    = (const float*)d_in[4];
    const float* A_log      = (const float*)d_in[5];
    const float* Dv         = (const float*)d_in[6];
    const float* norm_w     = (const float*)d_in[7];
    const float* out_proj_w = (const float*)d_in[8];
    float* out = (float*)d_out;

    float* zx = nullptr;
    __nv_bfloat16 *uh, *ul, *w1h, *w1l, *w2h, *w2l, *ynh, *ynl;
    cudaGetSymbolAddress((void**)&zx,  g_zx);
    cudaGetSymbolAddress((void**)&uh,  g_u_hi);
    cudaGetSymbolAddress((void**)&ul,  g_u_lo);
    cudaGetSymbolAddress((void**)&w1h, g_w1_hi);
    cudaGetSymbolAddress((void**)&w1l, g_w1_lo);
    cudaGetSymbolAddress((void**)&w2h, g_w2_hi);
    cudaGetSymbolAddress((void**)&w2l, g_w2_lo);
    cudaGetSymbolAddress((void**)&ynh, g_yn_hi);
    cudaGetSymbolAddress((void**)&ynl, g_yn_lo);

    cudaFuncSetAttribute(gemm_mma,
                         cudaFuncAttributeMaxDynamicSharedMemorySize, GEMM_SMEM);
    cudaFuncSetAttribute(gemm_mma64,
                         cudaFuncAttributeMaxDynamicSharedMemorySize, GEMM64_SMEM);
    cudaFuncSetAttribute(chunk_kernel,
                         cudaFuncAttributeMaxDynamicSharedMemorySize, CHUNK_SMEM);
    cudaFuncSetAttribute(inter_kernel,
                         cudaFuncAttributeMaxDynamicSharedMemorySize, INTER_SMEM);

    // 0) bf16 hi/lo splits for GEMM operands
    split_kernel<<<(NTOK * DMODEL + 255) / 256, 256>>>(u, uh, ul, NTOK * DMODEL);
    split_kernel<<<(DINPROJ * DMODEL + 255) / 256, 256>>>(in_proj_w, w1h, w1l,
                                                          DINPROJ * DMODEL);
    split_kernel<<<(DMODEL * DINNER + 255) / 256, 256>>>(out_proj_w, w2h, w2l,
                                                         DMODEL * DINNER);

    // 1) zxbcdt = u @ in_proj_w^T — HMMA bf16x3 (frozen R9 config)
    dim3 g1((DINPROJ + 127) / 128, NTOK / 128);
    gemm_mma<<<g1, 256, GEMM_SMEM>>>(uh, ul, w1h, w1l, zx,
                                     NTOK, DINPROJ, DMODEL);

    // 2) depthwise causal conv + silu (+ one-time bf16 hi/lo emit)
    conv_silu_kernel<<<(NTOK * CONVDIM + 255) / 256, 256>>>(conv_w, conv_b);

    // 3) dt softplus / log-decay a
    dt_kernel<<<(NTOK * NHEADS + 255) / 256, 256>>>(dt_bias, A_log);

    // 4) SSD chunk pass — tensor cores
    chunk_kernel<<<dim3(NCH, NHEADS, BATCH), 256, CHUNK_SMEM>>>();

    // 5) combine chunk states (4-way sliced for latency)
    combine_kernel<<<dim3(NHEADS, BATCH, 4), 256>>>();

    // 6) inter-chunk contribution — tensor cores
    inter_kernel<<<dim3(NCH - 1, NHEADS, BATCH), 256, INTER_SMEM>>>();

    // 7) gate + RMSNorm -> bf16 hi/lo
    gate_norm_kernel<<<NTOK, 256>>>(Dv, norm_w);

    // 8) out = yn @ out_proj_w^T — 64x128 tiles (384 blocks, no wave quant)
    dim3 g2((DMODEL + 127) / 128, NTOK / 64);
    gemm_mma64<<<g2, 256, GEMM64_SMEM>>>(ynh, ynl, w2h, w2l, out,
                                         NTOK, DMODEL, DINNER);
}

// round 16
// speedup vs baseline: 1.5150x; 1.2013x over previous
#include <cuda_runtime.h>
#include <cuda_bf16.h>
#include <cuda_fp16.h>
#include <math.h>
#include <stdint.h>

#define BATCH   2
#define SEQLEN  2048
#define NTOK    (BATCH*SEQLEN)        // 4096
#define DMODEL  768
#define DINNER  1536
#define DSTATE  128
#define HEADDIM 64
#define NHEADS  24
#define CONVDIM 1792                  // DINNER + 2*DSTATE
#define DINPROJ 3352                  // 2*DINNER + 2*DSTATE + NHEADS
#define CT      64                    // chunk tokens
#define NCH     (SEQLEN/CT)           // 32 chunks per sequence

// ---------------------------------------------------------------------------
// Scratch buffers (device globals — no allocations allowed)
// ---------------------------------------------------------------------------
__device__ __align__(128) float g_zx[NTOK * DINPROJ];     // in_proj output
__device__ __align__(128) float g_conv[NTOK * CONVDIM];   // conv+silu fp32 (x slice)
__device__ __align__(128) __nv_bfloat16 g_cvh[NTOK * CONVDIM]; // conv out bf16 hi
__device__ __align__(128) __nv_bfloat16 g_cvl[NTOK * CONVDIM]; // conv out bf16 lo
__device__ __align__(128) float g_dt[NTOK * NHEADS];
__device__ __align__(128) float g_a[NTOK * NHEADS];
__device__ __align__(128) float g_ecum[NTOK * NHEADS];
__device__ __align__(128) float g_ptot[BATCH*NHEADS*NCH];
__device__ __align__(128) float g_y[NTOK * DINNER];
__device__ __align__(128) float g_cstate[BATCH*NHEADS*NCH*HEADDIM*DSTATE];
__device__ __align__(128) __nv_bfloat16 g_isth[BATCH*NHEADS*NCH*HEADDIM*DSTATE];
__device__ __align__(128) __nv_bfloat16 g_istl[BATCH*NHEADS*NCH*HEADDIM*DSTATE];

// fp16 operands for the projection GEMMs (A = activations hi/lo, B = weights 1x)
__device__ __align__(128) __half g_u_hi[NTOK * DMODEL];
__device__ __align__(128) __half g_u_lo[NTOK * DMODEL];
__device__ __align__(128) __half g_w1_h[DINPROJ * DMODEL];
__device__ __align__(128) __half g_w2_h[DMODEL * DINNER];
__device__ __align__(128) __half g_yn_hi[NTOK * DINNER];
__device__ __align__(128) __half g_yn_lo[NTOK * DINNER];

// ---------------------------------------------------------------------------
// MMA helpers
// ---------------------------------------------------------------------------
static __device__ __forceinline__ uint32_t smem_u32(const void* p) {
    return (uint32_t)__cvta_generic_to_shared(p);
}

static __device__ __forceinline__ void mma_fp16(
    float* d, const uint32_t* a, const uint32_t* b)
{
    asm volatile(
        "mma.sync.aligned.m16n8k16.row.col.f32.f16.f16.f32 "
        "{%0,%1,%2,%3}, {%4,%5,%6,%7}, {%8,%9}, {%0,%1,%2,%3};"
        : "+f"(d[0]), "+f"(d[1]), "+f"(d[2]), "+f"(d[3])
        : "r"(a[0]), "r"(a[1]), "r"(a[2]), "r"(a[3]), "r"(b[0]), "r"(b[1]));
}

static __device__ __forceinline__ void mma_bf16(
    float* d, const uint32_t* a, const uint32_t* b)
{
    asm volatile(
        "mma.sync.aligned.m16n8k16.row.col.f32.bf16.bf16.f32 "
        "{%0,%1,%2,%3}, {%4,%5,%6,%7}, {%8,%9}, {%0,%1,%2,%3};"
        : "+f"(d[0]), "+f"(d[1]), "+f"(d[2]), "+f"(d[3])
        : "r"(a[0]), "r"(a[1]), "r"(a[2]), "r"(a[3]), "r"(b[0]), "r"(b[1]));
}

static __device__ __forceinline__ void ldmatrix_x4(uint32_t* r, uint32_t addr)
{
    asm volatile("ldmatrix.sync.aligned.m8n8.x4.shared.b16 {%0,%1,%2,%3}, [%4];"
                 : "=r"(r[0]), "=r"(r[1]), "=r"(r[2]), "=r"(r[3]) : "r"(addr));
}

static __device__ __forceinline__ void ldmatrix_x2(uint32_t* r, uint32_t addr)
{
    asm volatile("ldmatrix.sync.aligned.m8n8.x2.shared.b16 {%0,%1}, [%2];"
                 : "=r"(r[0]), "=r"(r[1]) : "r"(addr));
}

static __device__ __forceinline__ void ldmatrix_x2_trans(uint32_t* r, uint32_t addr)
{
    asm volatile("ldmatrix.sync.aligned.m8n8.x2.trans.shared.b16 {%0,%1}, [%2];"
                 : "=r"(r[0]), "=r"(r[1]) : "r"(addr));
}

static __device__ __forceinline__ void cp16(uint32_t dst, const void* src, int sz)
{
    asm volatile("cp.async.cg.shared.global [%0], [%1], 16, %2;"
                 :: "r"(dst), "l"(src), "r"(sz));
}

// split fp32x4 into packed bf16 hi/lo (uint2 each)
static __device__ __forceinline__ void split4(float4 v, uint2& hi, uint2& lo)
{
    __nv_bfloat16 h0=__float2bfloat16(v.x), h1=__float2bfloat16(v.y),
                  h2=__float2bfloat16(v.z), h3=__float2bfloat16(v.w);
    __nv_bfloat16 l0=__float2bfloat16(v.x-__bfloat162float(h0)),
                  l1=__float2bfloat16(v.y-__bfloat162float(h1)),
                  l2=__float2bfloat16(v.z-__bfloat162float(h2)),
                  l3=__float2bfloat16(v.w-__bfloat162float(h3));
    hi.x = ((uint32_t)__bfloat16_as_ushort(h1)<<16) | __bfloat16_as_ushort(h0);
    hi.y = ((uint32_t)__bfloat16_as_ushort(h3)<<16) | __bfloat16_as_ushort(h2);
    lo.x = ((uint32_t)__bfloat16_as_ushort(l1)<<16) | __bfloat16_as_ushort(l0);
    lo.y = ((uint32_t)__bfloat16_as_ushort(l3)<<16) | __bfloat16_as_ushort(l2);
}

// ---------------------------------------------------------------------------
// fp16x2 GEMM via mma.sync:  C = A @ B^T, A = Ah + Al (fp16 hi/lo split of
// fp32 activations), B = fp16(weights). 2 MMAs per tile (Ah*B, Al*B).
// Dominant error = weight rounding ~2^-12 (RMS) — well under 1e-3 threshold.
// CTA tile 128x128, BK=32, 8 warps, 61440B smem -> 2 CTAs/SM.
// ---------------------------------------------------------------------------
#define ROWB   80
#define MATB   (128 * ROWB)
#define STAGEB (3 * MATB)                 // 30720 (Ah | Al | B)
#define GEMM_SMEM (2 * STAGEB)            // 61440

__global__ void __launch_bounds__(256) gemm_mma(
    const __half* __restrict__ Ah, const __half* __restrict__ Al,
    const __half* __restrict__ Bw,
    float* __restrict__ C, int M, int N, int K)
{
    extern __shared__ __align__(128) char smem[];
    const uint32_t sb = smem_u32(smem);
    const int tid = threadIdx.x;
    const int wid = tid >> 5, lid = tid & 31;
    const int bm = blockIdx.y * 128;
    const int bn = blockIdx.x * 128;
    const int wr = wid & 1;
    const int wc = wid >> 1;

    float acc[4][4][4];
#pragma unroll
    for (int i = 0; i < 4; i++)
#pragma unroll
        for (int j = 0; j < 4; j++)
#pragma unroll
            for (int k = 0; k < 4; k++) acc[i][j][k] = 0.f;

    const int lrow = tid >> 1;
    const int lch  = (tid & 1) * 2;
    const int bok  = (bn + lrow) < N ? 16 : 0;
    const size_t arowoff = (size_t)(bm + lrow) * K + lch * 8;
    const size_t browoff = (size_t)(bok ? (bn + lrow) : 0) * K + lch * 8;
    const uint32_t dst0 = sb + lrow * ROWB + lch * 16;

    const int NC = K >> 5;

    auto stage_issue = [&](int c) {
        const uint32_t d = dst0 + (uint32_t)(c & 1) * STAGEB;
        const size_t ao = arowoff + (size_t)c * 32;
        const size_t bo = browoff + (size_t)c * 32;
        cp16(d,          Ah + ao, 16); cp16(d + 16,          Ah + ao + 8, 16);
        cp16(d + MATB,   Al + ao, 16); cp16(d + MATB + 16,   Al + ao + 8, 16);
        cp16(d + 2*MATB, Bw + bo, bok); cp16(d + 2*MATB + 16, Bw + bo + 8, bok);
        asm volatile("cp.async.commit_group;");
    };

    stage_issue(0);

    for (int c = 0; c < NC; ++c) {
        if (c + 1 < NC) {
            stage_issue(c + 1);
            asm volatile("cp.async.wait_group 1;");
        } else {
            asm volatile("cp.async.wait_group 0;");
        }
        __syncthreads();

        const uint32_t st = sb + (c & 1) * STAGEB;
#pragma unroll
        for (int ks = 0; ks < 2; ++ks) {
            uint32_t ah[4][4], al[4][4], bh[4][2];
            const int arow = wr * 64 + (lid & 15);
            const int akc  = ks * 2 + (lid >> 4);
#pragma unroll
            for (int mt = 0; mt < 4; ++mt) {
                const uint32_t a = st + (arow + mt * 16) * ROWB + akc * 16;
                ldmatrix_x4(ah[mt], a);
                ldmatrix_x4(al[mt], a + MATB);
            }
            const int brow = wc * 32 + (lid & 7);
            const int bkc  = ks * 2 + ((lid >> 3) & 1);
#pragma unroll
            for (int nt = 0; nt < 4; ++nt) {
                const uint32_t b = st + 2*MATB + (brow + nt * 8) * ROWB + bkc * 16;
                ldmatrix_x2(bh[nt], b);
            }
#pragma unroll
            for (int mt = 0; mt < 4; ++mt)
#pragma unroll
                for (int nt = 0; nt < 4; ++nt) {
                    mma_fp16(acc[mt][nt], ah[mt], bh[nt]);
                    mma_fp16(acc[mt][nt], al[mt], bh[nt]);
                }
        }
        __syncthreads();
    }

    const int mbase = bm + wr * 64 + (lid >> 2);
    const int nbase = bn + wc * 32 + (lid & 3) * 2;
#pragma unroll
    for (int mt = 0; mt < 4; ++mt) {
#pragma unroll
        for (int nt = 0; nt < 4; ++nt) {
            const int n0 = nbase + nt * 8;
            if (n0 < N) {
                const int m0 = mbase + mt * 16;
                float2 v0 = make_float2(acc[mt][nt][0], acc[mt][nt][1]);
                float2 v1 = make_float2(acc[mt][nt][2], acc[mt][nt][3]);
                *(float2*)(C + (size_t)m0 * N + n0)       = v0;
                *(float2*)(C + (size_t)(m0 + 8) * N + n0) = v1;
            }
        }
    }
}

// ---------------------------------------------------------------------------
// fp16x2 GEMM, 64x128 CTA tile (GEMM2: 384 blocks -> no wave quantization)
// ---------------------------------------------------------------------------
#define AMATB64 (64 * ROWB)                 // 5120
#define STAGE64 (2 * AMATB64 + MATB)        // 20480
#define GEMM64_SMEM (2 * STAGE64)           // 40960

__global__ void __launch_bounds__(256) gemm_mma64(
    const __half* __restrict__ Ah, const __half* __restrict__ Al,
    const __half* __restrict__ Bw,
    float* __restrict__ C, int M, int N, int K)
{
    extern __shared__ __align__(128) char smem[];
    const uint32_t sb = smem_u32(smem);
    const int tid = threadIdx.x;
    const int wid = tid >> 5, lid = tid & 31;
    const int bm = blockIdx.y * 64;
    const int bn = blockIdx.x * 128;
    const int wr = wid & 1;
    const int wc = wid >> 1;

    float acc[2][4][4];
#pragma unroll
    for (int i = 0; i < 2; i++)
#pragma unroll
        for (int j = 0; j < 4; j++)
#pragma unroll
            for (int k = 0; k < 4; k++) acc[i][j][k] = 0.f;

    const int alrow = tid >> 2;
    const int alch  = tid & 3;
    const size_t arowoff = (size_t)(bm + alrow) * K + alch * 8;
    const uint32_t adst0 = sb + alrow * ROWB + alch * 16;
    const int blrow = tid >> 1;
    const int blch  = (tid & 1) * 2;
    const int bok   = (bn + blrow) < N ? 16 : 0;
    const size_t browoff = (size_t)(bok ? (bn + blrow) : 0) * K + blch * 8;
    const uint32_t bdst0 = sb + 2 * AMATB64 + blrow * ROWB + blch * 16;

    const int NC = K >> 5;

    auto stage_issue = [&](int c) {
        const uint32_t so = (uint32_t)(c & 1) * STAGE64;
        const size_t ao = arowoff + (size_t)c * 32;
        const size_t bo = browoff + (size_t)c * 32;
        cp16(adst0 + so,           Ah + ao, 16);
        cp16(adst0 + so + AMATB64, Al + ao, 16);
        cp16(bdst0 + so,      Bw + bo, bok);
        cp16(bdst0 + so + 16, Bw + bo + 8, bok);
        asm volatile("cp.async.commit_group;");
    };

    stage_issue(0);

    for (int c = 0; c < NC; ++c) {
        if (c + 1 < NC) {
            stage_issue(c + 1);
            asm volatile("cp.async.wait_group 1;");
        } else {
            asm volatile("cp.async.wait_group 0;");
        }
        __syncthreads();

        const uint32_t st = sb + (uint32_t)(c & 1) * STAGE64;
#pragma unroll
        for (int ks = 0; ks < 2; ++ks) {
            uint32_t ah[2][4], al[2][4], bh[4][2];
            const int arow = wr * 32 + (lid & 15);
            const int akc  = ks * 2 + (lid >> 4);
#pragma unroll
            for (int mt = 0; mt < 2; ++mt) {
                const uint32_t a = st + (arow + mt * 16) * ROWB + akc * 16;
                ldmatrix_x4(ah[mt], a);
                ldmatrix_x4(al[mt], a + AMATB64);
            }
            const int brow = wc * 32 + (lid & 7);
            const int bkc  = ks * 2 + ((lid >> 3) & 1);
#pragma unroll
            for (int nt = 0; nt < 4; ++nt) {
                const uint32_t b = st + 2 * AMATB64 + (brow + nt * 8) * ROWB + bkc * 16;
                ldmatrix_x2(bh[nt], b);
            }
#pragma unroll
            for (int mt = 0; mt < 2; ++mt)
#pragma unroll
                for (int nt = 0; nt < 4; ++nt) {
                    mma_fp16(acc[mt][nt], ah[mt], bh[nt]);
                    mma_fp16(acc[mt][nt], al[mt], bh[nt]);
                }
        }
        __syncthreads();
    }

    const int mbase = bm + wr * 32 + (lid >> 2);
    const int nbase = bn + wc * 32 + (lid & 3) * 2;
#pragma unroll
    for (int mt = 0; mt < 2; ++mt) {
#pragma unroll
        for (int nt = 0; nt < 4; ++nt) {
            const int n0 = nbase + nt * 8;
            if (n0 < N) {
                const int m0 = mbase + mt * 16;
                float2 v0 = make_float2(acc[mt][nt][0], acc[mt][nt][1]);
                float2 v1 = make_float2(acc[mt][nt][2], acc[mt][nt][3]);
                *(float2*)(C + (size_t)m0 * N + n0)       = v0;
                *(float2*)(C + (size_t)(m0 + 8) * N + n0) = v1;
            }
        }
    }
}

// ---------------------------------------------------------------------------
// fp32 -> fp16 hi/lo split (A operands)
// ---------------------------------------------------------------------------
__global__ void split_fp16_kernel(const float* __restrict__ src,
                                  __half* __restrict__ hi,
                                  __half* __restrict__ lo, int n)
{
    const int i = blockIdx.x * 256 + threadIdx.x;
    if (i >= n) return;
    const float x = src[i];
    const __half h = __float2half(x);
    hi[i] = h;
    lo[i] = __float2half(x - __half2float(h));
}

// fp32 -> fp16 single rounding (weight operands)
__global__ void cvt_fp16_kernel(const float* __restrict__ src,
                                __half* __restrict__ dst, int n)
{
    const int i = blockIdx.x * 256 + threadIdx.x;
    if (i < n) dst[i] = __float2half(src[i]);
}

// ---------------------------------------------------------------------------
// Depthwise causal conv (width 4) + bias + SiLU.
// ---------------------------------------------------------------------------
__global__ void conv_silu_kernel(const float* __restrict__ cw,
                                 const float* __restrict__ cb)
{
    const int idx = blockIdx.x * 256 + threadIdx.x;
    if (idx >= NTOK * CONVDIM) return;
    const int c  = idx % CONVDIM;
    const int bt = idx / CONVDIM;
    const int t  = bt % SEQLEN;
    float acc = cb[c];
#pragma unroll
    for (int k = 0; k < 4; k++) {
        const int tt = t - 3 + k;
        if (tt >= 0)
            acc = fmaf(cw[c * 4 + k],
                       g_zx[((size_t)bt + k - 3) * DINPROJ + DINNER + c], acc);
    }
    const float v = acc / (1.f + __expf(-acc));   // silu
    if (c < DINNER) g_conv[idx] = v;
    const __nv_bfloat16 hb = __float2bfloat16(v);
    g_cvh[idx] = hb;
    g_cvl[idx] = __float2bfloat16(v - __bfloat162float(hb));
}

// ---------------------------------------------------------------------------
// dt_dis = softplus(dt + dt_bias); a = dt_dis * A  (log decay, negative)
// ---------------------------------------------------------------------------
__global__ void dt_kernel(const float* __restrict__ dt_bias,
                          const float* __restrict__ A_log)
{
    const int idx = blockIdx.x * 256 + threadIdx.x;
    if (idx >= NTOK * NHEADS) return;
    const int h  = idx % NHEADS;
    const int bt = idx / NHEADS;
    const float x  = g_zx[(size_t)bt * DINPROJ + DINNER + CONVDIM + h] + dt_bias[h];
    const float sp = (x > 20.f) ? x : log1pf(expf(x));
    const float Ah = -expf(A_log[h]);
    g_dt[idx] = sp;
    g_a[idx]  = sp * Ah;
}

// ---------------------------------------------------------------------------
// SSD chunk kernel (bf16x3, unchanged — errors here feed the recurrence)
// ---------------------------------------------------------------------------
#define PB 272
#define PX 144
#define SM_BH 0
#define SM_BL 17408
#define SM_CH 34816
#define SM_CL 52224
#define SM_XH 69632
#define SM_XL 78848
#define SM_PH 88064
#define SM_PL 97280
#define SM_CUM 106496
#define SM_DTA 106752
#define SM_WW  107008
#define CHUNK_SMEM 107264

__global__ void __launch_bounds__(256) chunk_kernel()
{
    extern __shared__ __align__(128) char smem[];
    const uint32_t sb = smem_u32(smem);
    const int ch = blockIdx.x, h = blockIdx.y, b = blockIdx.z;
    const int tid = threadIdx.x;
    const int wid = tid >> 5, lid = tid & 31;
    const int wr = wid & 1, wc = wid >> 1;
    const size_t tb = (size_t)b * SEQLEN + (size_t)ch * CT;

    float* s_cum = (float*)(smem + SM_CUM);
    float* s_dt  = (float*)(smem + SM_DTA);
    float* s_w   = (float*)(smem + SM_WW);

    {
        const int row = tid >> 2, c0 = (tid & 3) * 32;
        const size_t so = (tb + row) * CONVDIM + DINNER + c0;
#pragma unroll
        for (int c = 0; c < 32; c += 8) {
            *(uint4*)(smem + SM_BH + row * PB + (c0 + c) * 2) =
                *(const uint4*)(g_cvh + so + c);
            *(uint4*)(smem + SM_BL + row * PB + (c0 + c) * 2) =
                *(const uint4*)(g_cvl + so + c);
            *(uint4*)(smem + SM_CH + row * PB + (c0 + c) * 2) =
                *(const uint4*)(g_cvh + so + DSTATE + c);
            *(uint4*)(smem + SM_CL + row * PB + (c0 + c) * 2) =
                *(const uint4*)(g_cvl + so + DSTATE + c);
        }
    }
    {
        const int t = tid >> 2, p0 = (tid & 3) * 16;
        const size_t so = (tb + t) * CONVDIM + h * HEADDIM + p0;
#pragma unroll
        for (int p = 0; p < 16; ++p) {
            *(unsigned short*)(smem + SM_XH + (p0 + p) * PX + t * 2) =
                *(const unsigned short*)(g_cvh + so + p);
            *(unsigned short*)(smem + SM_XL + (p0 + p) * PX + t * 2) =
                *(const unsigned short*)(g_cvl + so + p);
        }
    }
    if (wid == 0) {
        const float a0 = g_a[(tb + 2 * lid)     * NHEADS + h];
        const float a1 = g_a[(tb + 2 * lid + 1) * NHEADS + h];
        const float ps = a0 + a1;
        float sc = ps;
#pragma unroll
        for (int off = 1; off < 32; off <<= 1) {
            const float t = __shfl_up_sync(0xffffffffu, sc, off);
            if (lid >= off) sc += t;
        }
        float excl = __shfl_up_sync(0xffffffffu, sc, 1);
        if (lid == 0) excl = 0.f;
        s_cum[2 * lid]     = excl + a0;
        s_cum[2 * lid + 1] = excl + ps;
    }
    if (tid >= 64 && tid < 128) s_dt[tid - 64] = g_dt[(tb + tid - 64) * NHEADS + h];
    __syncthreads();

    if (tid < 64) {
        const float ct = s_cum[tid], tot = s_cum[63];
        s_w[tid] = expf(tot - ct) * s_dt[tid];
        g_ecum[(tb + tid) * NHEADS + h] = expf(ct);
        if (tid == 63)
            g_ptot[((size_t)b * NHEADS + h) * NCH + ch] = expf(tot);
    }

    float gacc[2][2][4];
#pragma unroll
    for (int i = 0; i < 2; i++)
#pragma unroll
        for (int j = 0; j < 2; j++)
#pragma unroll
            for (int k = 0; k < 4; k++) gacc[i][j][k] = 0.f;
#pragma unroll
    for (int ks = 0; ks < 8; ++ks) {
        uint32_t ah[2][4], al[2][4], bh2[2][2], bl2[2][2];
        const int arow = wr * 32 + (lid & 15);
        const int akc  = ks * 2 + (lid >> 4);
#pragma unroll
        for (int mt = 0; mt < 2; ++mt) {
            const uint32_t a = sb + SM_CH + (arow + mt * 16) * PB + akc * 16;
            ldmatrix_x4(ah[mt], a);
            ldmatrix_x4(al[mt], a + (SM_CL - SM_CH));
        }
        const int brow = wc * 16 + (lid & 7);
        const int bkc  = ks * 2 + ((lid >> 3) & 1);
#pragma unroll
        for (int nt = 0; nt < 2; ++nt) {
            const uint32_t bp = sb + SM_BH + (brow + nt * 8) * PB + bkc * 16;
            ldmatrix_x2(bh2[nt], bp);
            ldmatrix_x2(bl2[nt], bp + (SM_BL - SM_BH));
        }
#pragma unroll
        for (int mt = 0; mt < 2; ++mt)
#pragma unroll
            for (int nt = 0; nt < 2; ++nt) {
                mma_bf16(gacc[mt][nt], ah[mt], bh2[nt]);
                mma_bf16(gacc[mt][nt], ah[mt], bl2[nt]);
                mma_bf16(gacc[mt][nt], al[mt], bh2[nt]);
            }
    }

#pragma unroll
    for (int mt = 0; mt < 2; ++mt)
#pragma unroll
        for (int nt = 0; nt < 2; ++nt)
#pragma unroll
            for (int r = 0; r < 4; ++r) {
                const int t1 = wr * 32 + mt * 16 + (lid >> 2) + ((r >> 1) ? 8 : 0);
                const int t2 = wc * 16 + nt * 8 + (lid & 3) * 2 + (r & 1);
                float pv = 0.f;
                if (t1 >= t2)
                    pv = __expf(s_cum[t1] - s_cum[t2]) * gacc[mt][nt][r] * s_dt[t2];
                const __nv_bfloat16 hb = __float2bfloat16(pv);
                const __nv_bfloat16 lb = __float2bfloat16(pv - __bfloat162float(hb));
                *(unsigned short*)(smem + SM_PH + t1 * PX + t2 * 2) =
                    __bfloat16_as_ushort(hb);
                *(unsigned short*)(smem + SM_PL + t1 * PX + t2 * 2) =
                    __bfloat16_as_ushort(lb);
            }
    __syncthreads();

    {
        float yacc[2][2][4];
#pragma unroll
        for (int i = 0; i < 2; i++)
#pragma unroll
            for (int j = 0; j < 2; j++)
#pragma unroll
                for (int k = 0; k < 4; k++) yacc[i][j][k] = 0.f;
#pragma unroll
        for (int ks = 0; ks < 4; ++ks) {
            uint32_t ah[2][4], al[2][4], bh2[2][2], bl2[2][2];
            const int arow = wr * 32 + (lid & 15);
            const int akc  = ks * 2 + (lid >> 4);
#pragma unroll
            for (int mt = 0; mt < 2; ++mt) {
                const uint32_t a = sb + SM_PH + (arow + mt * 16) * PX + akc * 16;
                ldmatrix_x4(ah[mt], a);
                ldmatrix_x4(al[mt], a + (SM_PL - SM_PH));
            }
            const int brow = wc * 16 + (lid & 7);
            const int bkc  = ks * 2 + ((lid >> 3) & 1);
#pragma unroll
            for (int nt = 0; nt < 2; ++nt) {
                const uint32_t bp = sb + SM_XH + (brow + nt * 8) * PX + bkc * 16;
                ldmatrix_x2(bh2[nt], bp);
                ldmatrix_x2(bl2[nt], bp + (SM_XL - SM_XH));
            }
#pragma unroll
            for (int mt = 0; mt < 2; ++mt)
#pragma unroll
                for (int nt = 0; nt < 2; ++nt) {
                    mma_bf16(yacc[mt][nt], ah[mt], bh2[nt]);
                    mma_bf16(yacc[mt][nt], ah[mt], bl2[nt]);
                    mma_bf16(yacc[mt][nt], al[mt], bh2[nt]);
                }
        }
#pragma unroll
        for (int mt = 0; mt < 2; ++mt)
#pragma unroll
            for (int nt = 0; nt < 2; ++nt) {
                const int t0 = wr * 32 + mt * 16 + (lid >> 2);
                const int p0 = wc * 16 + nt * 8 + (lid & 3) * 2;
                *(float2*)(g_y + (tb + t0) * DINNER + h * HEADDIM + p0) =
                    make_float2(yacc[mt][nt][0], yacc[mt][nt][1]);
                *(float2*)(g_y + (tb + t0 + 8) * DINNER + h * HEADDIM + p0) =
                    make_float2(yacc[mt][nt][2], yacc[mt][nt][3]);
            }
    }
    __syncthreads();

    {
        const int p = tid >> 2, j0 = (tid & 3) * 16;
#pragma unroll
        for (int j = 0; j < 16; ++j) {
            const int jj = j0 + j;
            const float xv =
                __bfloat162float(__ushort_as_bfloat16(
                    *(unsigned short*)(smem + SM_XH + p * PX + jj * 2))) +
                __bfloat162float(__ushort_as_bfloat16(
                    *(unsigned short*)(smem + SM_XL + p * PX + jj * 2)));
            const float xw = xv * s_w[jj];
            const __nv_bfloat16 hb = __float2bfloat16(xw);
            const __nv_bfloat16 lb = __float2bfloat16(xw - __bfloat162float(hb));
            *(unsigned short*)(smem + SM_PH + p * PX + jj * 2) =
                __bfloat16_as_ushort(hb);
            *(unsigned short*)(smem + SM_PL + p * PX + jj * 2) =
                __bfloat16_as_ushort(lb);
        }
    }
    __syncthreads();

    {
        float lacc[2][4][4];
#pragma unroll
        for (int i = 0; i < 2; i++)
#pragma unroll
            for (int j = 0; j < 4; j++)
#pragma unroll
                for (int k = 0; k < 4; k++) lacc[i][j][k] = 0.f;
#pragma unroll
        for (int ks = 0; ks < 4; ++ks) {
            uint32_t ah[2][4], al[2][4];
            const int arow = wr * 32 + (lid & 15);
            const int akc  = ks * 2 + (lid >> 4);
#pragma unroll
            for (int mt = 0; mt < 2; ++mt) {
                const uint32_t a = sb + SM_PH + (arow + mt * 16) * PX + akc * 16;
                ldmatrix_x4(ah[mt], a);
                ldmatrix_x4(al[mt], a + (SM_PL - SM_PH));
            }
            const int j0 = ks * 16 + (lid & 15);
#pragma unroll
            for (int nt = 0; nt < 4; ++nt) {
                const int n0 = wc * 32 + nt * 8;
                uint32_t bh2[2], bl2[2];
                const uint32_t bp = sb + SM_BH + j0 * PB + n0 * 2;
                ldmatrix_x2_trans(bh2, bp);
                ldmatrix_x2_trans(bl2, bp + (SM_BL - SM_BH));
#pragma unroll
                for (int mt = 0; mt < 2; ++mt) {
                    mma_bf16(lacc[mt][nt], ah[mt], bh2);
                    mma_bf16(lacc[mt][nt], ah[mt], bl2);
                    mma_bf16(lacc[mt][nt], al[mt], bh2);
                }
            }
        }
        float* Lout = g_cstate +
            (((size_t)b * NHEADS + h) * NCH + ch) * (HEADDIM * DSTATE);
#pragma unroll
        for (int mt = 0; mt < 2; ++mt)
#pragma unroll
            for (int nt = 0; nt < 4; ++nt) {
                const int p0 = wr * 32 + mt * 16 + (lid >> 2);
                const int n0 = wc * 32 + nt * 8 + (lid & 3) * 2;
                *(float2*)(Lout + (size_t)p0 * DSTATE + n0) =
                    make_float2(lacc[mt][nt][0], lacc[mt][nt][1]);
                *(float2*)(Lout + (size_t)(p0 + 8) * DSTATE + n0) =
                    make_float2(lacc[mt][nt][2], lacc[mt][nt][3]);
            }
    }
}

// ---------------------------------------------------------------------------
// Sequential combine over chunks — 4x parallel slices per (h,b)
// ---------------------------------------------------------------------------
__global__ __launch_bounds__(256) void combine_kernel()
{
    const int h = blockIdx.x, b = blockIdx.y, q = blockIdx.z;
    const int tid = threadIdx.x;
    const size_t off = (size_t)q * 2048 + (size_t)tid * 8;
    float4 acc[2];
#pragma unroll
    for (int r = 0; r < 2; r++) acc[r] = make_float4(0.f, 0.f, 0.f, 0.f);

    for (int c = 0; c < NCH; ++c) {
        const size_t base = (((size_t)b * NHEADS + h) * NCH + c) * (HEADDIM * DSTATE);
#pragma unroll
        for (int r = 0; r < 2; r++) {
            uint2 hi, lo;
            split4(acc[r], hi, lo);
            *(uint2*)(g_isth + base + off + r * 4) = hi;
            *(uint2*)(g_istl + base + off + r * 4) = lo;
        }
        const float P = g_ptot[((size_t)b * NHEADS + h) * NCH + c];
#pragma unroll
        for (int r = 0; r < 2; r++) {
            const float4 f = *(const float4*)(g_cstate + base + off + r * 4);
            acc[r].x = fmaf(acc[r].x, P, f.x);
            acc[r].y = fmaf(acc[r].y, P, f.y);
            acc[r].z = fmaf(acc[r].z, P, f.z);
            acc[r].w = fmaf(acc[r].w, P, f.w);
        }
    }
}

// ---------------------------------------------------------------------------
// Inter-chunk: Y[t,p] += ecum_t * (C_t · S0[p,:])
// ---------------------------------------------------------------------------
#define ISM_CH 0
#define ISM_CL 17408
#define ISM_SH 34816
#define ISM_SL 52224
#define ISM_EC 69632
#define INTER_SMEM 69888

__global__ void __launch_bounds__(256) inter_kernel()
{
    extern __shared__ __align__(128) char smem[];
    const uint32_t sb = smem_u32(smem);
    const int ch = blockIdx.x + 1, h = blockIdx.y, b = blockIdx.z;
    const int tid = threadIdx.x;
    const int wid = tid >> 5, lid = tid & 31;
    const int wr = wid & 1, wc = wid >> 1;
    const size_t tb = (size_t)b * SEQLEN + (size_t)ch * CT;

    {
        const int row = tid >> 2, c0 = (tid & 3) * 32;
        const size_t co = (tb + row) * CONVDIM + DINNER + DSTATE + c0;
        const size_t so = (((size_t)b * NHEADS + h) * NCH + ch) * (HEADDIM * DSTATE)
                        + (size_t)row * DSTATE + c0;
#pragma unroll
        for (int c = 0; c < 32; c += 8) {
            *(uint4*)(smem + ISM_CH + row * PB + (c0 + c) * 2) =
                *(const uint4*)(g_cvh + co + c);
            *(uint4*)(smem + ISM_CL + row * PB + (c0 + c) * 2) =
                *(const uint4*)(g_cvl + co + c);
            *(uint4*)(smem + ISM_SH + row * PB + (c0 + c) * 2) =
                *(const uint4*)(g_isth + so + c);
            *(uint4*)(smem + ISM_SL + row * PB + (c0 + c) * 2) =
                *(const uint4*)(g_istl + so + c);
        }
    }
    if (tid < 64)
        ((float*)(smem + ISM_EC))[tid] = g_ecum[(tb + tid) * NHEADS + h];
    __syncthreads();

    float acc[2][2][4];
#pragma unroll
    for (int i = 0; i < 2; i++)
#pragma unroll
        for (int j = 0; j < 2; j++)
#pragma unroll
            for (int k = 0; k < 4; k++) acc[i][j][k] = 0.f;

#pragma unroll
    for (int ks = 0; ks < 8; ++ks) {
        uint32_t ah[2][4], al[2][4], bh2[2][2], bl2[2][2];
        const int arow = wr * 32 + (lid & 15);
        const int akc  = ks * 2 + (lid >> 4);
#pragma unroll
        for (int mt = 0; mt < 2; ++mt) {
            const uint32_t a = sb + ISM_CH + (arow + mt * 16) * PB + akc * 16;
            ldmatrix_x4(ah[mt], a);
            ldmatrix_x4(al[mt], a + (ISM_CL - ISM_CH));
        }
        const int brow = wc * 16 + (lid & 7);
        const int bkc  = ks * 2 + ((lid >> 3) & 1);
#pragma unroll
        for (int nt = 0; nt < 2; ++nt) {
            const uint32_t bp = sb + ISM_SH + (brow + nt * 8) * PB + bkc * 16;
            ldmatrix_x2(bh2[nt], bp);
            ldmatrix_x2(bl2[nt], bp + (ISM_SL - ISM_SH));
        }
#pragma unroll
        for (int mt = 0; mt < 2; ++mt)
#pragma unroll
            for (int nt = 0; nt < 2; ++nt) {
                mma_bf16(acc[mt][nt], ah[mt], bh2[nt]);
                mma_bf16(acc[mt][nt], ah[mt], bl2[nt]);
                mma_bf16(acc[mt][nt], al[mt], bh2[nt]);
            }
    }

    const float* s_ec = (const float*)(smem + ISM_EC);
#pragma unroll
    for (int mt = 0; mt < 2; ++mt)
#pragma unroll
        for (int nt = 0; nt < 2; ++nt) {
            const int t0 = wr * 32 + mt * 16 + (lid >> 2);
            const int p0 = wc * 16 + nt * 8 + (lid & 3) * 2;
            {
                float* yp = g_y + (tb + t0) * DINNER + h * HEADDIM + p0;
                float2 o = *(float2*)yp;
                o.x += s_ec[t0] * acc[mt][nt][0];
                o.y += s_ec[t0] * acc[mt][nt][1];
                *(float2*)yp = o;
            }
            {
                float* yp = g_y + (tb + t0 + 8) * DINNER + h * HEADDIM + p0;
                float2 o = *(float2*)yp;
                o.x += s_ec[t0 + 8] * acc[mt][nt][2];
                o.y += s_ec[t0 + 8] * acc[mt][nt][3];
                *(float2*)yp = o;
            }
        }
}

// ---------------------------------------------------------------------------
// y += x*D; yz = y*silu(z); RMSNorm(yz) * norm_w -> fp16 hi/lo (GEMM2 A op)
// ---------------------------------------------------------------------------
__global__ __launch_bounds__(256) void gate_norm_kernel(
    const float* __restrict__ Dv, const float* __restrict__ nw)
{
    const int bt = blockIdx.x;
    const float* zrow = g_zx   + (size_t)bt * DINPROJ;
    const float* xrow = g_conv + (size_t)bt * CONVDIM;
    const float* yrow = g_y    + (size_t)bt * DINNER;

    float v[6];
    float ss = 0.f;
#pragma unroll
    for (int i = 0; i < 6; i++) {
        const int c = threadIdx.x + i * 256;
        const float yv = fmaf(xrow[c], Dv[c >> 6], yrow[c]);
        const float z  = zrow[c];
        const float gz = z / (1.f + __expf(-z));
        const float val = yv * gz;
        v[i] = val;
        ss = fmaf(val, val, ss);
    }
#pragma unroll
    for (int o = 16; o; o >>= 1) ss += __shfl_xor_sync(0xffffffffu, ss, o);
    __shared__ float sred[8];
    if ((threadIdx.x & 31) == 0) sred[threadIdx.x >> 5] = ss;
    __syncthreads();
    float tot = 0.f;
#pragma unroll
    for (int i = 0; i < 8; i++) tot += sred[i];
    const float scale = rsqrtf(tot * (1.f / DINNER) + 1e-5f);

    __half* yh = g_yn_hi + (size_t)bt * DINNER;
    __half* yl = g_yn_lo + (size_t)bt * DINNER;
#pragma unroll
    for (int i = 0; i < 6; i++) {
        const int c = threadIdx.x + i * 256;
        const float val = v[i] * scale * nw[c];
        const __half hb = __float2half(val);
        yh[c] = hb;
        yl[c] = __float2half(val - __half2float(hb));
    }
}

// ---------------------------------------------------------------------------
// Launch
// ---------------------------------------------------------------------------
extern "C" void kernel_launch(void* const* d_in, const int* in_sizes, int n_in,
                              void* d_out, int out_size)
{
    const float* u          = (const float*)d_in[0];
    const float* in_proj_w  = (const float*)d_in[1];
    const float* conv_w     = (const float*)d_in[2];
    const float* conv_b     = (const float*)d_in[3];
    const float* dt_bias    = (const float*)d_in[4];
    const float* A_log      = (const float*)d_in[5];
    const float* Dv         = (const float*)d_in[6];
    const float* norm_w     = (const float*)d_in[7];
    const float* out_proj_w = (const float*)d_in[8];
    float* out = (float*)d_out;

    float* zx = nullptr;
    __half *uh, *ul, *w1, *w2, *ynh, *ynl;
    cudaGetSymbolAddress((void**)&zx,  g_zx);
    cudaGetSymbolAddress((void**)&uh,  g_u_hi);
    cudaGetSymbolAddress((void**)&ul,  g_u_lo);
    cudaGetSymbolAddress((void**)&w1,  g_w1_h);
    cudaGetSymbolAddress((void**)&w2,  g_w2_h);
    cudaGetSymbolAddress((void**)&ynh, g_yn_hi);
    cudaGetSymbolAddress((void**)&ynl, g_yn_lo);

    cudaFuncSetAttribute(gemm_mma,
                         cudaFuncAttributeMaxDynamicSharedMemorySize, GEMM_SMEM);
    cudaFuncSetAttribute(gemm_mma64,
                         cudaFuncAttributeMaxDynamicSharedMemorySize, GEMM64_SMEM);
    cudaFuncSetAttribute(chunk_kernel,
                         cudaFuncAttributeMaxDynamicSharedMemorySize, CHUNK_SMEM);
    cudaFuncSetAttribute(inter_kernel,
                         cudaFuncAttributeMaxDynamicSharedMemorySize, INTER_SMEM);

    // 0) fp16 operand prep
    split_fp16_kernel<<<(NTOK * DMODEL + 255) / 256, 256>>>(u, uh, ul,
                                                            NTOK * DMODEL);
    cvt_fp16_kernel<<<(DINPROJ * DMODEL + 255) / 256, 256>>>(in_proj_w, w1,
                                                             DINPROJ * DMODEL);
    cvt_fp16_kernel<<<(DMODEL * DINNER + 255) / 256, 256>>>(out_proj_w, w2,
                                                            DMODEL * DINNER);

    // 1) zxbcdt = u @ in_proj_w^T — fp16x2 HMMA
    dim3 g1((DINPROJ + 127) / 128, NTOK / 128);
    gemm_mma<<<g1, 256, GEMM_SMEM>>>(uh, ul, w1, zx, NTOK, DINPROJ, DMODEL);

    // 2) depthwise causal conv + silu (+ one-time bf16 hi/lo emit)
    conv_silu_kernel<<<(NTOK * CONVDIM + 255) / 256, 256>>>(conv_w, conv_b);

    // 3) dt softplus / log-decay a
    dt_kernel<<<(NTOK * NHEADS + 255) / 256, 256>>>(dt_bias, A_log);

    // 4) SSD chunk pass — tensor cores (bf16x3)
    chunk_kernel<<<dim3(NCH, NHEADS, BATCH), 256, CHUNK_SMEM>>>();

    // 5) combine chunk states (4-way sliced)
    combine_kernel<<<dim3(NHEADS, BATCH, 4), 256>>>();

    // 6) inter-chunk contribution — tensor cores (bf16x3)
    inter_kernel<<<dim3(NCH - 1, NHEADS, BATCH), 256, INTER_SMEM>>>();

    // 7) gate + RMSNorm -> fp16 hi/lo
    gate_norm_kernel<<<NTOK, 256>>>(Dv, norm_w);

    // 8) out = yn @ out_proj_w^T — fp16x2, 64x128 tiles (no wave quant)
    dim3 g2((DMODEL + 127) / 128, NTOK / 64);
    gemm_mma64<<<g2, 256, GEMM64_SMEM>>>(ynh, ynl, w2, out,
                                         NTOK, DMODEL, DINNER);
}

// round 17
// speedup vs baseline: 1.6233x; 1.0715x over previous
#include <cuda_runtime.h>
#include <cuda_bf16.h>
#include <cuda_fp16.h>
#include <math.h>
#include <stdint.h>

#define BATCH   2
#define SEQLEN  2048
#define NTOK    (BATCH*SEQLEN)        // 4096
#define DMODEL  768
#define DINNER  1536
#define DSTATE  128
#define HEADDIM 64
#define NHEADS  24
#define CONVDIM 1792                  // DINNER + 2*DSTATE
#define DINPROJ 3352                  // 2*DINNER + 2*DSTATE + NHEADS
#define CT      64                    // chunk tokens
#define NCH     (SEQLEN/CT)           // 32 chunks per sequence

// ---------------------------------------------------------------------------
// Scratch buffers (device globals — no allocations allowed)
// ---------------------------------------------------------------------------
__device__ __align__(128) float g_zx[NTOK * DINPROJ];     // in_proj output
__device__ __align__(128) float g_conv[NTOK * CONVDIM];   // conv+silu fp32 (x slice)
__device__ __align__(128) __half g_cvh[NTOK * CONVDIM];   // conv out fp16 hi
__device__ __align__(128) __half g_cvl[NTOK * CONVDIM];   // conv out fp16 lo
__device__ __align__(128) float g_dt[NTOK * NHEADS];
__device__ __align__(128) float g_a[NTOK * NHEADS];
__device__ __align__(128) float g_ecum[NTOK * NHEADS];
__device__ __align__(128) float g_ptot[BATCH*NHEADS*NCH];
__device__ __align__(128) float g_y[NTOK * DINNER];
__device__ __align__(128) float g_cstate[BATCH*NHEADS*NCH*HEADDIM*DSTATE];
__device__ __align__(128) __half g_isth[BATCH*NHEADS*NCH*HEADDIM*DSTATE]; // entry states fp16

// fp16 operands for the projection GEMMs
__device__ __align__(128) __half g_u_hi[NTOK * DMODEL];
__device__ __align__(128) __half g_u_lo[NTOK * DMODEL];
__device__ __align__(128) __half g_w1_h[DINPROJ * DMODEL];
__device__ __align__(128) __half g_w2_h[DMODEL * DINNER];
__device__ __align__(128) __half g_yn_hi[NTOK * DINNER];
__device__ __align__(128) __half g_yn_lo[NTOK * DINNER];

// ---------------------------------------------------------------------------
// MMA helpers
// ---------------------------------------------------------------------------
static __device__ __forceinline__ uint32_t smem_u32(const void* p) {
    return (uint32_t)__cvta_generic_to_shared(p);
}

static __device__ __forceinline__ void mma_fp16(
    float* d, const uint32_t* a, const uint32_t* b)
{
    asm volatile(
        "mma.sync.aligned.m16n8k16.row.col.f32.f16.f16.f32 "
        "{%0,%1,%2,%3}, {%4,%5,%6,%7}, {%8,%9}, {%0,%1,%2,%3};"
        : "+f"(d[0]), "+f"(d[1]), "+f"(d[2]), "+f"(d[3])
        : "r"(a[0]), "r"(a[1]), "r"(a[2]), "r"(a[3]), "r"(b[0]), "r"(b[1]));
}

static __device__ __forceinline__ void ldmatrix_x4(uint32_t* r, uint32_t addr)
{
    asm volatile("ldmatrix.sync.aligned.m8n8.x4.shared.b16 {%0,%1,%2,%3}, [%4];"
                 : "=r"(r[0]), "=r"(r[1]), "=r"(r[2]), "=r"(r[3]) : "r"(addr));
}

static __device__ __forceinline__ void ldmatrix_x2(uint32_t* r, uint32_t addr)
{
    asm volatile("ldmatrix.sync.aligned.m8n8.x2.shared.b16 {%0,%1}, [%2];"
                 : "=r"(r[0]), "=r"(r[1]) : "r"(addr));
}

static __device__ __forceinline__ void ldmatrix_x2_trans(uint32_t* r, uint32_t addr)
{
    asm volatile("ldmatrix.sync.aligned.m8n8.x2.trans.shared.b16 {%0,%1}, [%2];"
                 : "=r"(r[0]), "=r"(r[1]) : "r"(addr));
}

static __device__ __forceinline__ void cp16(uint32_t dst, const void* src, int sz)
{
    asm volatile("cp.async.cg.shared.global [%0], [%1], 16, %2;"
                 :: "r"(dst), "l"(src), "r"(sz));
}

// split fp32x4 into packed fp16 hi/lo (uint2 each)
static __device__ __forceinline__ void split4h(float4 v, uint2& hi, uint2& lo)
{
    __half h0=__float2half(v.x), h1=__float2half(v.y),
           h2=__float2half(v.z), h3=__float2half(v.w);
    __half l0=__float2half(v.x-__half2float(h0)),
           l1=__float2half(v.y-__half2float(h1)),
           l2=__float2half(v.z-__half2float(h2)),
           l3=__float2half(v.w-__half2float(h3));
    hi.x = ((uint32_t)__half_as_ushort(h1)<<16) | __half_as_ushort(h0);
    hi.y = ((uint32_t)__half_as_ushort(h3)<<16) | __half_as_ushort(h2);
    lo.x = ((uint32_t)__half_as_ushort(l1)<<16) | __half_as_ushort(l0);
    lo.y = ((uint32_t)__half_as_ushort(l3)<<16) | __half_as_ushort(l2);
}

// pack fp32x4 into fp16x4 (single rounding)
static __device__ __forceinline__ uint2 pack4h(float4 v)
{
    uint2 r;
    r.x = ((uint32_t)__half_as_ushort(__float2half(v.y))<<16) |
          __half_as_ushort(__float2half(v.x));
    r.y = ((uint32_t)__half_as_ushort(__float2half(v.w))<<16) |
          __half_as_ushort(__float2half(v.z));
    return r;
}

// ---------------------------------------------------------------------------
// fp16x2 GEMM via mma.sync (128x128 tile, GEMM1)
// ---------------------------------------------------------------------------
#define ROWB   80
#define MATB   (128 * ROWB)
#define STAGEB (3 * MATB)                 // 30720 (Ah | Al | B)
#define GEMM_SMEM (2 * STAGEB)            // 61440

__global__ void __launch_bounds__(256) gemm_mma(
    const __half* __restrict__ Ah, const __half* __restrict__ Al,
    const __half* __restrict__ Bw,
    float* __restrict__ C, int M, int N, int K)
{
    extern __shared__ __align__(128) char smem[];
    const uint32_t sb = smem_u32(smem);
    const int tid = threadIdx.x;
    const int wid = tid >> 5, lid = tid & 31;
    const int bm = blockIdx.y * 128;
    const int bn = blockIdx.x * 128;
    const int wr = wid & 1;
    const int wc = wid >> 1;

    float acc[4][4][4];
#pragma unroll
    for (int i = 0; i < 4; i++)
#pragma unroll
        for (int j = 0; j < 4; j++)
#pragma unroll
            for (int k = 0; k < 4; k++) acc[i][j][k] = 0.f;

    const int lrow = tid >> 1;
    const int lch  = (tid & 1) * 2;
    const int bok  = (bn + lrow) < N ? 16 : 0;
    const size_t arowoff = (size_t)(bm + lrow) * K + lch * 8;
    const size_t browoff = (size_t)(bok ? (bn + lrow) : 0) * K + lch * 8;
    const uint32_t dst0 = sb + lrow * ROWB + lch * 16;

    const int NC = K >> 5;

    auto stage_issue = [&](int c) {
        const uint32_t d = dst0 + (uint32_t)(c & 1) * STAGEB;
        const size_t ao = arowoff + (size_t)c * 32;
        const size_t bo = browoff + (size_t)c * 32;
        cp16(d,          Ah + ao, 16); cp16(d + 16,          Ah + ao + 8, 16);
        cp16(d + MATB,   Al + ao, 16); cp16(d + MATB + 16,   Al + ao + 8, 16);
        cp16(d + 2*MATB, Bw + bo, bok); cp16(d + 2*MATB + 16, Bw + bo + 8, bok);
        asm volatile("cp.async.commit_group;");
    };

    stage_issue(0);

    for (int c = 0; c < NC; ++c) {
        if (c + 1 < NC) {
            stage_issue(c + 1);
            asm volatile("cp.async.wait_group 1;");
        } else {
            asm volatile("cp.async.wait_group 0;");
        }
        __syncthreads();

        const uint32_t st = sb + (c & 1) * STAGEB;
#pragma unroll
        for (int ks = 0; ks < 2; ++ks) {
            uint32_t ah[4][4], al[4][4], bh[4][2];
            const int arow = wr * 64 + (lid & 15);
            const int akc  = ks * 2 + (lid >> 4);
#pragma unroll
            for (int mt = 0; mt < 4; ++mt) {
                const uint32_t a = st + (arow + mt * 16) * ROWB + akc * 16;
                ldmatrix_x4(ah[mt], a);
                ldmatrix_x4(al[mt], a + MATB);
            }
            const int brow = wc * 32 + (lid & 7);
            const int bkc  = ks * 2 + ((lid >> 3) & 1);
#pragma unroll
            for (int nt = 0; nt < 4; ++nt) {
                const uint32_t b = st + 2*MATB + (brow + nt * 8) * ROWB + bkc * 16;
                ldmatrix_x2(bh[nt], b);
            }
#pragma unroll
            for (int mt = 0; mt < 4; ++mt)
#pragma unroll
                for (int nt = 0; nt < 4; ++nt) {
                    mma_fp16(acc[mt][nt], ah[mt], bh[nt]);
                    mma_fp16(acc[mt][nt], al[mt], bh[nt]);
                }
        }
        __syncthreads();
    }

    const int mbase = bm + wr * 64 + (lid >> 2);
    const int nbase = bn + wc * 32 + (lid & 3) * 2;
#pragma unroll
    for (int mt = 0; mt < 4; ++mt) {
#pragma unroll
        for (int nt = 0; nt < 4; ++nt) {
            const int n0 = nbase + nt * 8;
            if (n0 < N) {
                const int m0 = mbase + mt * 16;
                float2 v0 = make_float2(acc[mt][nt][0], acc[mt][nt][1]);
                float2 v1 = make_float2(acc[mt][nt][2], acc[mt][nt][3]);
                *(float2*)(C + (size_t)m0 * N + n0)       = v0;
                *(float2*)(C + (size_t)(m0 + 8) * N + n0) = v1;
            }
        }
    }
}

// ---------------------------------------------------------------------------
// fp16x2 GEMM, 64x128 CTA tile (GEMM2)
// ---------------------------------------------------------------------------
#define AMATB64 (64 * ROWB)                 // 5120
#define STAGE64 (2 * AMATB64 + MATB)        // 20480
#define GEMM64_SMEM (2 * STAGE64)           // 40960

__global__ void __launch_bounds__(256) gemm_mma64(
    const __half* __restrict__ Ah, const __half* __restrict__ Al,
    const __half* __restrict__ Bw,
    float* __restrict__ C, int M, int N, int K)
{
    extern __shared__ __align__(128) char smem[];
    const uint32_t sb = smem_u32(smem);
    const int tid = threadIdx.x;
    const int wid = tid >> 5, lid = tid & 31;
    const int bm = blockIdx.y * 64;
    const int bn = blockIdx.x * 128;
    const int wr = wid & 1;
    const int wc = wid >> 1;

    float acc[2][4][4];
#pragma unroll
    for (int i = 0; i < 2; i++)
#pragma unroll
        for (int j = 0; j < 4; j++)
#pragma unroll
            for (int k = 0; k < 4; k++) acc[i][j][k] = 0.f;

    const int alrow = tid >> 2;
    const int alch  = tid & 3;
    const size_t arowoff = (size_t)(bm + alrow) * K + alch * 8;
    const uint32_t adst0 = sb + alrow * ROWB + alch * 16;
    const int blrow = tid >> 1;
    const int blch  = (tid & 1) * 2;
    const int bok   = (bn + blrow) < N ? 16 : 0;
    const size_t browoff = (size_t)(bok ? (bn + blrow) : 0) * K + blch * 8;
    const uint32_t bdst0 = sb + 2 * AMATB64 + blrow * ROWB + blch * 16;

    const int NC = K >> 5;

    auto stage_issue = [&](int c) {
        const uint32_t so = (uint32_t)(c & 1) * STAGE64;
        const size_t ao = arowoff + (size_t)c * 32;
        const size_t bo = browoff + (size_t)c * 32;
        cp16(adst0 + so,           Ah + ao, 16);
        cp16(adst0 + so + AMATB64, Al + ao, 16);
        cp16(bdst0 + so,      Bw + bo, bok);
        cp16(bdst0 + so + 16, Bw + bo + 8, bok);
        asm volatile("cp.async.commit_group;");
    };

    stage_issue(0);

    for (int c = 0; c < NC; ++c) {
        if (c + 1 < NC) {
            stage_issue(c + 1);
            asm volatile("cp.async.wait_group 1;");
        } else {
            asm volatile("cp.async.wait_group 0;");
        }
        __syncthreads();

        const uint32_t st = sb + (uint32_t)(c & 1) * STAGE64;
#pragma unroll
        for (int ks = 0; ks < 2; ++ks) {
            uint32_t ah[2][4], al[2][4], bh[4][2];
            const int arow = wr * 32 + (lid & 15);
            const int akc  = ks * 2 + (lid >> 4);
#pragma unroll
            for (int mt = 0; mt < 2; ++mt) {
                const uint32_t a = st + (arow + mt * 16) * ROWB + akc * 16;
                ldmatrix_x4(ah[mt], a);
                ldmatrix_x4(al[mt], a + AMATB64);
            }
            const int brow = wc * 32 + (lid & 7);
            const int bkc  = ks * 2 + ((lid >> 3) & 1);
#pragma unroll
            for (int nt = 0; nt < 4; ++nt) {
                const uint32_t b = st + 2 * AMATB64 + (brow + nt * 8) * ROWB + bkc * 16;
                ldmatrix_x2(bh[nt], b);
            }
#pragma unroll
            for (int mt = 0; mt < 2; ++mt)
#pragma unroll
                for (int nt = 0; nt < 4; ++nt) {
                    mma_fp16(acc[mt][nt], ah[mt], bh[nt]);
                    mma_fp16(acc[mt][nt], al[mt], bh[nt]);
                }
        }
        __syncthreads();
    }

    const int mbase = bm + wr * 32 + (lid >> 2);
    const int nbase = bn + wc * 32 + (lid & 3) * 2;
#pragma unroll
    for (int mt = 0; mt < 2; ++mt) {
#pragma unroll
        for (int nt = 0; nt < 4; ++nt) {
            const int n0 = nbase + nt * 8;
            if (n0 < N) {
                const int m0 = mbase + mt * 16;
                float2 v0 = make_float2(acc[mt][nt][0], acc[mt][nt][1]);
                float2 v1 = make_float2(acc[mt][nt][2], acc[mt][nt][3]);
                *(float2*)(C + (size_t)m0 * N + n0)       = v0;
                *(float2*)(C + (size_t)(m0 + 8) * N + n0) = v1;
            }
        }
    }
}

// ---------------------------------------------------------------------------
// fp32 -> fp16 hi/lo split; fp32 -> fp16 single
// ---------------------------------------------------------------------------
__global__ void split_fp16_kernel(const float* __restrict__ src,
                                  __half* __restrict__ hi,
                                  __half* __restrict__ lo, int n)
{
    const int i = blockIdx.x * 256 + threadIdx.x;
    if (i >= n) return;
    const float x = src[i];
    const __half h = __float2half(x);
    hi[i] = h;
    lo[i] = __float2half(x - __half2float(h));
}

__global__ void cvt_fp16_kernel(const float* __restrict__ src,
                                __half* __restrict__ dst, int n)
{
    const int i = blockIdx.x * 256 + threadIdx.x;
    if (i < n) dst[i] = __float2half(src[i]);
}

// ---------------------------------------------------------------------------
// Depthwise causal conv (width 4) + bias + SiLU -> fp16 hi/lo (+fp32 x slice)
// ---------------------------------------------------------------------------
__global__ void conv_silu_kernel(const float* __restrict__ cw,
                                 const float* __restrict__ cb)
{
    const int idx = blockIdx.x * 256 + threadIdx.x;
    if (idx >= NTOK * CONVDIM) return;
    const int c  = idx % CONVDIM;
    const int bt = idx / CONVDIM;
    const int t  = bt % SEQLEN;
    float acc = cb[c];
#pragma unroll
    for (int k = 0; k < 4; k++) {
        const int tt = t - 3 + k;
        if (tt >= 0)
            acc = fmaf(cw[c * 4 + k],
                       g_zx[((size_t)bt + k - 3) * DINPROJ + DINNER + c], acc);
    }
    const float v = acc / (1.f + __expf(-acc));   // silu
    if (c < DINNER) g_conv[idx] = v;
    const __half hb = __float2half(v);
    g_cvh[idx] = hb;
    g_cvl[idx] = __float2half(v - __half2float(hb));
}

// ---------------------------------------------------------------------------
// dt_dis = softplus(dt + dt_bias); a = dt_dis * A
// ---------------------------------------------------------------------------
__global__ void dt_kernel(const float* __restrict__ dt_bias,
                          const float* __restrict__ A_log)
{
    const int idx = blockIdx.x * 256 + threadIdx.x;
    if (idx >= NTOK * NHEADS) return;
    const int h  = idx % NHEADS;
    const int bt = idx / NHEADS;
    const float x  = g_zx[(size_t)bt * DINPROJ + DINNER + CONVDIM + h] + dt_bias[h];
    const float sp = (x > 20.f) ? x : log1pf(expf(x));
    const float Ah = -expf(A_log[h]);
    g_dt[idx] = sp;
    g_a[idx]  = sp * Ah;
}

// ---------------------------------------------------------------------------
// SSD chunk kernel — fp16 2-MMA scheme. A-ops hi/lo (C, P, Xw); B-ops single
// (B, X). smem 80640B -> 2 CTAs/SM.
// ---------------------------------------------------------------------------
#define PB 272
#define PX 144
#define SM_BH 0
#define SM_CH 17408
#define SM_CL 34816
#define SM_XH 52224
#define SM_PH 61440
#define SM_PL 70656
#define SM_CUM 79872
#define SM_DTA 80128
#define SM_WW  80384
#define CHUNK_SMEM 80640

__global__ void __launch_bounds__(256) chunk_kernel()
{
    extern __shared__ __align__(128) char smem[];
    const uint32_t sb = smem_u32(smem);
    const int ch = blockIdx.x, h = blockIdx.y, b = blockIdx.z;
    const int tid = threadIdx.x;
    const int wid = tid >> 5, lid = tid & 31;
    const int wr = wid & 1, wc = wid >> 1;
    const size_t tb = (size_t)b * SEQLEN + (size_t)ch * CT;

    float* s_cum = (float*)(smem + SM_CUM);
    float* s_dt  = (float*)(smem + SM_DTA);
    float* s_w   = (float*)(smem + SM_WW);

    // ---- stage B (single hi), C (hi/lo) ----
    {
        const int row = tid >> 2, c0 = (tid & 3) * 32;
        const size_t so = (tb + row) * CONVDIM + DINNER + c0;
#pragma unroll
        for (int c = 0; c < 32; c += 8) {
            *(uint4*)(smem + SM_BH + row * PB + (c0 + c) * 2) =
                *(const uint4*)(g_cvh + so + c);
            *(uint4*)(smem + SM_CH + row * PB + (c0 + c) * 2) =
                *(const uint4*)(g_cvh + so + DSTATE + c);
            *(uint4*)(smem + SM_CL + row * PB + (c0 + c) * 2) =
                *(const uint4*)(g_cvl + so + DSTATE + c);
        }
    }
    // ---- stage X transposed (single hi): Xs[p][t] ----
    {
        const int t = tid >> 2, p0 = (tid & 3) * 16;
        const size_t so = (tb + t) * CONVDIM + h * HEADDIM + p0;
#pragma unroll
        for (int p = 0; p < 16; ++p)
            *(unsigned short*)(smem + SM_XH + (p0 + p) * PX + t * 2) =
                *(const unsigned short*)(g_cvh + so + p);
    }
    // ---- warp 0: within-chunk inclusive cumsum of a (64) ----
    if (wid == 0) {
        const float a0 = g_a[(tb + 2 * lid)     * NHEADS + h];
        const float a1 = g_a[(tb + 2 * lid + 1) * NHEADS + h];
        const float ps = a0 + a1;
        float sc = ps;
#pragma unroll
        for (int off = 1; off < 32; off <<= 1) {
            const float t = __shfl_up_sync(0xffffffffu, sc, off);
            if (lid >= off) sc += t;
        }
        float excl = __shfl_up_sync(0xffffffffu, sc, 1);
        if (lid == 0) excl = 0.f;
        s_cum[2 * lid]     = excl + a0;
        s_cum[2 * lid + 1] = excl + ps;
    }
    if (tid >= 64 && tid < 128) s_dt[tid - 64] = g_dt[(tb + tid - 64) * NHEADS + h];
    __syncthreads();

    if (tid < 64) {
        const float ct = s_cum[tid], tot = s_cum[63];
        s_w[tid] = expf(tot - ct) * s_dt[tid];
        g_ecum[(tb + tid) * NHEADS + h] = expf(ct);
        if (tid == 63)
            g_ptot[((size_t)b * NHEADS + h) * NCH + ch] = expf(tot);
    }

    // ---- G = C·B^T (A = C hi/lo, B = B single): 2 MMAs ----
    float gacc[2][2][4];
#pragma unroll
    for (int i = 0; i < 2; i++)
#pragma unroll
        for (int j = 0; j < 2; j++)
#pragma unroll
            for (int k = 0; k < 4; k++) gacc[i][j][k] = 0.f;
#pragma unroll
    for (int ks = 0; ks < 8; ++ks) {
        uint32_t ah[2][4], al[2][4], bh2[2][2];
        const int arow = wr * 32 + (lid & 15);
        const int akc  = ks * 2 + (lid >> 4);
#pragma unroll
        for (int mt = 0; mt < 2; ++mt) {
            const uint32_t a = sb + SM_CH + (arow + mt * 16) * PB + akc * 16;
            ldmatrix_x4(ah[mt], a);
            ldmatrix_x4(al[mt], a + (SM_CL - SM_CH));
        }
        const int brow = wc * 16 + (lid & 7);
        const int bkc  = ks * 2 + ((lid >> 3) & 1);
#pragma unroll
        for (int nt = 0; nt < 2; ++nt) {
            const uint32_t bp = sb + SM_BH + (brow + nt * 8) * PB + bkc * 16;
            ldmatrix_x2(bh2[nt], bp);
        }
#pragma unroll
        for (int mt = 0; mt < 2; ++mt)
#pragma unroll
            for (int nt = 0; nt < 2; ++nt) {
                mma_fp16(gacc[mt][nt], ah[mt], bh2[nt]);
                mma_fp16(gacc[mt][nt], al[mt], bh2[nt]);
            }
    }

    // ---- P = mask * G * dt -> smem fp16 hi/lo ----
#pragma unroll
    for (int mt = 0; mt < 2; ++mt)
#pragma unroll
        for (int nt = 0; nt < 2; ++nt)
#pragma unroll
            for (int r = 0; r < 4; ++r) {
                const int t1 = wr * 32 + mt * 16 + (lid >> 2) + ((r >> 1) ? 8 : 0);
                const int t2 = wc * 16 + nt * 8 + (lid & 3) * 2 + (r & 1);
                float pv = 0.f;
                if (t1 >= t2)
                    pv = __expf(s_cum[t1] - s_cum[t2]) * gacc[mt][nt][r] * s_dt[t2];
                const __half hb = __float2half(pv);
                const __half lb = __float2half(pv - __half2float(hb));
                *(unsigned short*)(smem + SM_PH + t1 * PX + t2 * 2) =
                    __half_as_ushort(hb);
                *(unsigned short*)(smem + SM_PL + t1 * PX + t2 * 2) =
                    __half_as_ushort(lb);
            }
    __syncthreads();

    // ---- Y_intra = P·X (A = P hi/lo, B = X single): 2 MMAs ----
    {
        float yacc[2][2][4];
#pragma unroll
        for (int i = 0; i < 2; i++)
#pragma unroll
            for (int j = 0; j < 2; j++)
#pragma unroll
                for (int k = 0; k < 4; k++) yacc[i][j][k] = 0.f;
#pragma unroll
        for (int ks = 0; ks < 4; ++ks) {
            uint32_t ah[2][4], al[2][4], bh2[2][2];
            const int arow = wr * 32 + (lid & 15);
            const int akc  = ks * 2 + (lid >> 4);
#pragma unroll
            for (int mt = 0; mt < 2; ++mt) {
                const uint32_t a = sb + SM_PH + (arow + mt * 16) * PX + akc * 16;
                ldmatrix_x4(ah[mt], a);
                ldmatrix_x4(al[mt], a + (SM_PL - SM_PH));
            }
            const int brow = wc * 16 + (lid & 7);
            const int bkc  = ks * 2 + ((lid >> 3) & 1);
#pragma unroll
            for (int nt = 0; nt < 2; ++nt) {
                const uint32_t bp = sb + SM_XH + (brow + nt * 8) * PX + bkc * 16;
                ldmatrix_x2(bh2[nt], bp);
            }
#pragma unroll
            for (int mt = 0; mt < 2; ++mt)
#pragma unroll
                for (int nt = 0; nt < 2; ++nt) {
                    mma_fp16(yacc[mt][nt], ah[mt], bh2[nt]);
                    mma_fp16(yacc[mt][nt], al[mt], bh2[nt]);
                }
        }
#pragma unroll
        for (int mt = 0; mt < 2; ++mt)
#pragma unroll
            for (int nt = 0; nt < 2; ++nt) {
                const int t0 = wr * 32 + mt * 16 + (lid >> 2);
                const int p0 = wc * 16 + nt * 8 + (lid & 3) * 2;
                *(float2*)(g_y + (tb + t0) * DINNER + h * HEADDIM + p0) =
                    make_float2(yacc[mt][nt][0], yacc[mt][nt][1]);
                *(float2*)(g_y + (tb + t0 + 8) * DINNER + h * HEADDIM + p0) =
                    make_float2(yacc[mt][nt][2], yacc[mt][nt][3]);
            }
    }
    __syncthreads();

    // ---- Xw[p][j] = x[j,p] * w_j -> P region (fp16 hi/lo) ----
    {
        const int p = tid >> 2, j0 = (tid & 3) * 16;
#pragma unroll
        for (int j = 0; j < 16; ++j) {
            const int jj = j0 + j;
            const float xv = __half2float(__ushort_as_half(
                *(unsigned short*)(smem + SM_XH + p * PX + jj * 2)));
            const float xw = xv * s_w[jj];
            const __half hb = __float2half(xw);
            const __half lb = __float2half(xw - __half2float(hb));
            *(unsigned short*)(smem + SM_PH + p * PX + jj * 2) =
                __half_as_ushort(hb);
            *(unsigned short*)(smem + SM_PL + p * PX + jj * 2) =
                __half_as_ushort(lb);
        }
    }
    __syncthreads();

    // ---- L = Xw·B (A = Xw hi/lo, B = B single via trans): 2 MMAs ----
    {
        float lacc[2][4][4];
#pragma unroll
        for (int i = 0; i < 2; i++)
#pragma unroll
            for (int j = 0; j < 4; j++)
#pragma unroll
                for (int k = 0; k < 4; k++) lacc[i][j][k] = 0.f;
#pragma unroll
        for (int ks = 0; ks < 4; ++ks) {
            uint32_t ah[2][4], al[2][4];
            const int arow = wr * 32 + (lid & 15);
            const int akc  = ks * 2 + (lid >> 4);
#pragma unroll
            for (int mt = 0; mt < 2; ++mt) {
                const uint32_t a = sb + SM_PH + (arow + mt * 16) * PX + akc * 16;
                ldmatrix_x4(ah[mt], a);
                ldmatrix_x4(al[mt], a + (SM_PL - SM_PH));
            }
            const int j0 = ks * 16 + (lid & 15);
#pragma unroll
            for (int nt = 0; nt < 4; ++nt) {
                const int n0 = wc * 32 + nt * 8;
                uint32_t bh2[2];
                const uint32_t bp = sb + SM_BH + j0 * PB + n0 * 2;
                ldmatrix_x2_trans(bh2, bp);
#pragma unroll
                for (int mt = 0; mt < 2; ++mt) {
                    mma_fp16(lacc[mt][nt], ah[mt], bh2);
                    mma_fp16(lacc[mt][nt], al[mt], bh2);
                }
            }
        }
        float* Lout = g_cstate +
            (((size_t)b * NHEADS + h) * NCH + ch) * (HEADDIM * DSTATE);
#pragma unroll
        for (int mt = 0; mt < 2; ++mt)
#pragma unroll
            for (int nt = 0; nt < 4; ++nt) {
                const int p0 = wr * 32 + mt * 16 + (lid >> 2);
                const int n0 = wc * 32 + nt * 8 + (lid & 3) * 2;
                *(float2*)(Lout + (size_t)p0 * DSTATE + n0) =
                    make_float2(lacc[mt][nt][0], lacc[mt][nt][1]);
                *(float2*)(Lout + (size_t)(p0 + 8) * DSTATE + n0) =
                    make_float2(lacc[mt][nt][2], lacc[mt][nt][3]);
            }
    }
}

// ---------------------------------------------------------------------------
// Sequential combine — 4x sliced; emits single-fp16 entry states
// ---------------------------------------------------------------------------
__global__ __launch_bounds__(256) void combine_kernel()
{
    const int h = blockIdx.x, b = blockIdx.y, q = blockIdx.z;
    const int tid = threadIdx.x;
    const size_t off = (size_t)q * 2048 + (size_t)tid * 8;
    float4 acc[2];
#pragma unroll
    for (int r = 0; r < 2; r++) acc[r] = make_float4(0.f, 0.f, 0.f, 0.f);

    for (int c = 0; c < NCH; ++c) {
        const size_t base = (((size_t)b * NHEADS + h) * NCH + c) * (HEADDIM * DSTATE);
#pragma unroll
        for (int r = 0; r < 2; r++)
            *(uint2*)(g_isth + base + off + r * 4) = pack4h(acc[r]);
        const float P = g_ptot[((size_t)b * NHEADS + h) * NCH + c];
#pragma unroll
        for (int r = 0; r < 2; r++) {
            const float4 f = *(const float4*)(g_cstate + base + off + r * 4);
            acc[r].x = fmaf(acc[r].x, P, f.x);
            acc[r].y = fmaf(acc[r].y, P, f.y);
            acc[r].z = fmaf(acc[r].z, P, f.z);
            acc[r].w = fmaf(acc[r].w, P, f.w);
        }
    }
}

// ---------------------------------------------------------------------------
// Inter-chunk: Y += ecum * (C · S0)  — A = C hi/lo, B = S0 single: 2 MMAs
// ---------------------------------------------------------------------------
#define ISM_CH 0
#define ISM_CL 17408
#define ISM_SH 34816
#define ISM_EC 52224
#define INTER_SMEM 52480

__global__ void __launch_bounds__(256) inter_kernel()
{
    extern __shared__ __align__(128) char smem[];
    const uint32_t sb = smem_u32(smem);
    const int ch = blockIdx.x + 1, h = blockIdx.y, b = blockIdx.z;
    const int tid = threadIdx.x;
    const int wid = tid >> 5, lid = tid & 31;
    const int wr = wid & 1, wc = wid >> 1;
    const size_t tb = (size_t)b * SEQLEN + (size_t)ch * CT;

    {
        const int row = tid >> 2, c0 = (tid & 3) * 32;
        const size_t co = (tb + row) * CONVDIM + DINNER + DSTATE + c0;
        const size_t so = (((size_t)b * NHEADS + h) * NCH + ch) * (HEADDIM * DSTATE)
                        + (size_t)row * DSTATE + c0;
#pragma unroll
        for (int c = 0; c < 32; c += 8) {
            *(uint4*)(smem + ISM_CH + row * PB + (c0 + c) * 2) =
                *(const uint4*)(g_cvh + co + c);
            *(uint4*)(smem + ISM_CL + row * PB + (c0 + c) * 2) =
                *(const uint4*)(g_cvl + co + c);
            *(uint4*)(smem + ISM_SH + row * PB + (c0 + c) * 2) =
                *(const uint4*)(g_isth + so + c);
        }
    }
    if (tid < 64)
        ((float*)(smem + ISM_EC))[tid] = g_ecum[(tb + tid) * NHEADS + h];
    __syncthreads();

    float acc[2][2][4];
#pragma unroll
    for (int i = 0; i < 2; i++)
#pragma unroll
        for (int j = 0; j < 2; j++)
#pragma unroll
            for (int k = 0; k < 4; k++) acc[i][j][k] = 0.f;

#pragma unroll
    for (int ks = 0; ks < 8; ++ks) {
        uint32_t ah[2][4], al[2][4], bh2[2][2];
        const int arow = wr * 32 + (lid & 15);
        const int akc  = ks * 2 + (lid >> 4);
#pragma unroll
        for (int mt = 0; mt < 2; ++mt) {
            const uint32_t a = sb + ISM_CH + (arow + mt * 16) * PB + akc * 16;
            ldmatrix_x4(ah[mt], a);
            ldmatrix_x4(al[mt], a + (ISM_CL - ISM_CH));
        }
        const int brow = wc * 16 + (lid & 7);
        const int bkc  = ks * 2 + ((lid >> 3) & 1);
#pragma unroll
        for (int nt = 0; nt < 2; ++nt) {
            const uint32_t bp = sb + ISM_SH + (brow + nt * 8) * PB + bkc * 16;
            ldmatrix_x2(bh2[nt], bp);
        }
#pragma unroll
        for (int mt = 0; mt < 2; ++mt)
#pragma unroll
            for (int nt = 0; nt < 2; ++nt) {
                mma_fp16(acc[mt][nt], ah[mt], bh2[nt]);
                mma_fp16(acc[mt][nt], al[mt], bh2[nt]);
            }
    }

    const float* s_ec = (const float*)(smem + ISM_EC);
#pragma unroll
    for (int mt = 0; mt < 2; ++mt)
#pragma unroll
        for (int nt = 0; nt < 2; ++nt) {
            const int t0 = wr * 32 + mt * 16 + (lid >> 2);
            const int p0 = wc * 16 + nt * 8 + (lid & 3) * 2;
            {
                float* yp = g_y + (tb + t0) * DINNER + h * HEADDIM + p0;
                float2 o = *(float2*)yp;
                o.x += s_ec[t0] * acc[mt][nt][0];
                o.y += s_ec[t0] * acc[mt][nt][1];
                *(float2*)yp = o;
            }
            {
                float* yp = g_y + (tb + t0 + 8) * DINNER + h * HEADDIM + p0;
                float2 o = *(float2*)yp;
                o.x += s_ec[t0 + 8] * acc[mt][nt][2];
                o.y += s_ec[t0 + 8] * acc[mt][nt][3];
                *(float2*)yp = o;
            }
        }
}

// ---------------------------------------------------------------------------
// y += x*D; yz = y*silu(z); RMSNorm(yz) * norm_w -> fp16 hi/lo
// ---------------------------------------------------------------------------
__global__ __launch_bounds__(256) void gate_norm_kernel(
    const float* __restrict__ Dv, const float* __restrict__ nw)
{
    const int bt = blockIdx.x;
    const float* zrow = g_zx   + (size_t)bt * DINPROJ;
    const float* xrow = g_conv + (size_t)bt * CONVDIM;
    const float* yrow = g_y    + (size_t)bt * DINNER;

    float v[6];
    float ss = 0.f;
#pragma unroll
    for (int i = 0; i < 6; i++) {
        const int c = threadIdx.x + i * 256;
        const float yv = fmaf(xrow[c], Dv[c >> 6], yrow[c]);
        const float z  = zrow[c];
        const float gz = z / (1.f + __expf(-z));
        const float val = yv * gz;
        v[i] = val;
        ss = fmaf(val, val, ss);
    }
#pragma unroll
    for (int o = 16; o; o >>= 1) ss += __shfl_xor_sync(0xffffffffu, ss, o);
    __shared__ float sred[8];
    if ((threadIdx.x & 31) == 0) sred[threadIdx.x >> 5] = ss;
    __syncthreads();
    float tot = 0.f;
#pragma unroll
    for (int i = 0; i < 8; i++) tot += sred[i];
    const float scale = rsqrtf(tot * (1.f / DINNER) + 1e-5f);

    __half* yh = g_yn_hi + (size_t)bt * DINNER;
    __half* yl = g_yn_lo + (size_t)bt * DINNER;
#pragma unroll
    for (int i = 0; i < 6; i++) {
        const int c = threadIdx.x + i * 256;
        const float val = v[i] * scale * nw[c];
        const __half hb = __float2half(val);
        yh[c] = hb;
        yl[c] = __float2half(val - __half2float(hb));
    }
}

// ---------------------------------------------------------------------------
// Launch
// ---------------------------------------------------------------------------
extern "C" void kernel_launch(void* const* d_in, const int* in_sizes, int n_in,
                              void* d_out, int out_size)
{
    const float* u          = (const float*)d_in[0];
    const float* in_proj_w  = (const float*)d_in[1];
    const float* conv_w     = (const float*)d_in[2];
    const float* conv_b     = (const float*)d_in[3];
    const float* dt_bias    = (const float*)d_in[4];
    const float* A_log      = (const float*)d_in[5];
    const float* Dv         = (const float*)d_in[6];
    const float* norm_w     = (const float*)d_in[7];
    const float* out_proj_w = (const float*)d_in[8];
    float* out = (float*)d_out;

    float* zx = nullptr;
    __half *uh, *ul, *w1, *w2, *ynh, *ynl;
    cudaGetSymbolAddress((void**)&zx,  g_zx);
    cudaGetSymbolAddress((void**)&uh,  g_u_hi);
    cudaGetSymbolAddress((void**)&ul,  g_u_lo);
    cudaGetSymbolAddress((void**)&w1,  g_w1_h);
    cudaGetSymbolAddress((void**)&w2,  g_w2_h);
    cudaGetSymbolAddress((void**)&ynh, g_yn_hi);
    cudaGetSymbolAddress((void**)&ynl, g_yn_lo);

    cudaFuncSetAttribute(gemm_mma,
                         cudaFuncAttributeMaxDynamicSharedMemorySize, GEMM_SMEM);
    cudaFuncSetAttribute(gemm_mma64,
                         cudaFuncAttributeMaxDynamicSharedMemorySize, GEMM64_SMEM);
    cudaFuncSetAttribute(chunk_kernel,
                         cudaFuncAttributeMaxDynamicSharedMemorySize, CHUNK_SMEM);
    cudaFuncSetAttribute(inter_kernel,
                         cudaFuncAttributeMaxDynamicSharedMemorySize, INTER_SMEM);

    // 0) fp16 operand prep
    split_fp16_kernel<<<(NTOK * DMODEL + 255) / 256, 256>>>(u, uh, ul,
                                                            NTOK * DMODEL);
    cvt_fp16_kernel<<<(DINPROJ * DMODEL + 255) / 256, 256>>>(in_proj_w, w1,
                                                             DINPROJ * DMODEL);
    cvt_fp16_kernel<<<(DMODEL * DINNER + 255) / 256, 256>>>(out_proj_w, w2,
                                                            DMODEL * DINNER);

    // 1) zxbcdt = u @ in_proj_w^T — fp16x2 HMMA
    dim3 g1((DINPROJ + 127) / 128, NTOK / 128);
    gemm_mma<<<g1, 256, GEMM_SMEM>>>(uh, ul, w1, zx, NTOK, DINPROJ, DMODEL);

    // 2) depthwise causal conv + silu (+ fp16 hi/lo emit)
    conv_silu_kernel<<<(NTOK * CONVDIM + 255) / 256, 256>>>(conv_w, conv_b);

    // 3) dt softplus / log-decay a
    dt_kernel<<<(NTOK * NHEADS + 255) / 256, 256>>>(dt_bias, A_log);

    // 4) SSD chunk pass — fp16 2-MMA
    chunk_kernel<<<dim3(NCH, NHEADS, BATCH), 256, CHUNK_SMEM>>>();

    // 5) combine chunk states (4-way sliced)
    combine_kernel<<<dim3(NHEADS, BATCH, 4), 256>>>();

    // 6) inter-chunk contribution — fp16 2-MMA
    inter_kernel<<<dim3(NCH - 1, NHEADS, BATCH), 256, INTER_SMEM>>>();

    // 7) gate + RMSNorm -> fp16 hi/lo
    gate_norm_kernel<<<NTOK, 256>>>(Dv, norm_w);

    // 8) out = yn @ out_proj_w^T — fp16x2, 64x128 tiles
    dim3 g2((DMODEL + 127) / 128, NTOK / 64);
    gemm_mma64<<<g2, 256, GEMM64_SMEM>>>(ynh, ynl, w2, out,
                                         NTOK, DMODEL, DINNER);
}